// round 3
// baseline (speedup 1.0000x reference)
#include <cuda_runtime.h>
#include <math.h>

// Problem constants
#define BB   4
#define CCH  64
#define HH   256
#define WW   256
#define HWSZ (HH*WW)
#define DGRP 8
#define NTAP 9

// ---------------------------------------------------------------------------
// Scratch buffers (device globals; no allocation allowed in kernel_launch)
// ---------------------------------------------------------------------------
__device__ float g_warped[BB*CCH*HWSZ];
__device__ float g_feat0 [BB*CCH*HWSZ];
__device__ float g_tmp   [BB*CCH*HWSZ];
__device__ float g_feat  [BB*CCH*HWSZ];
__device__ float g_off   [BB*216*HWSZ];

// Transposed weights: [cin][tap][cout] (cout padded to CoutP)
__device__ float g_wT_fc [128*9*64];
__device__ float g_wT_c1 [64*9*64];
__device__ float g_wT_c2 [64*9*64];
__device__ float g_wT_c3 [64*9*64];
__device__ float g_wT_c4 [64*9*64];
__device__ float g_wT_c5 [64*9*64];
__device__ float g_wT_c6 [64*9*64];
__device__ float g_wT_off[64*9*256];      // Cout=216 padded to 256
__device__ float g_wT_dcn[9*64*64];       // [tap][cin][cout]

// ---------------------------------------------------------------------------
// Weight transposes (tiny, run each call; deterministic)
// ---------------------------------------------------------------------------
__global__ void transpose_w_kernel(const float* __restrict__ w, float* __restrict__ wT,
                                   int CIN, int Cout, int CoutP)
{
    int idx = blockIdx.x * 256 + threadIdx.x;
    int total = CIN * 9 * CoutP;
    if (idx >= total) return;
    int cout = idx % CoutP;
    int tap  = (idx / CoutP) % 9;
    int cin  = idx / (9 * CoutP);
    wT[idx] = (cout < Cout) ? w[(cout * CIN + cin) * 9 + tap] : 0.f;
}

__global__ void transpose_dcn_kernel(const float* __restrict__ w, float* __restrict__ wT)
{
    int idx = blockIdx.x * 256 + threadIdx.x;   // 9*64*64
    if (idx >= 9*64*64) return;
    int cout = idx % 64;
    int c    = (idx / 64) % 64;
    int k    = idx / (64 * 64);
    wT[idx] = w[(cout * 64 + c) * 9 + k];
}

// ---------------------------------------------------------------------------
// flow_warp: bilinear sample (zero padding) of supp at (x+fx, y+fy)
// ---------------------------------------------------------------------------
__global__ void warp_kernel(const float* __restrict__ supp,
                            const float* __restrict__ flow,
                            float* __restrict__ outw)
{
    int p = blockIdx.x * 256 + threadIdx.x;
    int b = blockIdx.y;
    if (p >= HWSZ) return;
    int y = p / WW, x = p % WW;
    float fx = flow[(b*2 + 0)*HWSZ + p];
    float fy = flow[(b*2 + 1)*HWSZ + p];
    float sy = (float)y + fy;
    float sx = (float)x + fx;
    float y0f = floorf(sy), x0f = floorf(sx);
    int iy0 = (int)y0f, ix0 = (int)x0f;
    int iy1 = iy0 + 1,  ix1 = ix0 + 1;
    float wy = sy - y0f, wx = sx - x0f;
    bool vy0 = ((unsigned)iy0 < HH), vy1 = ((unsigned)iy1 < HH);
    bool vx0 = ((unsigned)ix0 < WW), vx1 = ((unsigned)ix1 < WW);
    float w00 = (1.f - wy) * (1.f - wx) * ((vy0 && vx0) ? 1.f : 0.f);
    float w01 = (1.f - wy) * wx        * ((vy0 && vx1) ? 1.f : 0.f);
    float w10 = wy * (1.f - wx)        * ((vy1 && vx0) ? 1.f : 0.f);
    float w11 = wy * wx                * ((vy1 && vx1) ? 1.f : 0.f);
    int cy0 = min(max(iy0, 0), HH-1), cy1 = min(max(iy1, 0), HH-1);
    int cx0 = min(max(ix0, 0), WW-1), cx1 = min(max(ix1, 0), WW-1);
    int i00 = cy0*WW + cx0, i01 = cy0*WW + cx1;
    int i10 = cy1*WW + cx0, i11 = cy1*WW + cx1;
    const float* sb = supp + b*CCH*HWSZ;
    float*       ob = outw + b*CCH*HWSZ;
    #pragma unroll 8
    for (int c = 0; c < CCH; c++) {
        const float* ch = sb + c*HWSZ;
        ob[c*HWSZ + p] = w00*ch[i00] + w01*ch[i01] + w10*ch[i10] + w11*ch[i11];
    }
}

// ---------------------------------------------------------------------------
// Generic 3x3 conv, NCHW fp32.
//   block = 256 threads: cout = tid&63 (+ 64*chunk), pixel-group = tid>>6,
//   each thread computes 16 contiguous pixels of one row.
//   ACT: 0 none, 1 relu, 2 leaky-relu(0.1)
//   EPI: 0 store, 1 out = res + v, 2 out += 0.1*v
//   If CIN==128, cin<64 comes from in0, cin>=64 from in1 (fused concat).
// ---------------------------------------------------------------------------
template<int CIN, int DIL, int ACT, int EPI, int NCHUNK>
__global__ void __launch_bounds__(256, 2)
conv3x3_kernel(const float* __restrict__ in0, const float* __restrict__ in1,
               const float* __restrict__ wT, const float* __restrict__ bias,
               float* __restrict__ out, const float* __restrict__ res,
               int Cout, int CoutP)
{
    extern __shared__ float sIn[];
    const int TW  = 64 + 2*DIL;
    const int SEG = 16 + 2*DIL;
    int b     = blockIdx.z / NCHUNK;
    int chunk = blockIdx.z % NCHUNK;
    int y     = blockIdx.y;
    int x0    = blockIdx.x * 64;
    int tid   = threadIdx.x;

    // Cooperative load of the 3-row input tile (zero padded), all CIN channels
    int total = CIN * 3 * TW;
    for (int i = tid; i < total; i += 256) {
        int xx  = i % TW;
        int rr  = (i / TW) % 3;
        int cin = i / (3 * TW);
        int gy = y + (rr - 1) * DIL;
        int gx = x0 - DIL + xx;
        float v = 0.f;
        if ((unsigned)gy < HH && (unsigned)gx < WW) {
            const float* base = (cin < 64) ? in0 : in1;
            int cc = cin & 63;
            v = base[((b*64 + cc)*HH + gy)*WW + gx];
        }
        sIn[i] = v;
    }
    __syncthreads();

    int cout  = chunk * 64 + (tid & 63);
    int pg    = tid >> 6;
    int xbase = pg * 16;
    float bv = (cout < Cout) ? bias[cout] : 0.f;
    float acc[16];
    #pragma unroll
    for (int i = 0; i < 16; i++) acc[i] = bv;

    const float* wp = wT + cout;
    for (int cin = 0; cin < CIN; cin++) {
        const float* srowbase = sIn + cin * 3 * TW + xbase;
        #pragma unroll
        for (int r = 0; r < 3; r++) {
            float seg[SEG];
            const float* srow = srowbase + r * TW;
            #pragma unroll
            for (int i = 0; i < SEG; i++) seg[i] = srow[i];
            float w0 = wp[(cin*9 + r*3 + 0) * CoutP];
            float w1 = wp[(cin*9 + r*3 + 1) * CoutP];
            float w2 = wp[(cin*9 + r*3 + 2) * CoutP];
            #pragma unroll
            for (int px = 0; px < 16; px++) {
                acc[px] = fmaf(w0, seg[px],
                           fmaf(w1, seg[px + DIL],
                            fmaf(w2, seg[px + 2*DIL], acc[px])));
            }
        }
    }

    if (cout < Cout) {
        int ob = ((b*Cout + cout)*HH + y)*WW + x0 + xbase;
        #pragma unroll
        for (int px = 0; px < 16; px++) {
            float v = acc[px];
            if (ACT == 1) v = fmaxf(v, 0.f);
            else if (ACT == 2) v = (v > 0.f) ? v : 0.1f * v;
            if (EPI == 0)      out[ob + px] = v;
            else if (EPI == 1) out[ob + px] = res[ob + px] + v;
            else               out[ob + px] = out[ob + px] + 0.1f * v;
        }
    }
}

// ---------------------------------------------------------------------------
// Modulated deformable conv (DG=8 offset groups, full 64x64 weight, 3x3)
// Per tap k: 512 (pixel,group) sampling tasks fill sS[64ch][64px] in smem,
// then a register-blocked rank-64 update into 64cout x 16px accumulators.
// ---------------------------------------------------------------------------
__global__ void __launch_bounds__(256, 2)
dcn_kernel(const float* __restrict__ supp, const float* __restrict__ off,
           const float* __restrict__ flow, const float* __restrict__ wT,
           const float* __restrict__ bias, float* __restrict__ out)
{
    __shared__ __align__(16) float sS[64*64];
    int b  = blockIdx.z;
    int y  = blockIdx.y;
    int x0 = blockIdx.x * 64;
    int tid  = threadIdx.x;
    int cout = tid & 63;
    int pg   = tid >> 6;

    float bv = bias[cout];
    float acc[16];
    #pragma unroll
    for (int i = 0; i < 16; i++) acc[i] = bv;

    const float* fxp  = flow + (b*2 + 0)*HWSZ + y*WW + x0;
    const float* fyp  = flow + (b*2 + 1)*HWSZ + y*WW + x0;
    const float* offb = off  + b*216*HWSZ + y*WW + x0;

    for (int k = 0; k < NTAP; k++) {
        int ki = k / 3, kj = k % 3;
        __syncthreads();   // protect sS from previous iteration's readers
        #pragma unroll
        for (int it = 0; it < 2; it++) {
            int t  = tid + 256 * it;
            int px = t & 63;
            int g  = t >> 6;
            int cdy = g*18 + k*2;
            float rawdy = offb[cdy        *HWSZ + px];
            float rawdx = offb[(cdy + 1)  *HWSZ + px];
            float rawm  = offb[(144 + g*9 + k)*HWSZ + px];
            float fx = fxp[px], fy = fyp[px];
            // offset channel c gets +flow_x if c<72 else +flow_y (reference quirk)
            float ady = 25.f * tanhf(rawdy) + ((cdy     < 72) ? fx : fy);
            float adx = 25.f * tanhf(rawdx) + ((cdy + 1 < 72) ? fx : fy);
            float m   = 1.f / (1.f + expf(-rawm));
            float sy = (float)y        + (float)(ki - 1) + ady;
            float sx = (float)(x0 + px)+ (float)(kj - 1) + adx;
            float y0f = floorf(sy), x0f = floorf(sx);
            int iy0 = (int)y0f, ix0 = (int)x0f;
            int iy1 = iy0 + 1,  ix1 = ix0 + 1;
            float wy = sy - y0f, wx = sx - x0f;
            bool vy0 = ((unsigned)iy0 < HH), vy1 = ((unsigned)iy1 < HH);
            bool vx0 = ((unsigned)ix0 < WW), vx1 = ((unsigned)ix1 < WW);
            float w00 = (1.f - wy)*(1.f - wx) * ((vy0 && vx0) ? 1.f : 0.f) * m;
            float w01 = (1.f - wy)*wx         * ((vy0 && vx1) ? 1.f : 0.f) * m;
            float w10 = wy*(1.f - wx)         * ((vy1 && vx0) ? 1.f : 0.f) * m;
            float w11 = wy*wx                 * ((vy1 && vx1) ? 1.f : 0.f) * m;
            int cy0 = min(max(iy0, 0), HH-1), cy1 = min(max(iy1, 0), HH-1);
            int cx0 = min(max(ix0, 0), WW-1), cx1 = min(max(ix1, 0), WW-1);
            int i00 = cy0*WW + cx0, i01 = cy0*WW + cx1;
            int i10 = cy1*WW + cx0, i11 = cy1*WW + cx1;
            const float* sb = supp + (b*64 + g*8)*HWSZ;
            #pragma unroll
            for (int c = 0; c < 8; c++) {
                const float* ch = sb + c*HWSZ;
                float v = w00*ch[i00] + w01*ch[i01] + w10*ch[i10] + w11*ch[i11];
                sS[(g*8 + c)*64 + px] = v;
            }
        }
        __syncthreads();

        const float* wk = wT + k*64*64 + cout;
        #pragma unroll 4
        for (int c = 0; c < 64; c++) {
            float wv = wk[c*64];
            const float4* sr = (const float4*)(sS + c*64 + pg*16);
            #pragma unroll
            for (int q = 0; q < 4; q++) {
                float4 v = sr[q];
                acc[q*4+0] = fmaf(wv, v.x, acc[q*4+0]);
                acc[q*4+1] = fmaf(wv, v.y, acc[q*4+1]);
                acc[q*4+2] = fmaf(wv, v.z, acc[q*4+2]);
                acc[q*4+3] = fmaf(wv, v.w, acc[q*4+3]);
            }
        }
    }

    int ob = ((b*64 + cout)*HH + y)*WW + x0 + pg*16;
    #pragma unroll
    for (int px = 0; px < 16; px++) out[ob + px] = acc[px];
}

// ---------------------------------------------------------------------------
// Launch
// ---------------------------------------------------------------------------
extern "C" void kernel_launch(void* const* d_in, const int* in_sizes, int n_in,
                              void* d_out, int out_size)
{
    const float* ref   = (const float*)d_in[0];
    const float* supp  = (const float*)d_in[1];
    const float* flow  = (const float*)d_in[2];
    const float* fc_w  = (const float*)d_in[3];
    const float* fc_b  = (const float*)d_in[4];
    const float* cw[6], *cb[6];
    for (int i = 0; i < 6; i++) {
        cw[i] = (const float*)d_in[5 + 2*i];
        cb[i] = (const float*)d_in[6 + 2*i];
    }
    const float* off_w = (const float*)d_in[17];
    const float* off_b = (const float*)d_in[18];
    const float* dcn_w = (const float*)d_in[19];
    const float* dcn_b = (const float*)d_in[20];
    float* out = (float*)d_out;

    float *warped, *feat0, *tmp, *feat, *offbuf;
    float *wT_fc, *wT_c1, *wT_c2, *wT_c3, *wT_c4, *wT_c5, *wT_c6, *wT_off, *wT_dcn;
    cudaGetSymbolAddress((void**)&warped, g_warped);
    cudaGetSymbolAddress((void**)&feat0,  g_feat0);
    cudaGetSymbolAddress((void**)&tmp,    g_tmp);
    cudaGetSymbolAddress((void**)&feat,   g_feat);
    cudaGetSymbolAddress((void**)&offbuf, g_off);
    cudaGetSymbolAddress((void**)&wT_fc,  g_wT_fc);
    cudaGetSymbolAddress((void**)&wT_c1,  g_wT_c1);
    cudaGetSymbolAddress((void**)&wT_c2,  g_wT_c2);
    cudaGetSymbolAddress((void**)&wT_c3,  g_wT_c3);
    cudaGetSymbolAddress((void**)&wT_c4,  g_wT_c4);
    cudaGetSymbolAddress((void**)&wT_c5,  g_wT_c5);
    cudaGetSymbolAddress((void**)&wT_c6,  g_wT_c6);
    cudaGetSymbolAddress((void**)&wT_off, g_wT_off);
    cudaGetSymbolAddress((void**)&wT_dcn, g_wT_dcn);

    // Dynamic smem opt-in (idempotent)
    const int SM_FC = 128*3*(64+2)*4;   // 101376
    const int SM_D1 = 64*3*(64+2)*4;    // 50688
    const int SM_D2 = 64*3*(64+4)*4;    // 52224
    const int SM_D4 = 64*3*(64+8)*4;    // 55296
    cudaFuncSetAttribute((const void*)conv3x3_kernel<128,1,2,0,1>, cudaFuncAttributeMaxDynamicSharedMemorySize, SM_FC);
    cudaFuncSetAttribute((const void*)conv3x3_kernel<64,1,1,0,1>,  cudaFuncAttributeMaxDynamicSharedMemorySize, SM_D1);
    cudaFuncSetAttribute((const void*)conv3x3_kernel<64,1,1,1,1>,  cudaFuncAttributeMaxDynamicSharedMemorySize, SM_D1);
    cudaFuncSetAttribute((const void*)conv3x3_kernel<64,2,1,0,1>,  cudaFuncAttributeMaxDynamicSharedMemorySize, SM_D2);
    cudaFuncSetAttribute((const void*)conv3x3_kernel<64,2,1,2,1>,  cudaFuncAttributeMaxDynamicSharedMemorySize, SM_D2);
    cudaFuncSetAttribute((const void*)conv3x3_kernel<64,4,1,2,1>,  cudaFuncAttributeMaxDynamicSharedMemorySize, SM_D4);
    cudaFuncSetAttribute((const void*)conv3x3_kernel<64,1,0,0,4>,  cudaFuncAttributeMaxDynamicSharedMemorySize, SM_D1);

    // Weight transposes
    {
        int t;
        t = 128*9*64;  transpose_w_kernel<<<(t+255)/256, 256>>>(fc_w,  wT_fc, 128, 64, 64);
        t = 64*9*64;
        transpose_w_kernel<<<(t+255)/256, 256>>>(cw[0], wT_c1, 64, 64, 64);
        transpose_w_kernel<<<(t+255)/256, 256>>>(cw[1], wT_c2, 64, 64, 64);
        transpose_w_kernel<<<(t+255)/256, 256>>>(cw[2], wT_c3, 64, 64, 64);
        transpose_w_kernel<<<(t+255)/256, 256>>>(cw[3], wT_c4, 64, 64, 64);
        transpose_w_kernel<<<(t+255)/256, 256>>>(cw[4], wT_c5, 64, 64, 64);
        transpose_w_kernel<<<(t+255)/256, 256>>>(cw[5], wT_c6, 64, 64, 64);
        t = 64*9*256;  transpose_w_kernel<<<(t+255)/256, 256>>>(off_w, wT_off, 64, 216, 256);
        t = 9*64*64;   transpose_dcn_kernel<<<(t+255)/256, 256>>>(dcn_w, wT_dcn);
    }

    // 1. flow warp
    warp_kernel<<<dim3(HWSZ/256, BB), 256>>>(supp, flow, warped);

    dim3 cgrid(WW/64, HH, BB);
    // 2. fc conv: concat(warped, ref) -> feat0, lrelu 0.1
    conv3x3_kernel<128,1,2,0,1><<<cgrid, 256, SM_FC>>>(warped, ref, wT_fc, fc_b, feat0, nullptr, 64, 64);
    // 3-4. b1 branch
    conv3x3_kernel<64,1,1,0,1><<<cgrid, 256, SM_D1>>>(feat0, feat0, wT_c1, cb[0], tmp, nullptr, 64, 64);
    conv3x3_kernel<64,1,1,1,1><<<cgrid, 256, SM_D1>>>(tmp, tmp, wT_c2, cb[1], feat, feat0, 64, 64);
    // 5-6. b2 branch (feat += 0.1*b2)
    conv3x3_kernel<64,2,1,0,1><<<cgrid, 256, SM_D2>>>(feat0, feat0, wT_c3, cb[2], tmp, nullptr, 64, 64);
    conv3x3_kernel<64,2,1,2,1><<<cgrid, 256, SM_D2>>>(tmp, tmp, wT_c4, cb[3], feat, nullptr, 64, 64);
    // 7-8. b3 branch (feat += 0.1*b3)
    conv3x3_kernel<64,2,1,0,1><<<cgrid, 256, SM_D2>>>(feat0, feat0, wT_c5, cb[4], tmp, nullptr, 64, 64);
    conv3x3_kernel<64,4,1,2,1><<<cgrid, 256, SM_D4>>>(tmp, tmp, wT_c6, cb[5], feat, nullptr, 64, 64);
    // 9. offset/mask conv: 64 -> 216 (4 chunks of 64 couts, padded weights)
    dim3 ogrid(WW/64, HH, BB*4);
    conv3x3_kernel<64,1,0,0,4><<<ogrid, 256, SM_D1>>>(feat, feat, wT_off, off_b, offbuf, nullptr, 216, 256);
    // 10. modulated deformable conv
    dcn_kernel<<<cgrid, 256>>>(supp, offbuf, flow, wT_dcn, dcn_b, out);
}

// round 5
// speedup vs baseline: 1.6700x; 1.6700x over previous
#include <cuda_runtime.h>
#include <cuda_bf16.h>
#include <math.h>
#include <stdint.h>

#define BB 4
#define HH 256
#define WW 256
#define HWSZ 65536
#define NPX (BB*HWSZ)

// ---------------------------------------------------------------------------
// PTX helpers (plain sm_103-safe: ldmatrix + mma.sync only)
// ---------------------------------------------------------------------------
__device__ __forceinline__ uint32_t smem_u32(const void* p) {
    uint32_t a;
    asm("{ .reg .u64 t; cvta.to.shared.u64 t, %1; cvt.u32.u64 %0, t; }" : "=r"(a) : "l"(p));
    return a;
}

#define LDSM_X4(r0, r1, r2, r3, addr) \
    asm volatile("ldmatrix.sync.aligned.m8n8.x4.shared.b16 {%0,%1,%2,%3}, [%4];" \
        : "=r"(r0), "=r"(r1), "=r"(r2), "=r"(r3) : "r"(addr))

#define MMA_BF16(d, a, b0v, b1v) \
    asm volatile("mma.sync.aligned.m16n8k16.row.col.f32.bf16.bf16.f32 " \
        "{%0,%1,%2,%3},{%4,%5,%6,%7},{%8,%9},{%0,%1,%2,%3};" \
        : "+f"((d)[0]), "+f"((d)[1]), "+f"((d)[2]), "+f"((d)[3]) \
        : "r"((a)[0]), "r"((a)[1]), "r"((a)[2]), "r"((a)[3]), "r"(b0v), "r"(b1v))

// ---------------------------------------------------------------------------
// Device global scratch
// ---------------------------------------------------------------------------
#define FEAT_ELEMS ((size_t)NPX*64)
__device__ __nv_bfloat16 g_wH[FEAT_ELEMS], g_wL[FEAT_ELEMS];     // warped supp
__device__ __nv_bfloat16 g_rH[FEAT_ELEMS], g_rL[FEAT_ELEMS];     // ref
__device__ __nv_bfloat16 g_t0H[FEAT_ELEMS], g_t0L[FEAT_ELEMS];   // feat0
__device__ __nv_bfloat16 g_tmpH[FEAT_ELEMS], g_tmpL[FEAT_ELEMS];
__device__ __nv_bfloat16 g_ftH[FEAT_ELEMS], g_ftL[FEAT_ELEMS];   // final feat
__device__ float g_partF[FEAT_ELEMS];                             // fc partial
__device__ float g_f0F[FEAT_ELEMS];                               // feat0 fp32
__device__ float g_ffF[FEAT_ELEMS];                               // feat fp32 accum
__device__ float g_off[(size_t)BB*216*HWSZ];                      // NCHW
// 12 B-sets (fc0, fc1, c1..c6, off chunks 0..3), each 9 taps x (hi 8KB + lo 8KB)
#define BSET 73728
__device__ __nv_bfloat16 g_B[12*BSET];
__device__ float g_wT_dcn[9*64*64];

// ---------------------------------------------------------------------------
// B prep: OIHW fp32 -> per-tap SW128-swizzled bf16 hi/lo [cout row][cin col]
// ---------------------------------------------------------------------------
__global__ void prep_B_kernel(const float* __restrict__ w, __nv_bfloat16* __restrict__ out,
                              int cinTot, int cin0, int coutTot, int cout0)
{
    int idx = blockIdx.x * 256 + threadIdx.x;   // 9*64*64 = 36864
    if (idx >= 36864) return;
    int c = idx & 63;
    int r = (idx >> 6) & 63;
    int t = idx >> 12;
    float v = 0.f;
    int co = cout0 + r;
    if (co < coutTot) v = w[((size_t)co * cinTot + cin0 + c) * 9 + t];
    __nv_bfloat16 h = __float2bfloat16(v);
    __nv_bfloat16 l = __float2bfloat16(v - __bfloat162float(h));
    uint32_t off = (uint32_t)r * 128u + (uint32_t)c * 2u;
    uint32_t so = off ^ ((off >> 3) & 0x70u);
    char* ob = (char*)out + (size_t)t * 16384;
    *(__nv_bfloat16*)(ob + so) = h;
    *(__nv_bfloat16*)(ob + 8192 + so) = l;
}

__global__ void transpose_dcn_kernel(const float* __restrict__ w, float* __restrict__ wT)
{
    int idx = blockIdx.x * 256 + threadIdx.x;
    if (idx >= 9*64*64) return;
    int cout = idx % 64;
    int c    = (idx / 64) % 64;
    int k    = idx / (64 * 64);
    wT[idx] = w[(cout * 64 + c) * 9 + k];
}

// ---------------------------------------------------------------------------
// flow_warp -> NHWC bf16 hi/lo
// ---------------------------------------------------------------------------
__global__ void warp_nhwc_kernel(const float* __restrict__ supp, const float* __restrict__ flow,
                                 __nv_bfloat16* __restrict__ oH, __nv_bfloat16* __restrict__ oL)
{
    int p = blockIdx.x * 256 + threadIdx.x;
    int b = blockIdx.y;
    int y = p >> 8, x = p & 255;
    float fx = flow[((size_t)b*2    )*HWSZ + p];
    float fy = flow[((size_t)b*2 + 1)*HWSZ + p];
    float sy = (float)y + fy, sx = (float)x + fx;
    float y0f = floorf(sy), x0f = floorf(sx);
    int iy0 = (int)y0f, ix0 = (int)x0f, iy1 = iy0+1, ix1 = ix0+1;
    float wy = sy - y0f, wx = sx - x0f;
    bool vy0 = ((unsigned)iy0 < HH), vy1 = ((unsigned)iy1 < HH);
    bool vx0 = ((unsigned)ix0 < WW), vx1 = ((unsigned)ix1 < WW);
    float w00 = (1.f-wy)*(1.f-wx) * ((vy0&&vx0)?1.f:0.f);
    float w01 = (1.f-wy)*wx       * ((vy0&&vx1)?1.f:0.f);
    float w10 = wy*(1.f-wx)       * ((vy1&&vx0)?1.f:0.f);
    float w11 = wy*wx             * ((vy1&&vx1)?1.f:0.f);
    int cy0 = min(max(iy0,0),HH-1), cy1 = min(max(iy1,0),HH-1);
    int cx0 = min(max(ix0,0),WW-1), cx1 = min(max(ix1,0),WW-1);
    int i00 = cy0*WW+cx0, i01 = cy0*WW+cx1, i10 = cy1*WW+cx0, i11 = cy1*WW+cx1;
    const float* sb = supp + (size_t)b*64*HWSZ;
    __nv_bfloat16* ohp = oH + ((size_t)b*HWSZ + p)*64;
    __nv_bfloat16* olp = oL + ((size_t)b*HWSZ + p)*64;
    for (int g = 0; g < 8; g++) {
        uint4 uh, ul;
        uint32_t* ph = (uint32_t*)&uh;
        uint32_t* pl = (uint32_t*)&ul;
        #pragma unroll
        for (int q = 0; q < 4; q++) {
            const float* c0 = sb + (size_t)(g*8 + q*2)*HWSZ;
            const float* c1 = c0 + HWSZ;
            float v0 = w00*c0[i00] + w01*c0[i01] + w10*c0[i10] + w11*c0[i11];
            float v1 = w00*c1[i00] + w01*c1[i01] + w10*c1[i10] + w11*c1[i11];
            __nv_bfloat162 h2 = __floats2bfloat162_rn(v0, v1);
            float2 hf = __bfloat1622float2(h2);
            __nv_bfloat162 l2 = __floats2bfloat162_rn(v0 - hf.x, v1 - hf.y);
            ph[q] = *(uint32_t*)&h2;
            pl[q] = *(uint32_t*)&l2;
        }
        ((uint4*)ohp)[g] = uh;
        ((uint4*)olp)[g] = ul;
    }
}

// NCHW fp32 -> NHWC bf16 hi/lo
__global__ void to_nhwc_kernel(const float* __restrict__ src,
                               __nv_bfloat16* __restrict__ oH, __nv_bfloat16* __restrict__ oL)
{
    int p = blockIdx.x * 256 + threadIdx.x;
    int b = blockIdx.y;
    const float* sp = src + (size_t)b*64*HWSZ + p;
    __nv_bfloat16* ohp = oH + ((size_t)b*HWSZ + p)*64;
    __nv_bfloat16* olp = oL + ((size_t)b*HWSZ + p)*64;
    for (int g = 0; g < 8; g++) {
        uint4 uh, ul;
        uint32_t* ph = (uint32_t*)&uh;
        uint32_t* pl = (uint32_t*)&ul;
        #pragma unroll
        for (int q = 0; q < 4; q++) {
            float v0 = sp[(size_t)(g*8 + q*2    )*HWSZ];
            float v1 = sp[(size_t)(g*8 + q*2 + 1)*HWSZ];
            __nv_bfloat162 h2 = __floats2bfloat162_rn(v0, v1);
            float2 hf = __bfloat1622float2(h2);
            __nv_bfloat162 l2 = __floats2bfloat162_rn(v0 - hf.x, v1 - hf.y);
            ph[q] = *(uint32_t*)&h2;
            pl[q] = *(uint32_t*)&l2;
        }
        ((uint4*)ohp)[g] = uh;
        ((uint4*)olp)[g] = ul;
    }
}

// ---------------------------------------------------------------------------
// mma.sync conv: D[128px][64cout] per CTA, 9 taps x (AhBh + AhBl + AlBh).
// 8 warps = 4(M) x 2(N); warp tile 32px x 32cout; acc in registers.
// EPI: 0 raw f32 NHWC; 1 +res lrelu f32+hi/lo; 2 relu hi/lo; 3 relu res+v f32;
//      4 relu outF+=0.1v; 5 relu res+0.1v hi/lo; 6 NCHW f32 (coutTot guard)
// ---------------------------------------------------------------------------
template<int DIL, int EPI, int HASBIAS>
__global__ void __launch_bounds__(256, 1)
conv_mma_kernel(const __nv_bfloat16* __restrict__ inH,
                const __nv_bfloat16* __restrict__ inL,
                const __nv_bfloat16* __restrict__ Bimg,
                const float* __restrict__ bias,
                int nchunk, int coutTot,
                float* __restrict__ outF,
                __nv_bfloat16* __restrict__ outH,
                __nv_bfloat16* __restrict__ outL,
                const float* __restrict__ resF,
                float* __restrict__ outNCHW)
{
    extern __shared__ char smem[];
    uint32_t sb0 = smem_u32(smem);
    uint32_t base = (sb0 + 1023u) & ~1023u;
    const uint32_t SM_B = base;              // 147456 bytes (9 taps x hi/lo 8KB)
    const uint32_t SM_A = base + 147456u;    // 32768 bytes (hi 16KB + lo 16KB)
    uint32_t pad = base - sb0;

    int tid = threadIdx.x;
    int lane = tid & 31, w = tid >> 5;
    int z = blockIdx.z;
    int b = z / nchunk, chunk = z - b * nchunk;
    int y = blockIdx.y, x0 = blockIdx.x * 128;

    // Copy whole-layer B into smem
    {
        const uint4* bs = (const uint4*)Bimg + (size_t)chunk * (147456 / 16);
        uint4* bd = (uint4*)(smem + pad);
        #pragma unroll 4
        for (int i = tid; i < 147456 / 16; i += 256) bd[i] = bs[i];
    }

    int mbase = (w & 3) * 32;        // warp px base within tile
    int nbase = (w >> 2) * 32;       // warp cout base

    float acc[2][4][4];
    #pragma unroll
    for (int i = 0; i < 2; i++)
        #pragma unroll
        for (int j = 0; j < 4; j++)
            #pragma unroll
            for (int q = 0; q < 4; q++) acc[i][j][q] = 0.f;

    __syncthreads();

    int spx = tid >> 1, shf = tid & 1;  // staging: px, cin-half

    for (int t = 0; t < 9; t++) {
        // ---- stage A (hi+lo) for this tap ----
        int ki = t / 3, kj = t - ki * 3;
        int gy = y + (ki - 1) * DIL;
        int gx = x0 + spx + (kj - 1) * DIL;
        bool ok = ((unsigned)gy < HH) && ((unsigned)gx < WW);
        size_t gidx = ok ? ((((size_t)b * HH + gy) * WW + gx) * 64 + shf * 32) : 0;
        const uint4* sH = (const uint4*)(inH + gidx);
        const uint4* sL = (const uint4*)(inL + gidx);
        uint4 vh[4], vl[4];
        #pragma unroll
        for (int j = 0; j < 4; j++) {
            vh[j] = ok ? sH[j] : make_uint4(0,0,0,0);
            vl[j] = ok ? sL[j] : make_uint4(0,0,0,0);
        }
        #pragma unroll
        for (int j = 0; j < 4; j++) {
            uint32_t off = (uint32_t)spx * 128u + (uint32_t)shf * 64u + (uint32_t)j * 16u;
            uint32_t so = (uint32_t)spx * 128u +
                          (((uint32_t)shf * 64u + (uint32_t)j * 16u) ^ (((uint32_t)spx & 7u) * 16u));
            (void)off;
            asm volatile("st.shared.v4.b32 [%0], {%1,%2,%3,%4};"
                :: "r"(SM_A + so), "r"(vh[j].x), "r"(vh[j].y), "r"(vh[j].z), "r"(vh[j].w) : "memory");
            asm volatile("st.shared.v4.b32 [%0], {%1,%2,%3,%4};"
                :: "r"(SM_A + 16384u + so), "r"(vl[j].x), "r"(vl[j].y), "r"(vl[j].z), "r"(vl[j].w) : "memory");
        }
        __syncthreads();

        // ---- compute: 3 combos x 4 ksteps ----
        uint32_t Bt = SM_B + (uint32_t)t * 16384u;
        // precomputed ldmatrix row terms
        int lr = (lane & 7) + ((lane >> 3) & 1) * 8;   // row within 16-block
        int kq = (lane >> 4) * 16;                     // 16B col-half select
        #pragma unroll
        for (int combo = 0; combo < 3; combo++) {
            uint32_t Abuf = SM_A + ((combo == 2) ? 16384u : 0u);
            uint32_t Bbuf = Bt + ((combo == 1) ? 8192u : 0u);
            #pragma unroll
            for (int ks = 0; ks < 4; ks++) {
                uint32_t kb = (uint32_t)(ks * 32 + kq);
                uint32_t a0[4], a1[4], b0[4], b1[4];
                {
                    uint32_t row = (uint32_t)(mbase + lr);
                    LDSM_X4(a0[0], a0[1], a0[2], a0[3],
                            Abuf + row*128u + (kb ^ ((row & 7u)*16u)));
                    row += 16u;
                    LDSM_X4(a1[0], a1[1], a1[2], a1[3],
                            Abuf + row*128u + (kb ^ ((row & 7u)*16u)));
                }
                {
                    uint32_t row = (uint32_t)(nbase + lr);
                    LDSM_X4(b0[0], b0[1], b0[2], b0[3],
                            Bbuf + row*128u + (kb ^ ((row & 7u)*16u)));
                    row += 16u;
                    LDSM_X4(b1[0], b1[1], b1[2], b1[3],
                            Bbuf + row*128u + (kb ^ ((row & 7u)*16u)));
                }
                MMA_BF16(acc[0][0], a0, b0[0], b0[2]);
                MMA_BF16(acc[0][1], a0, b0[1], b0[3]);
                MMA_BF16(acc[0][2], a0, b1[0], b1[2]);
                MMA_BF16(acc[0][3], a0, b1[1], b1[3]);
                MMA_BF16(acc[1][0], a1, b0[0], b0[2]);
                MMA_BF16(acc[1][1], a1, b0[1], b0[3]);
                MMA_BF16(acc[1][2], a1, b1[0], b1[2]);
                MMA_BF16(acc[1][3], a1, b1[1], b1[3]);
            }
        }
        __syncthreads();
    }

    // ---- epilogue ----
    // d-frag mapping: pair (d0,d1)/(d2,d3): px = mbase+mt*16+(lane>>2)+rh*8,
    //                 cout = nbase+nb*8+(lane&3)*2 (+1)
    float bs2[4][2];
    #pragma unroll
    for (int nb = 0; nb < 4; nb++) {
        int co = chunk * 64 + nbase + nb * 8 + (lane & 3) * 2;
        bs2[nb][0] = (HASBIAS && co     < coutTot) ? bias[co]     : 0.f;
        bs2[nb][1] = (HASBIAS && co + 1 < coutTot) ? bias[co + 1] : 0.f;
    }
    #pragma unroll
    for (int mt = 0; mt < 2; mt++) {
        #pragma unroll
        for (int rh = 0; rh < 2; rh++) {
            int px = x0 + mbase + mt * 16 + (lane >> 2) + rh * 8;
            size_t P = ((size_t)b * HH + y) * WW + px;
            #pragma unroll
            for (int nb = 0; nb < 4; nb++) {
                int cl = nbase + nb * 8 + (lane & 3) * 2;   // local cout 0..63
                float v0 = acc[mt][nb][rh * 2 + 0] + bs2[nb][0];
                float v1 = acc[mt][nb][rh * 2 + 1] + bs2[nb][1];
                size_t ob = P * 64 + cl;

                if (EPI == 0) {
                    *(float2*)(outF + ob) = make_float2(v0, v1);
                } else if (EPI == 1) {
                    float2 rv = *(const float2*)(resF + ob);
                    v0 += rv.x; v1 += rv.y;
                    v0 = (v0 > 0.f) ? v0 : 0.1f * v0;
                    v1 = (v1 > 0.f) ? v1 : 0.1f * v1;
                    *(float2*)(outF + ob) = make_float2(v0, v1);
                    __nv_bfloat162 h2 = __floats2bfloat162_rn(v0, v1);
                    float2 hf = __bfloat1622float2(h2);
                    __nv_bfloat162 l2 = __floats2bfloat162_rn(v0 - hf.x, v1 - hf.y);
                    *(uint32_t*)(outH + ob) = *(uint32_t*)&h2;
                    *(uint32_t*)(outL + ob) = *(uint32_t*)&l2;
                } else if (EPI == 2) {
                    v0 = fmaxf(v0, 0.f); v1 = fmaxf(v1, 0.f);
                    __nv_bfloat162 h2 = __floats2bfloat162_rn(v0, v1);
                    float2 hf = __bfloat1622float2(h2);
                    __nv_bfloat162 l2 = __floats2bfloat162_rn(v0 - hf.x, v1 - hf.y);
                    *(uint32_t*)(outH + ob) = *(uint32_t*)&h2;
                    *(uint32_t*)(outL + ob) = *(uint32_t*)&l2;
                } else if (EPI == 3) {
                    float2 rv = *(const float2*)(resF + ob);
                    v0 = rv.x + fmaxf(v0, 0.f);
                    v1 = rv.y + fmaxf(v1, 0.f);
                    *(float2*)(outF + ob) = make_float2(v0, v1);
                } else if (EPI == 4) {
                    float2 rv = *(const float2*)(outF + ob);
                    v0 = rv.x + 0.1f * fmaxf(v0, 0.f);
                    v1 = rv.y + 0.1f * fmaxf(v1, 0.f);
                    *(float2*)(outF + ob) = make_float2(v0, v1);
                } else if (EPI == 5) {
                    float2 rv = *(const float2*)(resF + ob);
                    v0 = rv.x + 0.1f * fmaxf(v0, 0.f);
                    v1 = rv.y + 0.1f * fmaxf(v1, 0.f);
                    __nv_bfloat162 h2 = __floats2bfloat162_rn(v0, v1);
                    float2 hf = __bfloat1622float2(h2);
                    __nv_bfloat162 l2 = __floats2bfloat162_rn(v0 - hf.x, v1 - hf.y);
                    *(uint32_t*)(outH + ob) = *(uint32_t*)&h2;
                    *(uint32_t*)(outL + ob) = *(uint32_t*)&l2;
                } else if (EPI == 6) {
                    int co = chunk * 64 + cl;
                    size_t pix = ((size_t)y << 8) + px;
                    if (co < coutTot)
                        outNCHW[(((size_t)b * coutTot + co) << 16) + pix] = v0;
                    if (co + 1 < coutTot)
                        outNCHW[(((size_t)b * coutTot + co + 1) << 16) + pix] = v1;
                }
            }
        }
    }
}

// ---------------------------------------------------------------------------
// Modulated deformable conv (proven fp32 path)
// ---------------------------------------------------------------------------
__global__ void __launch_bounds__(256, 2)
dcn_kernel(const float* __restrict__ supp, const float* __restrict__ off,
           const float* __restrict__ flow, const float* __restrict__ wT,
           const float* __restrict__ bias, float* __restrict__ out)
{
    __shared__ __align__(16) float sS[64*64];
    int b  = blockIdx.z;
    int y  = blockIdx.y;
    int x0 = blockIdx.x * 64;
    int tid  = threadIdx.x;
    int cout = tid & 63;
    int pg   = tid >> 6;

    float bv = bias[cout];
    float acc[16];
    #pragma unroll
    for (int i = 0; i < 16; i++) acc[i] = bv;

    const float* fxp  = flow + ((size_t)b*2 + 0)*HWSZ + y*WW + x0;
    const float* fyp  = flow + ((size_t)b*2 + 1)*HWSZ + y*WW + x0;
    const float* offb = off  + (size_t)b*216*HWSZ + y*WW + x0;

    for (int k = 0; k < 9; k++) {
        int ki = k / 3, kj = k % 3;
        __syncthreads();
        #pragma unroll
        for (int it = 0; it < 2; it++) {
            int t  = tid + 256 * it;
            int px = t & 63;
            int g  = t >> 6;
            int cdy = g*18 + k*2;
            float rawdy = offb[(size_t)cdy          *HWSZ + px];
            float rawdx = offb[(size_t)(cdy + 1)    *HWSZ + px];
            float rawm  = offb[(size_t)(144 + g*9+k)*HWSZ + px];
            float fx = fxp[px], fy = fyp[px];
            float ady = 25.f * tanhf(rawdy) + ((cdy     < 72) ? fx : fy);
            float adx = 25.f * tanhf(rawdx) + ((cdy + 1 < 72) ? fx : fy);
            float m   = 1.f / (1.f + expf(-rawm));
            float sy = (float)y         + (float)(ki - 1) + ady;
            float sx = (float)(x0 + px) + (float)(kj - 1) + adx;
            float y0f = floorf(sy), x0f = floorf(sx);
            int iy0 = (int)y0f, ix0 = (int)x0f;
            int iy1 = iy0 + 1,  ix1 = ix0 + 1;
            float wy = sy - y0f, wx = sx - x0f;
            bool vy0 = ((unsigned)iy0 < HH), vy1 = ((unsigned)iy1 < HH);
            bool vx0 = ((unsigned)ix0 < WW), vx1 = ((unsigned)ix1 < WW);
            float w00 = (1.f - wy)*(1.f - wx) * ((vy0 && vx0) ? 1.f : 0.f) * m;
            float w01 = (1.f - wy)*wx         * ((vy0 && vx1) ? 1.f : 0.f) * m;
            float w10 = wy*(1.f - wx)         * ((vy1 && vx0) ? 1.f : 0.f) * m;
            float w11 = wy*wx                 * ((vy1 && vx1) ? 1.f : 0.f) * m;
            int cy0 = min(max(iy0, 0), HH-1), cy1 = min(max(iy1, 0), HH-1);
            int cx0 = min(max(ix0, 0), WW-1), cx1 = min(max(ix1, 0), WW-1);
            int i00 = cy0*WW + cx0, i01 = cy0*WW + cx1;
            int i10 = cy1*WW + cx0, i11 = cy1*WW + cx1;
            const float* sb = supp + ((size_t)b*64 + g*8)*HWSZ;
            #pragma unroll
            for (int c = 0; c < 8; c++) {
                const float* ch = sb + (size_t)c*HWSZ;
                float v = w00*ch[i00] + w01*ch[i01] + w10*ch[i10] + w11*ch[i11];
                sS[(g*8 + c)*64 + px] = v;
            }
        }
        __syncthreads();

        const float* wk = wT + k*64*64 + cout;
        #pragma unroll 4
        for (int c = 0; c < 64; c++) {
            float wv = wk[c*64];
            const float4* sr = (const float4*)(sS + c*64 + pg*16);
            #pragma unroll
            for (int q = 0; q < 4; q++) {
                float4 v = sr[q];
                acc[q*4+0] = fmaf(wv, v.x, acc[q*4+0]);
                acc[q*4+1] = fmaf(wv, v.y, acc[q*4+1]);
                acc[q*4+2] = fmaf(wv, v.z, acc[q*4+2]);
                acc[q*4+3] = fmaf(wv, v.w, acc[q*4+3]);
            }
        }
    }

    size_t ob = (((size_t)b*64 + cout)*HH + y)*WW + x0 + pg*16;
    #pragma unroll
    for (int px = 0; px < 16; px++) out[ob + px] = acc[px];
}

// ---------------------------------------------------------------------------
// Launch
// ---------------------------------------------------------------------------
extern "C" void kernel_launch(void* const* d_in, const int* in_sizes, int n_in,
                              void* d_out, int out_size)
{
    const float* ref   = (const float*)d_in[0];
    const float* supp  = (const float*)d_in[1];
    const float* flow  = (const float*)d_in[2];
    const float* fc_w  = (const float*)d_in[3];
    const float* fc_b  = (const float*)d_in[4];
    const float* cw[6], *cb[6];
    for (int i = 0; i < 6; i++) {
        cw[i] = (const float*)d_in[5 + 2*i];
        cb[i] = (const float*)d_in[6 + 2*i];
    }
    const float* off_w = (const float*)d_in[17];
    const float* off_b = (const float*)d_in[18];
    const float* dcn_w = (const float*)d_in[19];
    const float* dcn_b = (const float*)d_in[20];
    float* out = (float*)d_out;

    __nv_bfloat16 *wH, *wL, *rH, *rL, *t0H, *t0L, *tmpH, *tmpL, *ftH, *ftL, *Bg;
    float *partF, *f0F, *ffF, *offbuf, *wTd;
    cudaGetSymbolAddress((void**)&wH,  g_wH);   cudaGetSymbolAddress((void**)&wL,  g_wL);
    cudaGetSymbolAddress((void**)&rH,  g_rH);   cudaGetSymbolAddress((void**)&rL,  g_rL);
    cudaGetSymbolAddress((void**)&t0H, g_t0H);  cudaGetSymbolAddress((void**)&t0L, g_t0L);
    cudaGetSymbolAddress((void**)&tmpH,g_tmpH); cudaGetSymbolAddress((void**)&tmpL,g_tmpL);
    cudaGetSymbolAddress((void**)&ftH, g_ftH);  cudaGetSymbolAddress((void**)&ftL, g_ftL);
    cudaGetSymbolAddress((void**)&Bg,  g_B);
    cudaGetSymbolAddress((void**)&partF, g_partF);
    cudaGetSymbolAddress((void**)&f0F,   g_f0F);
    cudaGetSymbolAddress((void**)&ffF,   g_ffF);
    cudaGetSymbolAddress((void**)&offbuf,g_off);
    cudaGetSymbolAddress((void**)&wTd,   g_wT_dcn);

    const int SMB = 1024 + 147456 + 32768;   // align pad + B layer + A tile
    cudaFuncSetAttribute((const void*)conv_mma_kernel<1,0,1>, cudaFuncAttributeMaxDynamicSharedMemorySize, SMB);
    cudaFuncSetAttribute((const void*)conv_mma_kernel<1,1,0>, cudaFuncAttributeMaxDynamicSharedMemorySize, SMB);
    cudaFuncSetAttribute((const void*)conv_mma_kernel<1,2,1>, cudaFuncAttributeMaxDynamicSharedMemorySize, SMB);
    cudaFuncSetAttribute((const void*)conv_mma_kernel<1,3,1>, cudaFuncAttributeMaxDynamicSharedMemorySize, SMB);
    cudaFuncSetAttribute((const void*)conv_mma_kernel<2,2,1>, cudaFuncAttributeMaxDynamicSharedMemorySize, SMB);
    cudaFuncSetAttribute((const void*)conv_mma_kernel<2,4,1>, cudaFuncAttributeMaxDynamicSharedMemorySize, SMB);
    cudaFuncSetAttribute((const void*)conv_mma_kernel<4,5,1>, cudaFuncAttributeMaxDynamicSharedMemorySize, SMB);
    cudaFuncSetAttribute((const void*)conv_mma_kernel<1,6,1>, cudaFuncAttributeMaxDynamicSharedMemorySize, SMB);

    // Weight prep
    prep_B_kernel<<<144, 256>>>(fc_w, Bg + 0*BSET, 128, 0,  64, 0);
    prep_B_kernel<<<144, 256>>>(fc_w, Bg + 1*BSET, 128, 64, 64, 0);
    for (int i = 0; i < 6; i++)
        prep_B_kernel<<<144, 256>>>(cw[i], Bg + (2+i)*BSET, 64, 0, 64, 0);
    for (int ch = 0; ch < 4; ch++)
        prep_B_kernel<<<144, 256>>>(off_w, Bg + (8+ch)*BSET, 64, 0, 216, ch*64);
    transpose_dcn_kernel<<<144, 256>>>(dcn_w, wTd);

    // Input format conversion
    warp_nhwc_kernel<<<dim3(HWSZ/256, BB), 256>>>(supp, flow, wH, wL);
    to_nhwc_kernel<<<dim3(HWSZ/256, BB), 256>>>(ref, rH, rL);

    dim3 cg(2, 256, 4);
    // fc pass1: warped half (with bias) -> partial fp32
    conv_mma_kernel<1,0,1><<<cg, 256, SMB>>>(wH, wL, Bg + 0*BSET, fc_b, 1, 64,
                                             partF, nullptr, nullptr, nullptr, nullptr);
    // fc pass2: ref half + partial, lrelu -> feat0 (f32 + hi/lo)
    conv_mma_kernel<1,1,0><<<cg, 256, SMB>>>(rH, rL, Bg + 1*BSET, nullptr, 1, 64,
                                             f0F, t0H, t0L, partF, nullptr);
    // c1: relu -> tmp
    conv_mma_kernel<1,2,1><<<cg, 256, SMB>>>(t0H, t0L, Bg + 2*BSET, cb[0], 1, 64,
                                             nullptr, tmpH, tmpL, nullptr, nullptr);
    // c2: ff = feat0 + relu(v)
    conv_mma_kernel<1,3,1><<<cg, 256, SMB>>>(tmpH, tmpL, Bg + 3*BSET, cb[1], 1, 64,
                                             ffF, nullptr, nullptr, f0F, nullptr);
    // c3 (dil2): relu -> tmp
    conv_mma_kernel<2,2,1><<<cg, 256, SMB>>>(t0H, t0L, Bg + 4*BSET, cb[2], 1, 64,
                                             nullptr, tmpH, tmpL, nullptr, nullptr);
    // c4 (dil2): ff += 0.1*relu(v)
    conv_mma_kernel<2,4,1><<<cg, 256, SMB>>>(tmpH, tmpL, Bg + 5*BSET, cb[3], 1, 64,
                                             ffF, nullptr, nullptr, nullptr, nullptr);
    // c5 (dil2): relu -> tmp
    conv_mma_kernel<2,2,1><<<cg, 256, SMB>>>(t0H, t0L, Bg + 6*BSET, cb[4], 1, 64,
                                             nullptr, tmpH, tmpL, nullptr, nullptr);
    // c6 (dil4): feat = ff + 0.1*relu(v) -> hi/lo
    conv_mma_kernel<4,5,1><<<cg, 256, SMB>>>(tmpH, tmpL, Bg + 7*BSET, cb[5], 1, 64,
                                             nullptr, ftH, ftL, ffF, nullptr);
    // offset conv: 216 couts, 4 chunks, NCHW out
    dim3 og(2, 256, 16);
    conv_mma_kernel<1,6,1><<<og, 256, SMB>>>(ftH, ftL, Bg + 8*BSET, off_b, 4, 216,
                                             nullptr, nullptr, nullptr, nullptr, offbuf);
    // deformable conv
    dcn_kernel<<<dim3(4, 256, 4), 256>>>(supp, offbuf, flow, wTd, dcn_b, out);
}

// round 6
// speedup vs baseline: 1.9400x; 1.1617x over previous
#include <cuda_runtime.h>
#include <cuda_bf16.h>
#include <math.h>
#include <stdint.h>

#define BB 4
#define HH 256
#define WW 256
#define HWSZ 65536
#define NPX (BB*HWSZ)

// ---------------------------------------------------------------------------
// PTX helpers (plain sm_103-safe: ldmatrix + mma.sync + cp.async)
// ---------------------------------------------------------------------------
__device__ __forceinline__ uint32_t smem_u32(const void* p) {
    uint32_t a;
    asm("{ .reg .u64 t; cvta.to.shared.u64 t, %1; cvt.u32.u64 %0, t; }" : "=r"(a) : "l"(p));
    return a;
}

#define LDSM_X4(r0, r1, r2, r3, addr) \
    asm volatile("ldmatrix.sync.aligned.m8n8.x4.shared.b16 {%0,%1,%2,%3}, [%4];" \
        : "=r"(r0), "=r"(r1), "=r"(r2), "=r"(r3) : "r"(addr))

#define MMA_BF16(d, a, b0v, b1v) \
    asm volatile("mma.sync.aligned.m16n8k16.row.col.f32.bf16.bf16.f32 " \
        "{%0,%1,%2,%3},{%4,%5,%6,%7},{%8,%9},{%0,%1,%2,%3};" \
        : "+f"((d)[0]), "+f"((d)[1]), "+f"((d)[2]), "+f"((d)[3]) \
        : "r"((a)[0]), "r"((a)[1]), "r"((a)[2]), "r"((a)[3]), "r"(b0v), "r"(b1v))

#define CP_ASYNC16(dst, src, sz) \
    asm volatile("cp.async.cg.shared.global [%0], [%1], 16, %2;" \
        :: "r"(dst), "l"(src), "r"(sz) : "memory")
#define CP_COMMIT() asm volatile("cp.async.commit_group;" ::: "memory")
#define CP_WAIT1() asm volatile("cp.async.wait_group 1;" ::: "memory")
#define CP_WAIT0() asm volatile("cp.async.wait_group 0;" ::: "memory")

// ---------------------------------------------------------------------------
// Device global scratch
// ---------------------------------------------------------------------------
#define FEAT_ELEMS ((size_t)NPX*64)
__device__ __nv_bfloat16 g_wH[FEAT_ELEMS], g_wL[FEAT_ELEMS];     // warped supp
__device__ __nv_bfloat16 g_rH[FEAT_ELEMS], g_rL[FEAT_ELEMS];     // ref
__device__ __nv_bfloat16 g_t0H[FEAT_ELEMS], g_t0L[FEAT_ELEMS];   // feat0
__device__ __nv_bfloat16 g_tmpH[FEAT_ELEMS], g_tmpL[FEAT_ELEMS];
__device__ __nv_bfloat16 g_ftH[FEAT_ELEMS], g_ftL[FEAT_ELEMS];   // final feat
__device__ float g_partF[FEAT_ELEMS];                             // fc partial
__device__ float g_f0F[FEAT_ELEMS];                               // feat0 fp32
__device__ float g_ffF[FEAT_ELEMS];                               // feat fp32 accum
__device__ float g_off[(size_t)BB*216*HWSZ];                      // NCHW
// 12 B-sets (fc0, fc1, c1..c6, off chunks 0..3), each 9 taps x (hi 8KB + lo 8KB)
#define BSET 73728
__device__ __nv_bfloat16 g_B[12*BSET];
__device__ float g_wT_dcn[9*64*64];

// ---------------------------------------------------------------------------
// B prep: OIHW fp32 -> per-tap SW128-swizzled bf16 hi/lo [cout row][cin col]
// ---------------------------------------------------------------------------
__global__ void prep_B_kernel(const float* __restrict__ w, __nv_bfloat16* __restrict__ out,
                              int cinTot, int cin0, int coutTot, int cout0)
{
    int idx = blockIdx.x * 256 + threadIdx.x;   // 9*64*64 = 36864
    if (idx >= 36864) return;
    int c = idx & 63;
    int r = (idx >> 6) & 63;
    int t = idx >> 12;
    float v = 0.f;
    int co = cout0 + r;
    if (co < coutTot) v = w[((size_t)co * cinTot + cin0 + c) * 9 + t];
    __nv_bfloat16 h = __float2bfloat16(v);
    __nv_bfloat16 l = __float2bfloat16(v - __bfloat162float(h));
    uint32_t off = (uint32_t)r * 128u + (uint32_t)c * 2u;
    uint32_t so = off ^ ((off >> 3) & 0x70u);
    char* ob = (char*)out + (size_t)t * 16384;
    *(__nv_bfloat16*)(ob + so) = h;
    *(__nv_bfloat16*)(ob + 8192 + so) = l;
}

__global__ void transpose_dcn_kernel(const float* __restrict__ w, float* __restrict__ wT)
{
    int idx = blockIdx.x * 256 + threadIdx.x;
    if (idx >= 9*64*64) return;
    int cout = idx % 64;
    int c    = (idx / 64) % 64;
    int k    = idx / (64 * 64);
    wT[idx] = w[(cout * 64 + c) * 9 + k];
}

// ---------------------------------------------------------------------------
// flow_warp -> NHWC bf16 hi/lo
// ---------------------------------------------------------------------------
__global__ void warp_nhwc_kernel(const float* __restrict__ supp, const float* __restrict__ flow,
                                 __nv_bfloat16* __restrict__ oH, __nv_bfloat16* __restrict__ oL)
{
    int p = blockIdx.x * 256 + threadIdx.x;
    int b = blockIdx.y;
    int y = p >> 8, x = p & 255;
    float fx = flow[((size_t)b*2    )*HWSZ + p];
    float fy = flow[((size_t)b*2 + 1)*HWSZ + p];
    float sy = (float)y + fy, sx = (float)x + fx;
    float y0f = floorf(sy), x0f = floorf(sx);
    int iy0 = (int)y0f, ix0 = (int)x0f, iy1 = iy0+1, ix1 = ix0+1;
    float wy = sy - y0f, wx = sx - x0f;
    bool vy0 = ((unsigned)iy0 < HH), vy1 = ((unsigned)iy1 < HH);
    bool vx0 = ((unsigned)ix0 < WW), vx1 = ((unsigned)ix1 < WW);
    float w00 = (1.f-wy)*(1.f-wx) * ((vy0&&vx0)?1.f:0.f);
    float w01 = (1.f-wy)*wx       * ((vy0&&vx1)?1.f:0.f);
    float w10 = wy*(1.f-wx)       * ((vy1&&vx0)?1.f:0.f);
    float w11 = wy*wx             * ((vy1&&vx1)?1.f:0.f);
    int cy0 = min(max(iy0,0),HH-1), cy1 = min(max(iy1,0),HH-1);
    int cx0 = min(max(ix0,0),WW-1), cx1 = min(max(ix1,0),WW-1);
    int i00 = cy0*WW+cx0, i01 = cy0*WW+cx1, i10 = cy1*WW+cx0, i11 = cy1*WW+cx1;
    const float* sb = supp + (size_t)b*64*HWSZ;
    __nv_bfloat16* ohp = oH + ((size_t)b*HWSZ + p)*64;
    __nv_bfloat16* olp = oL + ((size_t)b*HWSZ + p)*64;
    for (int g = 0; g < 8; g++) {
        uint4 uh, ul;
        uint32_t* ph = (uint32_t*)&uh;
        uint32_t* pl = (uint32_t*)&ul;
        #pragma unroll
        for (int q = 0; q < 4; q++) {
            const float* c0 = sb + (size_t)(g*8 + q*2)*HWSZ;
            const float* c1 = c0 + HWSZ;
            float v0 = w00*c0[i00] + w01*c0[i01] + w10*c0[i10] + w11*c0[i11];
            float v1 = w00*c1[i00] + w01*c1[i01] + w10*c1[i10] + w11*c1[i11];
            __nv_bfloat162 h2 = __floats2bfloat162_rn(v0, v1);
            float2 hf = __bfloat1622float2(h2);
            __nv_bfloat162 l2 = __floats2bfloat162_rn(v0 - hf.x, v1 - hf.y);
            ph[q] = *(uint32_t*)&h2;
            pl[q] = *(uint32_t*)&l2;
        }
        ((uint4*)ohp)[g] = uh;
        ((uint4*)olp)[g] = ul;
    }
}

// NCHW fp32 -> NHWC bf16 hi/lo
__global__ void to_nhwc_kernel(const float* __restrict__ src,
                               __nv_bfloat16* __restrict__ oH, __nv_bfloat16* __restrict__ oL)
{
    int p = blockIdx.x * 256 + threadIdx.x;
    int b = blockIdx.y;
    const float* sp = src + (size_t)b*64*HWSZ + p;
    __nv_bfloat16* ohp = oH + ((size_t)b*HWSZ + p)*64;
    __nv_bfloat16* olp = oL + ((size_t)b*HWSZ + p)*64;
    for (int g = 0; g < 8; g++) {
        uint4 uh, ul;
        uint32_t* ph = (uint32_t*)&uh;
        uint32_t* pl = (uint32_t*)&ul;
        #pragma unroll
        for (int q = 0; q < 4; q++) {
            float v0 = sp[(size_t)(g*8 + q*2    )*HWSZ];
            float v1 = sp[(size_t)(g*8 + q*2 + 1)*HWSZ];
            __nv_bfloat162 h2 = __floats2bfloat162_rn(v0, v1);
            float2 hf = __bfloat1622float2(h2);
            __nv_bfloat162 l2 = __floats2bfloat162_rn(v0 - hf.x, v1 - hf.y);
            ph[q] = *(uint32_t*)&h2;
            pl[q] = *(uint32_t*)&l2;
        }
        ((uint4*)ohp)[g] = uh;
        ((uint4*)olp)[g] = ul;
    }
}

// ---------------------------------------------------------------------------
// mma.sync conv with cp.async double-buffered A staging.
// D[128px][64cout] per CTA, 9 taps x (AhBh + AhBl + AlBh).
// 8 warps = 4(M) x 2(N); warp tile 32px x 32cout; acc in registers.
// EPI: 0 raw f32 NHWC; 1 +res lrelu f32+hi/lo; 2 relu hi/lo; 3 relu res+v f32;
//      4 relu outF+=0.1v; 5 relu res+0.1v hi/lo; 6 NCHW f32 (coutTot guard)
// ---------------------------------------------------------------------------
template<int DIL, int EPI, int HASBIAS>
__global__ void __launch_bounds__(256, 1)
conv_mma_kernel(const __nv_bfloat16* __restrict__ inH,
                const __nv_bfloat16* __restrict__ inL,
                const __nv_bfloat16* __restrict__ Bimg,
                const float* __restrict__ bias,
                int nchunk, int coutTot,
                float* __restrict__ outF,
                __nv_bfloat16* __restrict__ outH,
                __nv_bfloat16* __restrict__ outL,
                const float* __restrict__ resF,
                float* __restrict__ outNCHW)
{
    extern __shared__ char smem[];
    uint32_t sb0 = smem_u32(smem);
    uint32_t base = (sb0 + 1023u) & ~1023u;
    const uint32_t SM_B = base;              // 147456 bytes (9 taps x hi/lo 8KB)
    const uint32_t SM_A = base + 147456u;    // 2 x 32768 bytes (hi 16KB + lo 16KB)

    int tid = threadIdx.x;
    int lane = tid & 31, w = tid >> 5;
    int z = blockIdx.z;
    int b = z / nchunk, chunk = z - b * nchunk;
    int y = blockIdx.y, x0 = blockIdx.x * 128;

    int spx = tid >> 1, shf = tid & 1;  // staging: px, cin-half
    // Precomputed swizzled staging offsets (per thread, j = 0..3)
    uint32_t sso[4];
    #pragma unroll
    for (int j = 0; j < 4; j++)
        sso[j] = (uint32_t)spx * 128u +
                 (((uint32_t)shf * 64u + (uint32_t)j * 16u) ^ (((uint32_t)spx & 7u) * 16u));

    // ---- B copy via cp.async (group 0, overlapped with tap-0 A prefetch) ----
    {
        const char* bs = (const char*)(Bimg + (size_t)chunk * BSET);
        #pragma unroll 4
        for (int i = tid; i < 147456 / 16; i += 256)
            CP_ASYNC16(SM_B + (uint32_t)i * 16u, bs + (size_t)i * 16, 16);
    }

    // ---- A stage lambda-equivalent (macro-ish via inline code in loop) ----
    // prefetch tap 0 into buffer 0 (same group 0)
    {
        int ki = 0, kj = 0;   // tap 0
        int gy = y + (ki - 1) * DIL;
        int gx = x0 + spx + (kj - 1) * DIL;
        bool ok = ((unsigned)gy < HH) && ((unsigned)gx < WW);
        size_t gidx = ok ? ((((size_t)b * HH + gy) * WW + gx) * 64 + shf * 32) : 0;
        int sz = ok ? 16 : 0;
        const char* pH = (const char*)(inH + gidx);
        const char* pL = (const char*)(inL + gidx);
        #pragma unroll
        for (int j = 0; j < 4; j++) {
            CP_ASYNC16(SM_A + sso[j], pH + j * 16, sz);
            CP_ASYNC16(SM_A + 16384u + sso[j], pL + j * 16, sz);
        }
    }
    CP_COMMIT();

    int mbase = (w & 3) * 32;        // warp px base within tile
    int nbase = (w >> 2) * 32;       // warp cout base

    float acc[2][4][4];
    #pragma unroll
    for (int i = 0; i < 2; i++)
        #pragma unroll
        for (int j = 0; j < 4; j++)
            #pragma unroll
            for (int q = 0; q < 4; q++) acc[i][j][q] = 0.f;

    int lr = (lane & 7) + ((lane >> 3) & 1) * 8;   // ldmatrix row within 16-block
    int kq = (lane >> 4) * 16;                     // 16B col-half select

    for (int t = 0; t < 9; t++) {
        // ---- prefetch tap t+1 into other buffer ----
        if (t < 8) {
            int tn = t + 1;
            int ki = tn / 3, kj = tn - ki * 3;
            int gy = y + (ki - 1) * DIL;
            int gx = x0 + spx + (kj - 1) * DIL;
            bool ok = ((unsigned)gy < HH) && ((unsigned)gx < WW);
            size_t gidx = ok ? ((((size_t)b * HH + gy) * WW + gx) * 64 + shf * 32) : 0;
            int sz = ok ? 16 : 0;
            const char* pH = (const char*)(inH + gidx);
            const char* pL = (const char*)(inL + gidx);
            uint32_t aB = SM_A + (uint32_t)(tn & 1) * 32768u;
            #pragma unroll
            for (int j = 0; j < 4; j++) {
                CP_ASYNC16(aB + sso[j], pH + j * 16, sz);
                CP_ASYNC16(aB + 16384u + sso[j], pL + j * 16, sz);
            }
            CP_COMMIT();
            CP_WAIT1();
        } else {
            CP_WAIT0();
        }
        __syncthreads();   // tap t data visible to all; prior compute done

        // ---- compute tap t: 3 combos x 4 ksteps ----
        uint32_t At = SM_A + (uint32_t)(t & 1) * 32768u;
        uint32_t Bt = SM_B + (uint32_t)t * 16384u;
        #pragma unroll
        for (int combo = 0; combo < 3; combo++) {
            uint32_t Abuf = At + ((combo == 2) ? 16384u : 0u);
            uint32_t Bbuf = Bt + ((combo == 1) ? 8192u : 0u);
            #pragma unroll
            for (int ks = 0; ks < 4; ks++) {
                uint32_t kb = (uint32_t)(ks * 32 + kq);
                uint32_t a0[4], a1[4], b0[4], b1[4];
                {
                    uint32_t row = (uint32_t)(mbase + lr);
                    LDSM_X4(a0[0], a0[1], a0[2], a0[3],
                            Abuf + row*128u + (kb ^ ((row & 7u)*16u)));
                    row += 16u;
                    LDSM_X4(a1[0], a1[1], a1[2], a1[3],
                            Abuf + row*128u + (kb ^ ((row & 7u)*16u)));
                }
                {
                    uint32_t row = (uint32_t)(nbase + lr);
                    LDSM_X4(b0[0], b0[1], b0[2], b0[3],
                            Bbuf + row*128u + (kb ^ ((row & 7u)*16u)));
                    row += 16u;
                    LDSM_X4(b1[0], b1[1], b1[2], b1[3],
                            Bbuf + row*128u + (kb ^ ((row & 7u)*16u)));
                }
                MMA_BF16(acc[0][0], a0, b0[0], b0[2]);
                MMA_BF16(acc[0][1], a0, b0[1], b0[3]);
                MMA_BF16(acc[0][2], a0, b1[0], b1[2]);
                MMA_BF16(acc[0][3], a0, b1[1], b1[3]);
                MMA_BF16(acc[1][0], a1, b0[0], b0[2]);
                MMA_BF16(acc[1][1], a1, b0[1], b0[3]);
                MMA_BF16(acc[1][2], a1, b1[0], b1[2]);
                MMA_BF16(acc[1][3], a1, b1[1], b1[3]);
            }
        }
        __syncthreads();   // all warps done reading buffer before overwrite
    }

    // ---- epilogue ----
    float bs2[4][2];
    #pragma unroll
    for (int nb = 0; nb < 4; nb++) {
        int co = chunk * 64 + nbase + nb * 8 + (lane & 3) * 2;
        bs2[nb][0] = (HASBIAS && co     < coutTot) ? bias[co]     : 0.f;
        bs2[nb][1] = (HASBIAS && co + 1 < coutTot) ? bias[co + 1] : 0.f;
    }
    #pragma unroll
    for (int mt = 0; mt < 2; mt++) {
        #pragma unroll
        for (int rh = 0; rh < 2; rh++) {
            int px = x0 + mbase + mt * 16 + (lane >> 2) + rh * 8;
            size_t P = ((size_t)b * HH + y) * WW + px;
            #pragma unroll
            for (int nb = 0; nb < 4; nb++) {
                int cl = nbase + nb * 8 + (lane & 3) * 2;   // local cout 0..63
                float v0 = acc[mt][nb][rh * 2 + 0] + bs2[nb][0];
                float v1 = acc[mt][nb][rh * 2 + 1] + bs2[nb][1];
                size_t ob = P * 64 + cl;

                if (EPI == 0) {
                    *(float2*)(outF + ob) = make_float2(v0, v1);
                } else if (EPI == 1) {
                    float2 rv = *(const float2*)(resF + ob);
                    v0 += rv.x; v1 += rv.y;
                    v0 = (v0 > 0.f) ? v0 : 0.1f * v0;
                    v1 = (v1 > 0.f) ? v1 : 0.1f * v1;
                    *(float2*)(outF + ob) = make_float2(v0, v1);
                    __nv_bfloat162 h2 = __floats2bfloat162_rn(v0, v1);
                    float2 hf = __bfloat1622float2(h2);
                    __nv_bfloat162 l2 = __floats2bfloat162_rn(v0 - hf.x, v1 - hf.y);
                    *(uint32_t*)(outH + ob) = *(uint32_t*)&h2;
                    *(uint32_t*)(outL + ob) = *(uint32_t*)&l2;
                } else if (EPI == 2) {
                    v0 = fmaxf(v0, 0.f); v1 = fmaxf(v1, 0.f);
                    __nv_bfloat162 h2 = __floats2bfloat162_rn(v0, v1);
                    float2 hf = __bfloat1622float2(h2);
                    __nv_bfloat162 l2 = __floats2bfloat162_rn(v0 - hf.x, v1 - hf.y);
                    *(uint32_t*)(outH + ob) = *(uint32_t*)&h2;
                    *(uint32_t*)(outL + ob) = *(uint32_t*)&l2;
                } else if (EPI == 3) {
                    float2 rv = *(const float2*)(resF + ob);
                    v0 = rv.x + fmaxf(v0, 0.f);
                    v1 = rv.y + fmaxf(v1, 0.f);
                    *(float2*)(outF + ob) = make_float2(v0, v1);
                } else if (EPI == 4) {
                    float2 rv = *(const float2*)(outF + ob);
                    v0 = rv.x + 0.1f * fmaxf(v0, 0.f);
                    v1 = rv.y + 0.1f * fmaxf(v1, 0.f);
                    *(float2*)(outF + ob) = make_float2(v0, v1);
                } else if (EPI == 5) {
                    float2 rv = *(const float2*)(resF + ob);
                    v0 = rv.x + 0.1f * fmaxf(v0, 0.f);
                    v1 = rv.y + 0.1f * fmaxf(v1, 0.f);
                    __nv_bfloat162 h2 = __floats2bfloat162_rn(v0, v1);
                    float2 hf = __bfloat1622float2(h2);
                    __nv_bfloat162 l2 = __floats2bfloat162_rn(v0 - hf.x, v1 - hf.y);
                    *(uint32_t*)(outH + ob) = *(uint32_t*)&h2;
                    *(uint32_t*)(outL + ob) = *(uint32_t*)&l2;
                } else if (EPI == 6) {
                    int co = chunk * 64 + cl;
                    size_t pix = ((size_t)y << 8) + px;
                    if (co < coutTot)
                        outNCHW[(((size_t)b * coutTot + co) << 16) + pix] = v0;
                    if (co + 1 < coutTot)
                        outNCHW[(((size_t)b * coutTot + co + 1) << 16) + pix] = v1;
                }
            }
        }
    }
}

// ---------------------------------------------------------------------------
// Modulated deformable conv (proven fp32 path)
// ---------------------------------------------------------------------------
__global__ void __launch_bounds__(256, 2)
dcn_kernel(const float* __restrict__ supp, const float* __restrict__ off,
           const float* __restrict__ flow, const float* __restrict__ wT,
           const float* __restrict__ bias, float* __restrict__ out)
{
    __shared__ __align__(16) float sS[64*64];
    int b  = blockIdx.z;
    int y  = blockIdx.y;
    int x0 = blockIdx.x * 64;
    int tid  = threadIdx.x;
    int cout = tid & 63;
    int pg   = tid >> 6;

    float bv = bias[cout];
    float acc[16];
    #pragma unroll
    for (int i = 0; i < 16; i++) acc[i] = bv;

    const float* fxp  = flow + ((size_t)b*2 + 0)*HWSZ + y*WW + x0;
    const float* fyp  = flow + ((size_t)b*2 + 1)*HWSZ + y*WW + x0;
    const float* offb = off  + (size_t)b*216*HWSZ + y*WW + x0;

    for (int k = 0; k < 9; k++) {
        int ki = k / 3, kj = k % 3;
        __syncthreads();
        #pragma unroll
        for (int it = 0; it < 2; it++) {
            int t  = tid + 256 * it;
            int px = t & 63;
            int g  = t >> 6;
            int cdy = g*18 + k*2;
            float rawdy = offb[(size_t)cdy          *HWSZ + px];
            float rawdx = offb[(size_t)(cdy + 1)    *HWSZ + px];
            float rawm  = offb[(size_t)(144 + g*9+k)*HWSZ + px];
            float fx = fxp[px], fy = fyp[px];
            float ady = 25.f * tanhf(rawdy) + ((cdy     < 72) ? fx : fy);
            float adx = 25.f * tanhf(rawdx) + ((cdy + 1 < 72) ? fx : fy);
            float m   = 1.f / (1.f + expf(-rawm));
            float sy = (float)y         + (float)(ki - 1) + ady;
            float sx = (float)(x0 + px) + (float)(kj - 1) + adx;
            float y0f = floorf(sy), x0f = floorf(sx);
            int iy0 = (int)y0f, ix0 = (int)x0f;
            int iy1 = iy0 + 1,  ix1 = ix0 + 1;
            float wy = sy - y0f, wx = sx - x0f;
            bool vy0 = ((unsigned)iy0 < HH), vy1 = ((unsigned)iy1 < HH);
            bool vx0 = ((unsigned)ix0 < WW), vx1 = ((unsigned)ix1 < WW);
            float w00 = (1.f - wy)*(1.f - wx) * ((vy0 && vx0) ? 1.f : 0.f) * m;
            float w01 = (1.f - wy)*wx         * ((vy0 && vx1) ? 1.f : 0.f) * m;
            float w10 = wy*(1.f - wx)         * ((vy1 && vx0) ? 1.f : 0.f) * m;
            float w11 = wy*wx                 * ((vy1 && vx1) ? 1.f : 0.f) * m;
            int cy0 = min(max(iy0, 0), HH-1), cy1 = min(max(iy1, 0), HH-1);
            int cx0 = min(max(ix0, 0), WW-1), cx1 = min(max(ix1, 0), WW-1);
            int i00 = cy0*WW + cx0, i01 = cy0*WW + cx1;
            int i10 = cy1*WW + cx0, i11 = cy1*WW + cx1;
            const float* sb = supp + ((size_t)b*64 + g*8)*HWSZ;
            #pragma unroll
            for (int c = 0; c < 8; c++) {
                const float* ch = sb + (size_t)c*HWSZ;
                float v = w00*ch[i00] + w01*ch[i01] + w10*ch[i10] + w11*ch[i11];
                sS[(g*8 + c)*64 + px] = v;
            }
        }
        __syncthreads();

        const float* wk = wT + k*64*64 + cout;
        #pragma unroll 4
        for (int c = 0; c < 64; c++) {
            float wv = wk[c*64];
            const float4* sr = (const float4*)(sS + c*64 + pg*16);
            #pragma unroll
            for (int q = 0; q < 4; q++) {
                float4 v = sr[q];
                acc[q*4+0] = fmaf(wv, v.x, acc[q*4+0]);
                acc[q*4+1] = fmaf(wv, v.y, acc[q*4+1]);
                acc[q*4+2] = fmaf(wv, v.z, acc[q*4+2]);
                acc[q*4+3] = fmaf(wv, v.w, acc[q*4+3]);
            }
        }
    }

    size_t ob = (((size_t)b*64 + cout)*HH + y)*WW + x0 + pg*16;
    #pragma unroll
    for (int px = 0; px < 16; px++) out[ob + px] = acc[px];
}

// ---------------------------------------------------------------------------
// Launch
// ---------------------------------------------------------------------------
extern "C" void kernel_launch(void* const* d_in, const int* in_sizes, int n_in,
                              void* d_out, int out_size)
{
    const float* ref   = (const float*)d_in[0];
    const float* supp  = (const float*)d_in[1];
    const float* flow  = (const float*)d_in[2];
    const float* fc_w  = (const float*)d_in[3];
    const float* fc_b  = (const float*)d_in[4];
    const float* cw[6], *cb[6];
    for (int i = 0; i < 6; i++) {
        cw[i] = (const float*)d_in[5 + 2*i];
        cb[i] = (const float*)d_in[6 + 2*i];
    }
    const float* off_w = (const float*)d_in[17];
    const float* off_b = (const float*)d_in[18];
    const float* dcn_w = (const float*)d_in[19];
    const float* dcn_b = (const float*)d_in[20];
    float* out = (float*)d_out;

    __nv_bfloat16 *wH, *wL, *rH, *rL, *t0H, *t0L, *tmpH, *tmpL, *ftH, *ftL, *Bg;
    float *partF, *f0F, *ffF, *offbuf, *wTd;
    cudaGetSymbolAddress((void**)&wH,  g_wH);   cudaGetSymbolAddress((void**)&wL,  g_wL);
    cudaGetSymbolAddress((void**)&rH,  g_rH);   cudaGetSymbolAddress((void**)&rL,  g_rL);
    cudaGetSymbolAddress((void**)&t0H, g_t0H);  cudaGetSymbolAddress((void**)&t0L, g_t0L);
    cudaGetSymbolAddress((void**)&tmpH,g_tmpH); cudaGetSymbolAddress((void**)&tmpL,g_tmpL);
    cudaGetSymbolAddress((void**)&ftH, g_ftH);  cudaGetSymbolAddress((void**)&ftL, g_ftL);
    cudaGetSymbolAddress((void**)&Bg,  g_B);
    cudaGetSymbolAddress((void**)&partF, g_partF);
    cudaGetSymbolAddress((void**)&f0F,   g_f0F);
    cudaGetSymbolAddress((void**)&ffF,   g_ffF);
    cudaGetSymbolAddress((void**)&offbuf,g_off);
    cudaGetSymbolAddress((void**)&wTd,   g_wT_dcn);

    const int SMB = 1024 + 147456 + 65536;   // align pad + B layer + A double buffer
    cudaFuncSetAttribute((const void*)conv_mma_kernel<1,0,1>, cudaFuncAttributeMaxDynamicSharedMemorySize, SMB);
    cudaFuncSetAttribute((const void*)conv_mma_kernel<1,1,0>, cudaFuncAttributeMaxDynamicSharedMemorySize, SMB);
    cudaFuncSetAttribute((const void*)conv_mma_kernel<1,2,1>, cudaFuncAttributeMaxDynamicSharedMemorySize, SMB);
    cudaFuncSetAttribute((const void*)conv_mma_kernel<1,3,1>, cudaFuncAttributeMaxDynamicSharedMemorySize, SMB);
    cudaFuncSetAttribute((const void*)conv_mma_kernel<2,2,1>, cudaFuncAttributeMaxDynamicSharedMemorySize, SMB);
    cudaFuncSetAttribute((const void*)conv_mma_kernel<2,4,1>, cudaFuncAttributeMaxDynamicSharedMemorySize, SMB);
    cudaFuncSetAttribute((const void*)conv_mma_kernel<4,5,1>, cudaFuncAttributeMaxDynamicSharedMemorySize, SMB);
    cudaFuncSetAttribute((const void*)conv_mma_kernel<1,6,1>, cudaFuncAttributeMaxDynamicSharedMemorySize, SMB);

    // Weight prep
    prep_B_kernel<<<144, 256>>>(fc_w, Bg + 0*BSET, 128, 0,  64, 0);
    prep_B_kernel<<<144, 256>>>(fc_w, Bg + 1*BSET, 128, 64, 64, 0);
    for (int i = 0; i < 6; i++)
        prep_B_kernel<<<144, 256>>>(cw[i], Bg + (2+i)*BSET, 64, 0, 64, 0);
    for (int ch = 0; ch < 4; ch++)
        prep_B_kernel<<<144, 256>>>(off_w, Bg + (8+ch)*BSET, 64, 0, 216, ch*64);
    transpose_dcn_kernel<<<144, 256>>>(dcn_w, wTd);

    // Input format conversion
    warp_nhwc_kernel<<<dim3(HWSZ/256, BB), 256>>>(supp, flow, wH, wL);
    to_nhwc_kernel<<<dim3(HWSZ/256, BB), 256>>>(ref, rH, rL);

    dim3 cg(2, 256, 4);
    // fc pass1: warped half (with bias) -> partial fp32
    conv_mma_kernel<1,0,1><<<cg, 256, SMB>>>(wH, wL, Bg + 0*BSET, fc_b, 1, 64,
                                             partF, nullptr, nullptr, nullptr, nullptr);
    // fc pass2: ref half + partial, lrelu -> feat0 (f32 + hi/lo)
    conv_mma_kernel<1,1,0><<<cg, 256, SMB>>>(rH, rL, Bg + 1*BSET, nullptr, 1, 64,
                                             f0F, t0H, t0L, partF, nullptr);
    // c1: relu -> tmp
    conv_mma_kernel<1,2,1><<<cg, 256, SMB>>>(t0H, t0L, Bg + 2*BSET, cb[0], 1, 64,
                                             nullptr, tmpH, tmpL, nullptr, nullptr);
    // c2: ff = feat0 + relu(v)
    conv_mma_kernel<1,3,1><<<cg, 256, SMB>>>(tmpH, tmpL, Bg + 3*BSET, cb[1], 1, 64,
                                             ffF, nullptr, nullptr, f0F, nullptr);
    // c3 (dil2): relu -> tmp
    conv_mma_kernel<2,2,1><<<cg, 256, SMB>>>(t0H, t0L, Bg + 4*BSET, cb[2], 1, 64,
                                             nullptr, tmpH, tmpL, nullptr, nullptr);
    // c4 (dil2): ff += 0.1*relu(v)
    conv_mma_kernel<2,4,1><<<cg, 256, SMB>>>(tmpH, tmpL, Bg + 5*BSET, cb[3], 1, 64,
                                             ffF, nullptr, nullptr, nullptr, nullptr);
    // c5 (dil2): relu -> tmp
    conv_mma_kernel<2,2,1><<<cg, 256, SMB>>>(t0H, t0L, Bg + 6*BSET, cb[4], 1, 64,
                                             nullptr, tmpH, tmpL, nullptr, nullptr);
    // c6 (dil4): feat = ff + 0.1*relu(v) -> hi/lo
    conv_mma_kernel<4,5,1><<<cg, 256, SMB>>>(tmpH, tmpL, Bg + 7*BSET, cb[5], 1, 64,
                                             nullptr, ftH, ftL, ffF, nullptr);
    // offset conv: 216 couts, 4 chunks, NCHW out
    dim3 og(2, 256, 16);
    conv_mma_kernel<1,6,1><<<og, 256, SMB>>>(ftH, ftL, Bg + 8*BSET, off_b, 4, 216,
                                             nullptr, nullptr, nullptr, nullptr, offbuf);
    // deformable conv
    dcn_kernel<<<dim3(4, 256, 4), 256>>>(supp, offbuf, flow, wTd, dcn_b, out);
}

// round 7
// speedup vs baseline: 2.4239x; 1.2494x over previous
#include <cuda_runtime.h>
#include <cuda_bf16.h>
#include <math.h>
#include <stdint.h>

#define BB 4
#define HH 256
#define WW 256
#define HWSZ 65536
#define NPX (BB*HWSZ)

// ---------------------------------------------------------------------------
// PTX helpers (plain sm_103-safe: ldmatrix + mma.sync + cp.async)
// ---------------------------------------------------------------------------
__device__ __forceinline__ uint32_t smem_u32(const void* p) {
    uint32_t a;
    asm("{ .reg .u64 t; cvta.to.shared.u64 t, %1; cvt.u32.u64 %0, t; }" : "=r"(a) : "l"(p));
    return a;
}

#define LDSM_X4(r0, r1, r2, r3, addr) \
    asm volatile("ldmatrix.sync.aligned.m8n8.x4.shared.b16 {%0,%1,%2,%3}, [%4];" \
        : "=r"(r0), "=r"(r1), "=r"(r2), "=r"(r3) : "r"(addr))

#define MMA_BF16(d, a, b0v, b1v) \
    asm volatile("mma.sync.aligned.m16n8k16.row.col.f32.bf16.bf16.f32 " \
        "{%0,%1,%2,%3},{%4,%5,%6,%7},{%8,%9},{%0,%1,%2,%3};" \
        : "+f"((d)[0]), "+f"((d)[1]), "+f"((d)[2]), "+f"((d)[3]) \
        : "r"((a)[0]), "r"((a)[1]), "r"((a)[2]), "r"((a)[3]), "r"(b0v), "r"(b1v))

#define CP_ASYNC16(dst, src, sz) \
    asm volatile("cp.async.cg.shared.global [%0], [%1], 16, %2;" \
        :: "r"(dst), "l"(src), "r"(sz) : "memory")
#define CP_COMMIT() asm volatile("cp.async.commit_group;" ::: "memory")
#define CP_WAIT1() asm volatile("cp.async.wait_group 1;" ::: "memory")
#define CP_WAIT0() asm volatile("cp.async.wait_group 0;" ::: "memory")

// ---------------------------------------------------------------------------
// Device global scratch
// ---------------------------------------------------------------------------
#define FEAT_ELEMS ((size_t)NPX*64)
__device__ __nv_bfloat16 g_wH[FEAT_ELEMS], g_wL[FEAT_ELEMS];     // warped supp
__device__ __nv_bfloat16 g_rH[FEAT_ELEMS], g_rL[FEAT_ELEMS];     // ref
__device__ __nv_bfloat16 g_t0H[FEAT_ELEMS], g_t0L[FEAT_ELEMS];   // feat0
__device__ __nv_bfloat16 g_tmpH[FEAT_ELEMS], g_tmpL[FEAT_ELEMS];
__device__ __nv_bfloat16 g_ftH[FEAT_ELEMS], g_ftL[FEAT_ELEMS];   // final feat
__device__ float g_f0F[FEAT_ELEMS];                               // feat0 fp32
__device__ float g_ffF[FEAT_ELEMS];                               // feat fp32 accum
__device__ float g_off[(size_t)BB*216*HWSZ];                      // NCHW
// 13 B-sets (fc0, fc1, c1..c6, off chunks 0..3, dcn); each 9 taps x 16KB
#define BSET 73728
__device__ __nv_bfloat16 g_B[13*BSET];

// ---------------------------------------------------------------------------
// B prep: OIHW fp32 -> per-tap SW128-swizzled bf16 hi/lo [cout row][cin col]
// ---------------------------------------------------------------------------
__global__ void prep_B_kernel(const float* __restrict__ w, __nv_bfloat16* __restrict__ out,
                              int cinTot, int cin0, int coutTot, int cout0)
{
    int idx = blockIdx.x * 256 + threadIdx.x;   // 9*64*64 = 36864
    if (idx >= 36864) return;
    int c = idx & 63;
    int r = (idx >> 6) & 63;
    int t = idx >> 12;
    float v = 0.f;
    int co = cout0 + r;
    if (co < coutTot) v = w[((size_t)co * cinTot + cin0 + c) * 9 + t];
    __nv_bfloat16 h = __float2bfloat16(v);
    __nv_bfloat16 l = __float2bfloat16(v - __bfloat162float(h));
    uint32_t off = (uint32_t)r * 128u + (uint32_t)c * 2u;
    uint32_t so = off ^ ((off >> 3) & 0x70u);
    char* ob = (char*)out + (size_t)t * 16384;
    *(__nv_bfloat16*)(ob + so) = h;
    *(__nv_bfloat16*)(ob + 8192 + so) = l;
}

// ---------------------------------------------------------------------------
// flow_warp -> NHWC bf16 hi/lo
// ---------------------------------------------------------------------------
__global__ void warp_nhwc_kernel(const float* __restrict__ supp, const float* __restrict__ flow,
                                 __nv_bfloat16* __restrict__ oH, __nv_bfloat16* __restrict__ oL)
{
    int p = blockIdx.x * 256 + threadIdx.x;
    int b = blockIdx.y;
    int y = p >> 8, x = p & 255;
    float fx = flow[((size_t)b*2    )*HWSZ + p];
    float fy = flow[((size_t)b*2 + 1)*HWSZ + p];
    float sy = (float)y + fy, sx = (float)x + fx;
    float y0f = floorf(sy), x0f = floorf(sx);
    int iy0 = (int)y0f, ix0 = (int)x0f, iy1 = iy0+1, ix1 = ix0+1;
    float wy = sy - y0f, wx = sx - x0f;
    bool vy0 = ((unsigned)iy0 < HH), vy1 = ((unsigned)iy1 < HH);
    bool vx0 = ((unsigned)ix0 < WW), vx1 = ((unsigned)ix1 < WW);
    float w00 = (1.f-wy)*(1.f-wx) * ((vy0&&vx0)?1.f:0.f);
    float w01 = (1.f-wy)*wx       * ((vy0&&vx1)?1.f:0.f);
    float w10 = wy*(1.f-wx)       * ((vy1&&vx0)?1.f:0.f);
    float w11 = wy*wx             * ((vy1&&vx1)?1.f:0.f);
    int cy0 = min(max(iy0,0),HH-1), cy1 = min(max(iy1,0),HH-1);
    int cx0 = min(max(ix0,0),WW-1), cx1 = min(max(ix1,0),WW-1);
    int i00 = cy0*WW+cx0, i01 = cy0*WW+cx1, i10 = cy1*WW+cx0, i11 = cy1*WW+cx1;
    const float* sb = supp + (size_t)b*64*HWSZ;
    __nv_bfloat16* ohp = oH + ((size_t)b*HWSZ + p)*64;
    __nv_bfloat16* olp = oL + ((size_t)b*HWSZ + p)*64;
    for (int g = 0; g < 8; g++) {
        uint4 uh, ul;
        uint32_t* ph = (uint32_t*)&uh;
        uint32_t* pl = (uint32_t*)&ul;
        #pragma unroll
        for (int q = 0; q < 4; q++) {
            const float* c0 = sb + (size_t)(g*8 + q*2)*HWSZ;
            const float* c1 = c0 + HWSZ;
            float v0 = w00*c0[i00] + w01*c0[i01] + w10*c0[i10] + w11*c0[i11];
            float v1 = w00*c1[i00] + w01*c1[i01] + w10*c1[i10] + w11*c1[i11];
            __nv_bfloat162 h2 = __floats2bfloat162_rn(v0, v1);
            float2 hf = __bfloat1622float2(h2);
            __nv_bfloat162 l2 = __floats2bfloat162_rn(v0 - hf.x, v1 - hf.y);
            ph[q] = *(uint32_t*)&h2;
            pl[q] = *(uint32_t*)&l2;
        }
        ((uint4*)ohp)[g] = uh;
        ((uint4*)olp)[g] = ul;
    }
}

// NCHW fp32 -> NHWC bf16 hi/lo
__global__ void to_nhwc_kernel(const float* __restrict__ src,
                               __nv_bfloat16* __restrict__ oH, __nv_bfloat16* __restrict__ oL)
{
    int p = blockIdx.x * 256 + threadIdx.x;
    int b = blockIdx.y;
    const float* sp = src + (size_t)b*64*HWSZ + p;
    __nv_bfloat16* ohp = oH + ((size_t)b*HWSZ + p)*64;
    __nv_bfloat16* olp = oL + ((size_t)b*HWSZ + p)*64;
    for (int g = 0; g < 8; g++) {
        uint4 uh, ul;
        uint32_t* ph = (uint32_t*)&uh;
        uint32_t* pl = (uint32_t*)&ul;
        #pragma unroll
        for (int q = 0; q < 4; q++) {
            float v0 = sp[(size_t)(g*8 + q*2    )*HWSZ];
            float v1 = sp[(size_t)(g*8 + q*2 + 1)*HWSZ];
            __nv_bfloat162 h2 = __floats2bfloat162_rn(v0, v1);
            float2 hf = __bfloat1622float2(h2);
            __nv_bfloat162 l2 = __floats2bfloat162_rn(v0 - hf.x, v1 - hf.y);
            ph[q] = *(uint32_t*)&h2;
            pl[q] = *(uint32_t*)&l2;
        }
        ((uint4*)ohp)[g] = uh;
        ((uint4*)olp)[g] = ul;
    }
}

// ---------------------------------------------------------------------------
// mma.sync conv, per-tap streamed A+B (double-buffered cp.async), 2 CTAs/SM.
// D[128px][64cout] per CTA, NT taps x (AhBh + AhBl + AlBh).
// NT=18 fuses the two fc halves (taps 9..17 read inH2/inL2, B contiguous).
// EPI: 1 +bias lrelu -> f32+hi/lo; 2 relu hi/lo; 3 relu out=res+v f32;
//      4 relu outF+=0.1v; 5 relu res+0.1v hi/lo; 6 NCHW f32 (coutTot guard)
// ---------------------------------------------------------------------------
template<int DIL, int EPI, int HASBIAS, int NT>
__global__ void __launch_bounds__(256, 2)
conv_mma_kernel(const __nv_bfloat16* __restrict__ inH,
                const __nv_bfloat16* __restrict__ inL,
                const __nv_bfloat16* __restrict__ inH2,
                const __nv_bfloat16* __restrict__ inL2,
                const __nv_bfloat16* __restrict__ Bimg,
                const float* __restrict__ bias,
                int nchunk, int coutTot,
                float* __restrict__ outF,
                __nv_bfloat16* __restrict__ outH,
                __nv_bfloat16* __restrict__ outL,
                const float* __restrict__ resF,
                float* __restrict__ outNCHW)
{
    extern __shared__ char smem[];
    uint32_t base = (smem_u32(smem) + 1023u) & ~1023u;
    // buffer i at base + i*49152: A hi 16K | A lo 16K | B 16K

    int tid = threadIdx.x;
    int lane = tid & 31, w = tid >> 5;
    int z = blockIdx.z;
    int b = z / nchunk, chunk = z - b * nchunk;
    int y = blockIdx.y, x0 = blockIdx.x * 128;

    int spx = tid >> 1, shf = tid & 1;
    uint32_t sso[4];
    #pragma unroll
    for (int j = 0; j < 4; j++)
        sso[j] = (uint32_t)spx * 128u +
                 (((uint32_t)shf * 64u + (uint32_t)j * 16u) ^ (((uint32_t)spx & 7u) * 16u));

    const char* Bbase = (const char*)Bimg + (size_t)chunk * 147456;

    // staging of tap tt into buffer buf
    auto stage = [&](int tt, int buf) {
        int t = (NT == 18 && tt >= 9) ? tt - 9 : tt;
        const __nv_bfloat16* iH = (NT == 18 && tt >= 9) ? inH2 : inH;
        const __nv_bfloat16* iL = (NT == 18 && tt >= 9) ? inL2 : inL;
        int ki = t / 3, kj = t - ki * 3;
        int gy = y + (ki - 1) * DIL;
        int gx = x0 + spx + (kj - 1) * DIL;
        bool ok = ((unsigned)gy < HH) && ((unsigned)gx < WW);
        size_t gidx = ok ? ((((size_t)b * HH + gy) * WW + gx) * 64 + shf * 32) : 0;
        int sz = ok ? 16 : 0;
        const char* pH = (const char*)(iH + gidx);
        const char* pL = (const char*)(iL + gidx);
        uint32_t aB = base + (uint32_t)buf * 49152u;
        #pragma unroll
        for (int j = 0; j < 4; j++) {
            CP_ASYNC16(aB + sso[j], pH + j * 16, sz);
            CP_ASYNC16(aB + 16384u + sso[j], pL + j * 16, sz);
        }
        const char* bsrc = Bbase + (size_t)tt * 16384;
        uint32_t bB = aB + 32768u;
        #pragma unroll
        for (int kk = 0; kk < 4; kk++)
            CP_ASYNC16(bB + (uint32_t)tid * 16u + (uint32_t)kk * 4096u,
                       bsrc + tid * 16 + kk * 4096, 16);
    };

    stage(0, 0);
    CP_COMMIT();

    int mbase = (w & 3) * 32;
    int nbase = (w >> 2) * 32;

    float acc[2][4][4];
    #pragma unroll
    for (int i = 0; i < 2; i++)
        #pragma unroll
        for (int j = 0; j < 4; j++)
            #pragma unroll
            for (int q = 0; q < 4; q++) acc[i][j][q] = 0.f;

    int lr = (lane & 7) + ((lane >> 3) & 1) * 8;
    int kq = (lane >> 4) * 16;

    #pragma unroll 1
    for (int tt = 0; tt < NT; tt++) {
        if (tt + 1 < NT) {
            stage(tt + 1, (tt + 1) & 1);
            CP_COMMIT();
            CP_WAIT1();
        } else {
            CP_WAIT0();
        }
        __syncthreads();

        uint32_t At = base + (uint32_t)(tt & 1) * 49152u;
        uint32_t Bt = At + 32768u;
        #pragma unroll
        for (int combo = 0; combo < 3; combo++) {
            uint32_t Abuf = At + ((combo == 2) ? 16384u : 0u);
            uint32_t Bbuf = Bt + ((combo == 1) ? 8192u : 0u);
            #pragma unroll
            for (int ks = 0; ks < 4; ks++) {
                uint32_t kb = (uint32_t)(ks * 32 + kq);
                uint32_t a0[4], a1[4], b0[4], b1[4];
                {
                    uint32_t row = (uint32_t)(mbase + lr);
                    LDSM_X4(a0[0], a0[1], a0[2], a0[3],
                            Abuf + row*128u + (kb ^ ((row & 7u)*16u)));
                    row += 16u;
                    LDSM_X4(a1[0], a1[1], a1[2], a1[3],
                            Abuf + row*128u + (kb ^ ((row & 7u)*16u)));
                }
                {
                    uint32_t row = (uint32_t)(nbase + lr);
                    LDSM_X4(b0[0], b0[1], b0[2], b0[3],
                            Bbuf + row*128u + (kb ^ ((row & 7u)*16u)));
                    row += 16u;
                    LDSM_X4(b1[0], b1[1], b1[2], b1[3],
                            Bbuf + row*128u + (kb ^ ((row & 7u)*16u)));
                }
                MMA_BF16(acc[0][0], a0, b0[0], b0[2]);
                MMA_BF16(acc[0][1], a0, b0[1], b0[3]);
                MMA_BF16(acc[0][2], a0, b1[0], b1[2]);
                MMA_BF16(acc[0][3], a0, b1[1], b1[3]);
                MMA_BF16(acc[1][0], a1, b0[0], b0[2]);
                MMA_BF16(acc[1][1], a1, b0[1], b0[3]);
                MMA_BF16(acc[1][2], a1, b1[0], b1[2]);
                MMA_BF16(acc[1][3], a1, b1[1], b1[3]);
            }
        }
        __syncthreads();
    }

    // ---- epilogue ----
    float bs2[4][2];
    #pragma unroll
    for (int nb = 0; nb < 4; nb++) {
        int co = chunk * 64 + nbase + nb * 8 + (lane & 3) * 2;
        bs2[nb][0] = (HASBIAS && co     < coutTot) ? bias[co]     : 0.f;
        bs2[nb][1] = (HASBIAS && co + 1 < coutTot) ? bias[co + 1] : 0.f;
    }
    #pragma unroll
    for (int mt = 0; mt < 2; mt++) {
        #pragma unroll
        for (int rh = 0; rh < 2; rh++) {
            int px = x0 + mbase + mt * 16 + (lane >> 2) + rh * 8;
            size_t P = ((size_t)b * HH + y) * WW + px;
            #pragma unroll
            for (int nb = 0; nb < 4; nb++) {
                int cl = nbase + nb * 8 + (lane & 3) * 2;
                float v0 = acc[mt][nb][rh * 2 + 0] + bs2[nb][0];
                float v1 = acc[mt][nb][rh * 2 + 1] + bs2[nb][1];
                size_t ob = P * 64 + cl;

                if (EPI == 1) {
                    v0 = (v0 > 0.f) ? v0 : 0.1f * v0;
                    v1 = (v1 > 0.f) ? v1 : 0.1f * v1;
                    *(float2*)(outF + ob) = make_float2(v0, v1);
                    __nv_bfloat162 h2 = __floats2bfloat162_rn(v0, v1);
                    float2 hf = __bfloat1622float2(h2);
                    __nv_bfloat162 l2 = __floats2bfloat162_rn(v0 - hf.x, v1 - hf.y);
                    *(uint32_t*)(outH + ob) = *(uint32_t*)&h2;
                    *(uint32_t*)(outL + ob) = *(uint32_t*)&l2;
                } else if (EPI == 2) {
                    v0 = fmaxf(v0, 0.f); v1 = fmaxf(v1, 0.f);
                    __nv_bfloat162 h2 = __floats2bfloat162_rn(v0, v1);
                    float2 hf = __bfloat1622float2(h2);
                    __nv_bfloat162 l2 = __floats2bfloat162_rn(v0 - hf.x, v1 - hf.y);
                    *(uint32_t*)(outH + ob) = *(uint32_t*)&h2;
                    *(uint32_t*)(outL + ob) = *(uint32_t*)&l2;
                } else if (EPI == 3) {
                    float2 rv = *(const float2*)(resF + ob);
                    v0 = rv.x + fmaxf(v0, 0.f);
                    v1 = rv.y + fmaxf(v1, 0.f);
                    *(float2*)(outF + ob) = make_float2(v0, v1);
                } else if (EPI == 4) {
                    float2 rv = *(const float2*)(outF + ob);
                    v0 = rv.x + 0.1f * fmaxf(v0, 0.f);
                    v1 = rv.y + 0.1f * fmaxf(v1, 0.f);
                    *(float2*)(outF + ob) = make_float2(v0, v1);
                } else if (EPI == 5) {
                    float2 rv = *(const float2*)(resF + ob);
                    v0 = rv.x + 0.1f * fmaxf(v0, 0.f);
                    v1 = rv.y + 0.1f * fmaxf(v1, 0.f);
                    __nv_bfloat162 h2 = __floats2bfloat162_rn(v0, v1);
                    float2 hf = __bfloat1622float2(h2);
                    __nv_bfloat162 l2 = __floats2bfloat162_rn(v0 - hf.x, v1 - hf.y);
                    *(uint32_t*)(outH + ob) = *(uint32_t*)&h2;
                    *(uint32_t*)(outL + ob) = *(uint32_t*)&l2;
                } else if (EPI == 6) {
                    int co = chunk * 64 + cl;
                    size_t pix = ((size_t)y << 8) + px;
                    if (co < coutTot)
                        outNCHW[(((size_t)b * coutTot + co) << 16) + pix] = v0;
                    if (co + 1 < coutTot)
                        outNCHW[(((size_t)b * coutTot + co + 1) << 16) + pix] = v1;
                }
            }
        }
    }
}

// ---------------------------------------------------------------------------
// Modulated deformable conv, tensorized: per tap sample 128px x 64ch into
// bf16 hi/lo swizzled sS, stream dcn B per tap, 3-combo mma core.
// ---------------------------------------------------------------------------
__global__ void __launch_bounds__(256, 2)
dcn_mma_kernel(const float* __restrict__ supp, const float* __restrict__ off,
               const float* __restrict__ flow, const __nv_bfloat16* __restrict__ Bimg,
               const float* __restrict__ bias, float* __restrict__ out)
{
    extern __shared__ char smem[];
    uint32_t base = (smem_u32(smem) + 1023u) & ~1023u;
    const uint32_t SM_S = base;            // 32KB: hi 16K | lo 16K
    const uint32_t SM_Bd = base + 32768u;  // 2 x 16KB B double buffer

    int tid = threadIdx.x;
    int lane = tid & 31, w = tid >> 5;
    int b = blockIdx.z, y = blockIdx.y, x0 = blockIdx.x * 128;

    // prefetch B tap 0
    #pragma unroll
    for (int kk = 0; kk < 4; kk++)
        CP_ASYNC16(SM_Bd + (uint32_t)tid * 16u + (uint32_t)kk * 4096u,
                   (const char*)Bimg + tid * 16 + kk * 4096, 16);
    CP_COMMIT();

    int mbase = (w & 3) * 32;
    int nbase = (w >> 2) * 32;
    float acc[2][4][4];
    #pragma unroll
    for (int i = 0; i < 2; i++)
        #pragma unroll
        for (int j = 0; j < 4; j++)
            #pragma unroll
            for (int q = 0; q < 4; q++) acc[i][j][q] = 0.f;

    int lr = (lane & 7) + ((lane >> 3) & 1) * 8;
    int kq = (lane >> 4) * 16;

    const float* fxp  = flow + ((size_t)b*2 + 0)*HWSZ + y*WW + x0;
    const float* fyp  = flow + ((size_t)b*2 + 1)*HWSZ + y*WW + x0;
    const float* offb = off  + (size_t)b*216*HWSZ + y*WW + x0;

    #pragma unroll 1
    for (int k = 0; k < 9; k++) {
        if (k < 8) {   // prefetch next tap's B
            const char* bsrc = (const char*)Bimg + (size_t)(k + 1) * 16384;
            uint32_t bB = SM_Bd + (uint32_t)((k + 1) & 1) * 16384u;
            #pragma unroll
            for (int kk = 0; kk < 4; kk++)
                CP_ASYNC16(bB + (uint32_t)tid * 16u + (uint32_t)kk * 4096u,
                           bsrc + tid * 16 + kk * 4096, 16);
            CP_COMMIT();
        }

        // ---- sample tap k into sS (hi/lo) ----
        int ki = k / 3, kj = k - ki * 3;
        #pragma unroll 1
        for (int it = 0; it < 4; it++) {
            int task = tid + it * 256;
            int px = task & 127;
            int g  = task >> 7;
            int cdy = g*18 + k*2;
            float rawdy = offb[(size_t)cdy          *HWSZ + px];
            float rawdx = offb[(size_t)(cdy + 1)    *HWSZ + px];
            float rawm  = offb[(size_t)(144 + g*9+k)*HWSZ + px];
            float fx = fxp[px], fy = fyp[px];
            float ady = 25.f * tanhf(rawdy) + ((cdy     < 72) ? fx : fy);
            float adx = 25.f * tanhf(rawdx) + ((cdy + 1 < 72) ? fx : fy);
            float m   = 1.f / (1.f + expf(-rawm));
            float sy = (float)y         + (float)(ki - 1) + ady;
            float sx = (float)(x0 + px) + (float)(kj - 1) + adx;
            float y0f = floorf(sy), x0f = floorf(sx);
            int iy0 = (int)y0f, ix0 = (int)x0f;
            int iy1 = iy0 + 1,  ix1 = ix0 + 1;
            float wy = sy - y0f, wx = sx - x0f;
            bool vy0 = ((unsigned)iy0 < HH), vy1 = ((unsigned)iy1 < HH);
            bool vx0 = ((unsigned)ix0 < WW), vx1 = ((unsigned)ix1 < WW);
            float w00 = (1.f - wy)*(1.f - wx) * ((vy0 && vx0) ? 1.f : 0.f) * m;
            float w01 = (1.f - wy)*wx         * ((vy0 && vx1) ? 1.f : 0.f) * m;
            float w10 = wy*(1.f - wx)         * ((vy1 && vx0) ? 1.f : 0.f) * m;
            float w11 = wy*wx                 * ((vy1 && vx1) ? 1.f : 0.f) * m;
            int cy0 = min(max(iy0, 0), HH-1), cy1 = min(max(iy1, 0), HH-1);
            int cx0 = min(max(ix0, 0), WW-1), cx1 = min(max(ix1, 0), WW-1);
            int i00 = cy0*WW + cx0, i01 = cy0*WW + cx1;
            int i10 = cy1*WW + cx0, i11 = cy1*WW + cx1;
            const float* sb = supp + ((size_t)b*64 + g*8)*HWSZ;
            uint32_t hpk[4], lpk[4];
            #pragma unroll
            for (int q = 0; q < 4; q++) {
                const float* c0 = sb + (size_t)(q*2    )*HWSZ;
                const float* c1 = sb + (size_t)(q*2 + 1)*HWSZ;
                float v0 = w00*c0[i00] + w01*c0[i01] + w10*c0[i10] + w11*c0[i11];
                float v1 = w00*c1[i00] + w01*c1[i01] + w10*c1[i10] + w11*c1[i11];
                __nv_bfloat162 h2 = __floats2bfloat162_rn(v0, v1);
                float2 hf = __bfloat1622float2(h2);
                __nv_bfloat162 l2 = __floats2bfloat162_rn(v0 - hf.x, v1 - hf.y);
                hpk[q] = *(uint32_t*)&h2;
                lpk[q] = *(uint32_t*)&l2;
            }
            uint32_t so = (uint32_t)px * 128u +
                          (((uint32_t)g * 16u) ^ (((uint32_t)px & 7u) * 16u));
            asm volatile("st.shared.v4.b32 [%0], {%1,%2,%3,%4};"
                :: "r"(SM_S + so), "r"(hpk[0]), "r"(hpk[1]), "r"(hpk[2]), "r"(hpk[3]) : "memory");
            asm volatile("st.shared.v4.b32 [%0], {%1,%2,%3,%4};"
                :: "r"(SM_S + 16384u + so), "r"(lpk[0]), "r"(lpk[1]), "r"(lpk[2]), "r"(lpk[3]) : "memory");
        }

        if (k < 8) CP_WAIT1(); else CP_WAIT0();
        __syncthreads();

        // ---- mma tap k ----
        uint32_t Bt = SM_Bd + (uint32_t)(k & 1) * 16384u;
        #pragma unroll
        for (int combo = 0; combo < 3; combo++) {
            uint32_t Abuf = SM_S + ((combo == 2) ? 16384u : 0u);
            uint32_t Bbuf = Bt + ((combo == 1) ? 8192u : 0u);
            #pragma unroll
            for (int ks = 0; ks < 4; ks++) {
                uint32_t kb = (uint32_t)(ks * 32 + kq);
                uint32_t a0[4], a1[4], b0[4], b1[4];
                {
                    uint32_t row = (uint32_t)(mbase + lr);
                    LDSM_X4(a0[0], a0[1], a0[2], a0[3],
                            Abuf + row*128u + (kb ^ ((row & 7u)*16u)));
                    row += 16u;
                    LDSM_X4(a1[0], a1[1], a1[2], a1[3],
                            Abuf + row*128u + (kb ^ ((row & 7u)*16u)));
                }
                {
                    uint32_t row = (uint32_t)(nbase + lr);
                    LDSM_X4(b0[0], b0[1], b0[2], b0[3],
                            Bbuf + row*128u + (kb ^ ((row & 7u)*16u)));
                    row += 16u;
                    LDSM_X4(b1[0], b1[1], b1[2], b1[3],
                            Bbuf + row*128u + (kb ^ ((row & 7u)*16u)));
                }
                MMA_BF16(acc[0][0], a0, b0[0], b0[2]);
                MMA_BF16(acc[0][1], a0, b0[1], b0[3]);
                MMA_BF16(acc[0][2], a0, b1[0], b1[2]);
                MMA_BF16(acc[0][3], a0, b1[1], b1[3]);
                MMA_BF16(acc[1][0], a1, b0[0], b0[2]);
                MMA_BF16(acc[1][1], a1, b0[1], b0[3]);
                MMA_BF16(acc[1][2], a1, b1[0], b1[2]);
                MMA_BF16(acc[1][3], a1, b1[1], b1[3]);
            }
        }
        __syncthreads();
    }

    // ---- epilogue: bias + NCHW fp32 store ----
    float bs2[4][2];
    #pragma unroll
    for (int nb = 0; nb < 4; nb++) {
        int co = nbase + nb * 8 + (lane & 3) * 2;
        bs2[nb][0] = bias[co];
        bs2[nb][1] = bias[co + 1];
    }
    #pragma unroll
    for (int mt = 0; mt < 2; mt++) {
        #pragma unroll
        for (int rh = 0; rh < 2; rh++) {
            int px = x0 + mbase + mt * 16 + (lane >> 2) + rh * 8;
            size_t pix = ((size_t)y << 8) + px;
            #pragma unroll
            for (int nb = 0; nb < 4; nb++) {
                int co = nbase + nb * 8 + (lane & 3) * 2;
                out[(((size_t)b * 64 + co    ) << 16) + pix] = acc[mt][nb][rh*2+0] + bs2[nb][0];
                out[(((size_t)b * 64 + co + 1) << 16) + pix] = acc[mt][nb][rh*2+1] + bs2[nb][1];
            }
        }
    }
}

// ---------------------------------------------------------------------------
// Launch
// ---------------------------------------------------------------------------
extern "C" void kernel_launch(void* const* d_in, const int* in_sizes, int n_in,
                              void* d_out, int out_size)
{
    const float* ref   = (const float*)d_in[0];
    const float* supp  = (const float*)d_in[1];
    const float* flow  = (const float*)d_in[2];
    const float* fc_w  = (const float*)d_in[3];
    const float* fc_b  = (const float*)d_in[4];
    const float* cw[6], *cb[6];
    for (int i = 0; i < 6; i++) {
        cw[i] = (const float*)d_in[5 + 2*i];
        cb[i] = (const float*)d_in[6 + 2*i];
    }
    const float* off_w = (const float*)d_in[17];
    const float* off_b = (const float*)d_in[18];
    const float* dcn_w = (const float*)d_in[19];
    const float* dcn_b = (const float*)d_in[20];
    float* out = (float*)d_out;

    __nv_bfloat16 *wH, *wL, *rH, *rL, *t0H, *t0L, *tmpH, *tmpL, *ftH, *ftL, *Bg;
    float *f0F, *ffF, *offbuf;
    cudaGetSymbolAddress((void**)&wH,  g_wH);   cudaGetSymbolAddress((void**)&wL,  g_wL);
    cudaGetSymbolAddress((void**)&rH,  g_rH);   cudaGetSymbolAddress((void**)&rL,  g_rL);
    cudaGetSymbolAddress((void**)&t0H, g_t0H);  cudaGetSymbolAddress((void**)&t0L, g_t0L);
    cudaGetSymbolAddress((void**)&tmpH,g_tmpH); cudaGetSymbolAddress((void**)&tmpL,g_tmpL);
    cudaGetSymbolAddress((void**)&ftH, g_ftH);  cudaGetSymbolAddress((void**)&ftL, g_ftL);
    cudaGetSymbolAddress((void**)&Bg,  g_B);
    cudaGetSymbolAddress((void**)&f0F,   g_f0F);
    cudaGetSymbolAddress((void**)&ffF,   g_ffF);
    cudaGetSymbolAddress((void**)&offbuf,g_off);

    const int SMB = 1024 + 2 * 49152;   // 99328: align pad + 2 x (A 32K + B 16K)
    const int SMD = 1024 + 32768 + 32768; // 66560: pad + sS + B double buffer
    cudaFuncSetAttribute((const void*)conv_mma_kernel<1,1,1,18>, cudaFuncAttributeMaxDynamicSharedMemorySize, SMB);
    cudaFuncSetAttribute((const void*)conv_mma_kernel<1,2,1,9>,  cudaFuncAttributeMaxDynamicSharedMemorySize, SMB);
    cudaFuncSetAttribute((const void*)conv_mma_kernel<1,3,1,9>,  cudaFuncAttributeMaxDynamicSharedMemorySize, SMB);
    cudaFuncSetAttribute((const void*)conv_mma_kernel<2,2,1,9>,  cudaFuncAttributeMaxDynamicSharedMemorySize, SMB);
    cudaFuncSetAttribute((const void*)conv_mma_kernel<2,4,1,9>,  cudaFuncAttributeMaxDynamicSharedMemorySize, SMB);
    cudaFuncSetAttribute((const void*)conv_mma_kernel<4,5,1,9>,  cudaFuncAttributeMaxDynamicSharedMemorySize, SMB);
    cudaFuncSetAttribute((const void*)conv_mma_kernel<1,6,1,9>,  cudaFuncAttributeMaxDynamicSharedMemorySize, SMB);
    cudaFuncSetAttribute((const void*)dcn_mma_kernel, cudaFuncAttributeMaxDynamicSharedMemorySize, SMD);

    // Weight prep (13 B-sets)
    prep_B_kernel<<<144, 256>>>(fc_w, Bg + 0*BSET, 128, 0,  64, 0);
    prep_B_kernel<<<144, 256>>>(fc_w, Bg + 1*BSET, 128, 64, 64, 0);
    for (int i = 0; i < 6; i++)
        prep_B_kernel<<<144, 256>>>(cw[i], Bg + (2+i)*BSET, 64, 0, 64, 0);
    for (int ch = 0; ch < 4; ch++)
        prep_B_kernel<<<144, 256>>>(off_w, Bg + (8+ch)*BSET, 64, 0, 216, ch*64);
    prep_B_kernel<<<144, 256>>>(dcn_w, Bg + 12*BSET, 64, 0, 64, 0);

    // Input format conversion
    warp_nhwc_kernel<<<dim3(HWSZ/256, BB), 256>>>(supp, flow, wH, wL);
    to_nhwc_kernel<<<dim3(HWSZ/256, BB), 256>>>(ref, rH, rL);

    dim3 cg(2, 256, 4);
    // fc (fused 18-tap: taps 0-8 warped, 9-17 ref): lrelu -> feat0 (f32 + hi/lo)
    conv_mma_kernel<1,1,1,18><<<cg, 256, SMB>>>(wH, wL, rH, rL, Bg + 0*BSET, fc_b, 1, 64,
                                                f0F, t0H, t0L, nullptr, nullptr);
    // c1: relu -> tmp
    conv_mma_kernel<1,2,1,9><<<cg, 256, SMB>>>(t0H, t0L, nullptr, nullptr, Bg + 2*BSET, cb[0], 1, 64,
                                               nullptr, tmpH, tmpL, nullptr, nullptr);
    // c2: ff = feat0 + relu(v)
    conv_mma_kernel<1,3,1,9><<<cg, 256, SMB>>>(tmpH, tmpL, nullptr, nullptr, Bg + 3*BSET, cb[1], 1, 64,
                                               ffF, nullptr, nullptr, f0F, nullptr);
    // c3 (dil2): relu -> tmp
    conv_mma_kernel<2,2,1,9><<<cg, 256, SMB>>>(t0H, t0L, nullptr, nullptr, Bg + 4*BSET, cb[2], 1, 64,
                                               nullptr, tmpH, tmpL, nullptr, nullptr);
    // c4 (dil2): ff += 0.1*relu(v)
    conv_mma_kernel<2,4,1,9><<<cg, 256, SMB>>>(tmpH, tmpL, nullptr, nullptr, Bg + 5*BSET, cb[3], 1, 64,
                                               ffF, nullptr, nullptr, nullptr, nullptr);
    // c5 (dil2): relu -> tmp
    conv_mma_kernel<2,2,1,9><<<cg, 256, SMB>>>(t0H, t0L, nullptr, nullptr, Bg + 6*BSET, cb[4], 1, 64,
                                               nullptr, tmpH, tmpL, nullptr, nullptr);
    // c6 (dil4): feat = ff + 0.1*relu(v) -> hi/lo
    conv_mma_kernel<4,5,1,9><<<cg, 256, SMB>>>(tmpH, tmpL, nullptr, nullptr, Bg + 7*BSET, cb[5], 1, 64,
                                               nullptr, ftH, ftL, ffF, nullptr);
    // offset conv: 216 couts, 4 chunks, NCHW out
    dim3 og(2, 256, 16);
    conv_mma_kernel<1,6,1,9><<<og, 256, SMB>>>(ftH, ftL, nullptr, nullptr, Bg + 8*BSET, off_b, 4, 216,
                                               nullptr, nullptr, nullptr, nullptr, offbuf);
    // tensorized deformable conv
    dcn_mma_kernel<<<cg, 256, SMD>>>(supp, offbuf, flow, Bg + 12*BSET, dcn_b, out);
}

// round 8
// speedup vs baseline: 2.9576x; 1.2202x over previous
#include <cuda_runtime.h>
#include <cuda_bf16.h>
#include <math.h>
#include <stdint.h>

#define BB 4
#define HH 256
#define WW 256
#define HWSZ 65536
#define NPX (BB*HWSZ)

// ---------------------------------------------------------------------------
// PTX helpers (plain sm_103-safe: ldmatrix + mma.sync + cp.async)
// ---------------------------------------------------------------------------
__device__ __forceinline__ uint32_t smem_u32(const void* p) {
    uint32_t a;
    asm("{ .reg .u64 t; cvta.to.shared.u64 t, %1; cvt.u32.u64 %0, t; }" : "=r"(a) : "l"(p));
    return a;
}

#define LDSM_X4(r0, r1, r2, r3, addr) \
    asm volatile("ldmatrix.sync.aligned.m8n8.x4.shared.b16 {%0,%1,%2,%3}, [%4];" \
        : "=r"(r0), "=r"(r1), "=r"(r2), "=r"(r3) : "r"(addr))

#define MMA_BF16(d, a, b0v, b1v) \
    asm volatile("mma.sync.aligned.m16n8k16.row.col.f32.bf16.bf16.f32 " \
        "{%0,%1,%2,%3},{%4,%5,%6,%7},{%8,%9},{%0,%1,%2,%3};" \
        : "+f"((d)[0]), "+f"((d)[1]), "+f"((d)[2]), "+f"((d)[3]) \
        : "r"((a)[0]), "r"((a)[1]), "r"((a)[2]), "r"((a)[3]), "r"(b0v), "r"(b1v))

#define CP_ASYNC16(dst, src, sz) \
    asm volatile("cp.async.cg.shared.global [%0], [%1], 16, %2;" \
        :: "r"(dst), "l"(src), "r"(sz) : "memory")
#define CP_COMMIT() asm volatile("cp.async.commit_group;" ::: "memory")
#define CP_WAIT1() asm volatile("cp.async.wait_group 1;" ::: "memory")
#define CP_WAIT0() asm volatile("cp.async.wait_group 0;" ::: "memory")

// ---------------------------------------------------------------------------
// Device global scratch
// ---------------------------------------------------------------------------
#define FEAT_ELEMS ((size_t)NPX*64)
__device__ __nv_bfloat16 g_wH[FEAT_ELEMS], g_wL[FEAT_ELEMS];     // warped supp
__device__ __nv_bfloat16 g_rH[FEAT_ELEMS], g_rL[FEAT_ELEMS];     // ref
__device__ __nv_bfloat16 g_t0H[FEAT_ELEMS], g_t0L[FEAT_ELEMS];   // feat0
__device__ __nv_bfloat16 g_tmpH[FEAT_ELEMS], g_tmpL[FEAT_ELEMS];
__device__ __nv_bfloat16 g_ftH[FEAT_ELEMS], g_ftL[FEAT_ELEMS];   // final feat
__device__ float g_f0F[FEAT_ELEMS];                               // feat0 fp32
__device__ float g_ffF[FEAT_ELEMS];                               // feat fp32 accum
__device__ float g_off[(size_t)BB*216*HWSZ];                      // NCHW
// 13 B-sets (fc0, fc1, c1..c6, off chunks 0..3, dcn); each 9 taps x 16KB
#define BSET 73728
__device__ __nv_bfloat16 g_B[13*BSET];

// ---------------------------------------------------------------------------
// Fused B prep: all 13 sets in one launch (blockIdx.y = set)
// ---------------------------------------------------------------------------
struct PrepDesc { const float* w; int cinTot, cin0, coutTot, cout0; };
struct PrepTable { PrepDesc d[13]; };

__global__ void prep_all_kernel(PrepTable tab, __nv_bfloat16* __restrict__ outB)
{
    int set = blockIdx.y;
    PrepDesc pd = tab.d[set];
    int idx = blockIdx.x * 256 + threadIdx.x;   // < 36864
    int c = idx & 63;
    int r = (idx >> 6) & 63;
    int t = idx >> 12;
    float v = 0.f;
    int co = pd.cout0 + r;
    if (co < pd.coutTot) v = pd.w[((size_t)co * pd.cinTot + pd.cin0 + c) * 9 + t];
    __nv_bfloat16 h = __float2bfloat16(v);
    __nv_bfloat16 l = __float2bfloat16(v - __bfloat162float(h));
    uint32_t off = (uint32_t)r * 128u + (uint32_t)c * 2u;
    uint32_t so = off ^ ((off >> 3) & 0x70u);
    char* ob = (char*)(outB + (size_t)set * BSET) + (size_t)t * 16384;
    *(__nv_bfloat16*)(ob + so) = h;
    *(__nv_bfloat16*)(ob + 8192 + so) = l;
}

// ---------------------------------------------------------------------------
// flow_warp -> NHWC bf16 hi/lo
// ---------------------------------------------------------------------------
__global__ void warp_nhwc_kernel(const float* __restrict__ supp, const float* __restrict__ flow,
                                 __nv_bfloat16* __restrict__ oH, __nv_bfloat16* __restrict__ oL)
{
    int p = blockIdx.x * 256 + threadIdx.x;
    int b = blockIdx.y;
    int y = p >> 8, x = p & 255;
    float fx = flow[((size_t)b*2    )*HWSZ + p];
    float fy = flow[((size_t)b*2 + 1)*HWSZ + p];
    float sy = (float)y + fy, sx = (float)x + fx;
    float y0f = floorf(sy), x0f = floorf(sx);
    int iy0 = (int)y0f, ix0 = (int)x0f, iy1 = iy0+1, ix1 = ix0+1;
    float wy = sy - y0f, wx = sx - x0f;
    bool vy0 = ((unsigned)iy0 < HH), vy1 = ((unsigned)iy1 < HH);
    bool vx0 = ((unsigned)ix0 < WW), vx1 = ((unsigned)ix1 < WW);
    float w00 = (1.f-wy)*(1.f-wx) * ((vy0&&vx0)?1.f:0.f);
    float w01 = (1.f-wy)*wx       * ((vy0&&vx1)?1.f:0.f);
    float w10 = wy*(1.f-wx)       * ((vy1&&vx0)?1.f:0.f);
    float w11 = wy*wx             * ((vy1&&vx1)?1.f:0.f);
    int cy0 = min(max(iy0,0),HH-1), cy1 = min(max(iy1,0),HH-1);
    int cx0 = min(max(ix0,0),WW-1), cx1 = min(max(ix1,0),WW-1);
    int i00 = cy0*WW+cx0, i01 = cy0*WW+cx1, i10 = cy1*WW+cx0, i11 = cy1*WW+cx1;
    const float* sb = supp + (size_t)b*64*HWSZ;
    __nv_bfloat16* ohp = oH + ((size_t)b*HWSZ + p)*64;
    __nv_bfloat16* olp = oL + ((size_t)b*HWSZ + p)*64;
    for (int g = 0; g < 8; g++) {
        uint4 uh, ul;
        uint32_t* ph = (uint32_t*)&uh;
        uint32_t* pl = (uint32_t*)&ul;
        #pragma unroll
        for (int q = 0; q < 4; q++) {
            const float* c0 = sb + (size_t)(g*8 + q*2)*HWSZ;
            const float* c1 = c0 + HWSZ;
            float v0 = w00*c0[i00] + w01*c0[i01] + w10*c0[i10] + w11*c0[i11];
            float v1 = w00*c1[i00] + w01*c1[i01] + w10*c1[i10] + w11*c1[i11];
            __nv_bfloat162 h2 = __floats2bfloat162_rn(v0, v1);
            float2 hf = __bfloat1622float2(h2);
            __nv_bfloat162 l2 = __floats2bfloat162_rn(v0 - hf.x, v1 - hf.y);
            ph[q] = *(uint32_t*)&h2;
            pl[q] = *(uint32_t*)&l2;
        }
        ((uint4*)ohp)[g] = uh;
        ((uint4*)olp)[g] = ul;
    }
}

// NCHW fp32 -> NHWC bf16 hi/lo
__global__ void to_nhwc_kernel(const float* __restrict__ src,
                               __nv_bfloat16* __restrict__ oH, __nv_bfloat16* __restrict__ oL)
{
    int p = blockIdx.x * 256 + threadIdx.x;
    int b = blockIdx.y;
    const float* sp = src + (size_t)b*64*HWSZ + p;
    __nv_bfloat16* ohp = oH + ((size_t)b*HWSZ + p)*64;
    __nv_bfloat16* olp = oL + ((size_t)b*HWSZ + p)*64;
    for (int g = 0; g < 8; g++) {
        uint4 uh, ul;
        uint32_t* ph = (uint32_t*)&uh;
        uint32_t* pl = (uint32_t*)&ul;
        #pragma unroll
        for (int q = 0; q < 4; q++) {
            float v0 = sp[(size_t)(g*8 + q*2    )*HWSZ];
            float v1 = sp[(size_t)(g*8 + q*2 + 1)*HWSZ];
            __nv_bfloat162 h2 = __floats2bfloat162_rn(v0, v1);
            float2 hf = __bfloat1622float2(h2);
            __nv_bfloat162 l2 = __floats2bfloat162_rn(v0 - hf.x, v1 - hf.y);
            ph[q] = *(uint32_t*)&h2;
            pl[q] = *(uint32_t*)&l2;
        }
        ((uint4*)ohp)[g] = uh;
        ((uint4*)olp)[g] = ul;
    }
}

// ---------------------------------------------------------------------------
// mma.sync conv: A staged per-ki row group (reused across 3 kj taps via
// ldmatrix row offset), B streamed per-tap. Both double-buffered cp.async.
// D[128px][64cout] per CTA, 2 CTAs/SM. Per ks: 8 LDSM.x4 + 24 MMA.
// EPI: 1 +bias lrelu -> f32+hi/lo; 2 relu hi/lo; 3 relu out=res+v f32;
//      4 relu outF+=0.1v; 5 relu res+0.1v hi/lo; 6 NCHW f32 (coutTot guard)
// ---------------------------------------------------------------------------
#define AHALF 17408u            // 136 rows x 128B
#define ABUF  34816u            // hi + lo
#define BOFF  (2u*ABUF)         // B double buffer offset

template<int DIL, int EPI, int HASBIAS, int NT>
__global__ void __launch_bounds__(256, 2)
conv_mma_kernel(const __nv_bfloat16* __restrict__ inH,
                const __nv_bfloat16* __restrict__ inL,
                const __nv_bfloat16* __restrict__ inH2,
                const __nv_bfloat16* __restrict__ inL2,
                const __nv_bfloat16* __restrict__ Bimg,
                const float* __restrict__ bias,
                int nchunk, int coutTot,
                float* __restrict__ outF,
                __nv_bfloat16* __restrict__ outH,
                __nv_bfloat16* __restrict__ outL,
                const float* __restrict__ resF,
                float* __restrict__ outNCHW)
{
    extern __shared__ char smem[];
    uint32_t base = (smem_u32(smem) + 1023u) & ~1023u;

    int tid = threadIdx.x;
    int lane = tid & 31, w = tid >> 5;
    int z = blockIdx.z;
    int b = z / nchunk, chunk = z - b * nchunk;
    int y = blockIdx.y, x0 = blockIdx.x * 128;

    const int R = 128 + 2 * DIL;
    const char* Bbase = (const char*)Bimg + (size_t)chunk * 147456;

    // Stage the 3-kj row group for stage index s (A hi/lo, R pixel rows)
    auto stageA = [&](int s) {
        int ki = (NT == 18 && s >= 3) ? s - 3 : s;
        const __nv_bfloat16* iH = (NT == 18 && s >= 3) ? inH2 : inH;
        const __nv_bfloat16* iL = (NT == 18 && s >= 3) ? inL2 : inL;
        int gy = y + (ki - 1) * DIL;
        bool rowok = ((unsigned)gy < HH);
        uint32_t aB = base + (uint32_t)(s & 1) * ABUF;
        for (int i = tid; i < R * 8; i += 256) {
            int r = i >> 3, j = i & 7;
            int gx = x0 - DIL + r;
            bool ok = rowok && ((unsigned)gx < WW);
            size_t gidx = ok ? ((((size_t)b * HH + gy) * WW + gx) * 64) : 0;
            int sz = ok ? 16 : 0;
            uint32_t dst = aB + (uint32_t)r * 128u +
                           (((uint32_t)j * 16u) ^ (((uint32_t)r & 7u) * 16u));
            CP_ASYNC16(dst, (const char*)(iH + gidx) + j * 16, sz);
            CP_ASYNC16(dst + AHALF, (const char*)(iL + gidx) + j * 16, sz);
        }
    };
    auto stageB = [&](int t2) {
        const char* bsrc = Bbase + (size_t)t2 * 16384;
        uint32_t bB = base + BOFF + (uint32_t)(t2 & 1) * 16384u;
        #pragma unroll
        for (int kk = 0; kk < 4; kk++)
            CP_ASYNC16(bB + (uint32_t)tid * 16u + (uint32_t)kk * 4096u,
                       bsrc + tid * 16 + kk * 4096, 16);
    };

    stageA(0);
    stageB(0);
    CP_COMMIT();

    int mbase = (w & 3) * 32;
    int nbase = (w >> 2) * 32;

    float acc[2][4][4];
    #pragma unroll
    for (int i = 0; i < 2; i++)
        #pragma unroll
        for (int j = 0; j < 4; j++)
            #pragma unroll
            for (int q = 0; q < 4; q++) acc[i][j][q] = 0.f;

    int lr = (lane & 7) + ((lane >> 3) & 1) * 8;
    int kq = (lane >> 4) * 16;

    #pragma unroll 1
    for (int tt = 0; tt < NT; tt++) {
        if (tt + 1 < NT) {
            stageB(tt + 1);
            if ((tt + 1) % 3 == 0) stageA((tt + 1) / 3);
            CP_COMMIT();
            CP_WAIT1();
        } else {
            CP_WAIT0();
        }
        __syncthreads();

        int s = tt / 3, kj = tt - s * 3;
        uint32_t Ab = base + (uint32_t)(s & 1) * ABUF;
        uint32_t Bt = base + BOFF + (uint32_t)(tt & 1) * 16384u;
        uint32_t rowA0 = (uint32_t)(kj * DIL + mbase + lr);
        uint32_t rowB0 = (uint32_t)(nbase + lr);

        #pragma unroll
        for (int ks = 0; ks < 4; ks++) {
            uint32_t kb = (uint32_t)(ks * 32 + kq);
            uint32_t ah0[4], ah1[4], al0[4], al1[4];
            uint32_t bh0[4], bh1[4], bl0[4], bl1[4];
            {
                uint32_t r0 = rowA0, r1 = rowA0 + 16u;
                uint32_t o0 = r0*128u + (kb ^ ((r0 & 7u)*16u));
                uint32_t o1 = r1*128u + (kb ^ ((r1 & 7u)*16u));
                LDSM_X4(ah0[0], ah0[1], ah0[2], ah0[3], Ab + o0);
                LDSM_X4(ah1[0], ah1[1], ah1[2], ah1[3], Ab + o1);
                LDSM_X4(al0[0], al0[1], al0[2], al0[3], Ab + AHALF + o0);
                LDSM_X4(al1[0], al1[1], al1[2], al1[3], Ab + AHALF + o1);
            }
            {
                uint32_t r0 = rowB0, r1 = rowB0 + 16u;
                uint32_t o0 = r0*128u + (kb ^ ((r0 & 7u)*16u));
                uint32_t o1 = r1*128u + (kb ^ ((r1 & 7u)*16u));
                LDSM_X4(bh0[0], bh0[1], bh0[2], bh0[3], Bt + o0);
                LDSM_X4(bh1[0], bh1[1], bh1[2], bh1[3], Bt + o1);
                LDSM_X4(bl0[0], bl0[1], bl0[2], bl0[3], Bt + 8192u + o0);
                LDSM_X4(bl1[0], bl1[1], bl1[2], bl1[3], Bt + 8192u + o1);
            }
            // Ah*Bh
            MMA_BF16(acc[0][0], ah0, bh0[0], bh0[2]);
            MMA_BF16(acc[0][1], ah0, bh0[1], bh0[3]);
            MMA_BF16(acc[0][2], ah0, bh1[0], bh1[2]);
            MMA_BF16(acc[0][3], ah0, bh1[1], bh1[3]);
            MMA_BF16(acc[1][0], ah1, bh0[0], bh0[2]);
            MMA_BF16(acc[1][1], ah1, bh0[1], bh0[3]);
            MMA_BF16(acc[1][2], ah1, bh1[0], bh1[2]);
            MMA_BF16(acc[1][3], ah1, bh1[1], bh1[3]);
            // Ah*Bl
            MMA_BF16(acc[0][0], ah0, bl0[0], bl0[2]);
            MMA_BF16(acc[0][1], ah0, bl0[1], bl0[3]);
            MMA_BF16(acc[0][2], ah0, bl1[0], bl1[2]);
            MMA_BF16(acc[0][3], ah0, bl1[1], bl1[3]);
            MMA_BF16(acc[1][0], ah1, bl0[0], bl0[2]);
            MMA_BF16(acc[1][1], ah1, bl0[1], bl0[3]);
            MMA_BF16(acc[1][2], ah1, bl1[0], bl1[2]);
            MMA_BF16(acc[1][3], ah1, bl1[1], bl1[3]);
            // Al*Bh
            MMA_BF16(acc[0][0], al0, bh0[0], bh0[2]);
            MMA_BF16(acc[0][1], al0, bh0[1], bh0[3]);
            MMA_BF16(acc[0][2], al0, bh1[0], bh1[2]);
            MMA_BF16(acc[0][3], al0, bh1[1], bh1[3]);
            MMA_BF16(acc[1][0], al1, bh0[0], bh0[2]);
            MMA_BF16(acc[1][1], al1, bh0[1], bh0[3]);
            MMA_BF16(acc[1][2], al1, bh1[0], bh1[2]);
            MMA_BF16(acc[1][3], al1, bh1[1], bh1[3]);
        }
        __syncthreads();
    }

    // ---- epilogue ----
    float bs2[4][2];
    #pragma unroll
    for (int nb = 0; nb < 4; nb++) {
        int co = chunk * 64 + nbase + nb * 8 + (lane & 3) * 2;
        bs2[nb][0] = (HASBIAS && co     < coutTot) ? bias[co]     : 0.f;
        bs2[nb][1] = (HASBIAS && co + 1 < coutTot) ? bias[co + 1] : 0.f;
    }
    #pragma unroll
    for (int mt = 0; mt < 2; mt++) {
        #pragma unroll
        for (int rh = 0; rh < 2; rh++) {
            int px = x0 + mbase + mt * 16 + (lane >> 2) + rh * 8;
            size_t P = ((size_t)b * HH + y) * WW + px;
            #pragma unroll
            for (int nb = 0; nb < 4; nb++) {
                int cl = nbase + nb * 8 + (lane & 3) * 2;
                float v0 = acc[mt][nb][rh * 2 + 0] + bs2[nb][0];
                float v1 = acc[mt][nb][rh * 2 + 1] + bs2[nb][1];
                size_t ob = P * 64 + cl;

                if (EPI == 1) {
                    v0 = (v0 > 0.f) ? v0 : 0.1f * v0;
                    v1 = (v1 > 0.f) ? v1 : 0.1f * v1;
                    *(float2*)(outF + ob) = make_float2(v0, v1);
                    __nv_bfloat162 h2 = __floats2bfloat162_rn(v0, v1);
                    float2 hf = __bfloat1622float2(h2);
                    __nv_bfloat162 l2 = __floats2bfloat162_rn(v0 - hf.x, v1 - hf.y);
                    *(uint32_t*)(outH + ob) = *(uint32_t*)&h2;
                    *(uint32_t*)(outL + ob) = *(uint32_t*)&l2;
                } else if (EPI == 2) {
                    v0 = fmaxf(v0, 0.f); v1 = fmaxf(v1, 0.f);
                    __nv_bfloat162 h2 = __floats2bfloat162_rn(v0, v1);
                    float2 hf = __bfloat1622float2(h2);
                    __nv_bfloat162 l2 = __floats2bfloat162_rn(v0 - hf.x, v1 - hf.y);
                    *(uint32_t*)(outH + ob) = *(uint32_t*)&h2;
                    *(uint32_t*)(outL + ob) = *(uint32_t*)&l2;
                } else if (EPI == 3) {
                    float2 rv = *(const float2*)(resF + ob);
                    v0 = rv.x + fmaxf(v0, 0.f);
                    v1 = rv.y + fmaxf(v1, 0.f);
                    *(float2*)(outF + ob) = make_float2(v0, v1);
                } else if (EPI == 4) {
                    float2 rv = *(const float2*)(outF + ob);
                    v0 = rv.x + 0.1f * fmaxf(v0, 0.f);
                    v1 = rv.y + 0.1f * fmaxf(v1, 0.f);
                    *(float2*)(outF + ob) = make_float2(v0, v1);
                } else if (EPI == 5) {
                    float2 rv = *(const float2*)(resF + ob);
                    v0 = rv.x + 0.1f * fmaxf(v0, 0.f);
                    v1 = rv.y + 0.1f * fmaxf(v1, 0.f);
                    __nv_bfloat162 h2 = __floats2bfloat162_rn(v0, v1);
                    float2 hf = __bfloat1622float2(h2);
                    __nv_bfloat162 l2 = __floats2bfloat162_rn(v0 - hf.x, v1 - hf.y);
                    *(uint32_t*)(outH + ob) = *(uint32_t*)&h2;
                    *(uint32_t*)(outL + ob) = *(uint32_t*)&l2;
                } else if (EPI == 6) {
                    int co = chunk * 64 + cl;
                    size_t pix = ((size_t)y << 8) + px;
                    if (co < coutTot)
                        outNCHW[(((size_t)b * coutTot + co) << 16) + pix] = v0;
                    if (co + 1 < coutTot)
                        outNCHW[(((size_t)b * coutTot + co + 1) << 16) + pix] = v1;
                }
            }
        }
    }
}

// ---------------------------------------------------------------------------
// Modulated deformable conv, tensorized (sample -> bf16 hi/lo smem -> mma)
// ---------------------------------------------------------------------------
__global__ void __launch_bounds__(256, 2)
dcn_mma_kernel(const float* __restrict__ supp, const float* __restrict__ off,
               const float* __restrict__ flow, const __nv_bfloat16* __restrict__ Bimg,
               const float* __restrict__ bias, float* __restrict__ out)
{
    extern __shared__ char smem[];
    uint32_t base = (smem_u32(smem) + 1023u) & ~1023u;
    const uint32_t SM_S = base;            // 32KB: hi 16K | lo 16K
    const uint32_t SM_Bd = base + 32768u;  // 2 x 16KB B double buffer

    int tid = threadIdx.x;
    int lane = tid & 31, w = tid >> 5;
    int b = blockIdx.z, y = blockIdx.y, x0 = blockIdx.x * 128;

    #pragma unroll
    for (int kk = 0; kk < 4; kk++)
        CP_ASYNC16(SM_Bd + (uint32_t)tid * 16u + (uint32_t)kk * 4096u,
                   (const char*)Bimg + tid * 16 + kk * 4096, 16);
    CP_COMMIT();

    int mbase = (w & 3) * 32;
    int nbase = (w >> 2) * 32;
    float acc[2][4][4];
    #pragma unroll
    for (int i = 0; i < 2; i++)
        #pragma unroll
        for (int j = 0; j < 4; j++)
            #pragma unroll
            for (int q = 0; q < 4; q++) acc[i][j][q] = 0.f;

    int lr = (lane & 7) + ((lane >> 3) & 1) * 8;
    int kq = (lane >> 4) * 16;

    const float* fxp  = flow + ((size_t)b*2 + 0)*HWSZ + y*WW + x0;
    const float* fyp  = flow + ((size_t)b*2 + 1)*HWSZ + y*WW + x0;
    const float* offb = off  + (size_t)b*216*HWSZ + y*WW + x0;

    #pragma unroll 1
    for (int k = 0; k < 9; k++) {
        if (k < 8) {
            const char* bsrc = (const char*)Bimg + (size_t)(k + 1) * 16384;
            uint32_t bB = SM_Bd + (uint32_t)((k + 1) & 1) * 16384u;
            #pragma unroll
            for (int kk = 0; kk < 4; kk++)
                CP_ASYNC16(bB + (uint32_t)tid * 16u + (uint32_t)kk * 4096u,
                           bsrc + tid * 16 + kk * 4096, 16);
            CP_COMMIT();
        }

        int ki = k / 3, kj = k - ki * 3;
        #pragma unroll 1
        for (int it = 0; it < 4; it++) {
            int task = tid + it * 256;
            int px = task & 127;
            int g  = task >> 7;
            int cdy = g*18 + k*2;
            float rawdy = offb[(size_t)cdy          *HWSZ + px];
            float rawdx = offb[(size_t)(cdy + 1)    *HWSZ + px];
            float rawm  = offb[(size_t)(144 + g*9+k)*HWSZ + px];
            float fx = fxp[px], fy = fyp[px];
            float ady = 25.f * tanhf(rawdy) + ((cdy     < 72) ? fx : fy);
            float adx = 25.f * tanhf(rawdx) + ((cdy + 1 < 72) ? fx : fy);
            float m   = 1.f / (1.f + expf(-rawm));
            float sy = (float)y         + (float)(ki - 1) + ady;
            float sx = (float)(x0 + px) + (float)(kj - 1) + adx;
            float y0f = floorf(sy), x0f = floorf(sx);
            int iy0 = (int)y0f, ix0 = (int)x0f;
            int iy1 = iy0 + 1,  ix1 = ix0 + 1;
            float wy = sy - y0f, wx = sx - x0f;
            bool vy0 = ((unsigned)iy0 < HH), vy1 = ((unsigned)iy1 < HH);
            bool vx0 = ((unsigned)ix0 < WW), vx1 = ((unsigned)ix1 < WW);
            float w00 = (1.f - wy)*(1.f - wx) * ((vy0 && vx0) ? 1.f : 0.f) * m;
            float w01 = (1.f - wy)*wx         * ((vy0 && vx1) ? 1.f : 0.f) * m;
            float w10 = wy*(1.f - wx)         * ((vy1 && vx0) ? 1.f : 0.f) * m;
            float w11 = wy*wx                 * ((vy1 && vx1) ? 1.f : 0.f) * m;
            int cy0 = min(max(iy0, 0), HH-1), cy1 = min(max(iy1, 0), HH-1);
            int cx0 = min(max(ix0, 0), WW-1), cx1 = min(max(ix1, 0), WW-1);
            int i00 = cy0*WW + cx0, i01 = cy0*WW + cx1;
            int i10 = cy1*WW + cx0, i11 = cy1*WW + cx1;
            const float* sb = supp + ((size_t)b*64 + g*8)*HWSZ;
            uint32_t hpk[4], lpk[4];
            #pragma unroll
            for (int q = 0; q < 4; q++) {
                const float* c0 = sb + (size_t)(q*2    )*HWSZ;
                const float* c1 = sb + (size_t)(q*2 + 1)*HWSZ;
                float v0 = w00*c0[i00] + w01*c0[i01] + w10*c0[i10] + w11*c0[i11];
                float v1 = w00*c1[i00] + w01*c1[i01] + w10*c1[i10] + w11*c1[i11];
                __nv_bfloat162 h2 = __floats2bfloat162_rn(v0, v1);
                float2 hf = __bfloat1622float2(h2);
                __nv_bfloat162 l2 = __floats2bfloat162_rn(v0 - hf.x, v1 - hf.y);
                hpk[q] = *(uint32_t*)&h2;
                lpk[q] = *(uint32_t*)&l2;
            }
            uint32_t so = (uint32_t)px * 128u +
                          (((uint32_t)g * 16u) ^ (((uint32_t)px & 7u) * 16u));
            asm volatile("st.shared.v4.b32 [%0], {%1,%2,%3,%4};"
                :: "r"(SM_S + so), "r"(hpk[0]), "r"(hpk[1]), "r"(hpk[2]), "r"(hpk[3]) : "memory");
            asm volatile("st.shared.v4.b32 [%0], {%1,%2,%3,%4};"
                :: "r"(SM_S + 16384u + so), "r"(lpk[0]), "r"(lpk[1]), "r"(lpk[2]), "r"(lpk[3]) : "memory");
        }

        if (k < 8) CP_WAIT1(); else CP_WAIT0();
        __syncthreads();

        uint32_t Bt = SM_Bd + (uint32_t)(k & 1) * 16384u;
        uint32_t rowA0 = (uint32_t)(mbase + lr);
        uint32_t rowB0 = (uint32_t)(nbase + lr);
        #pragma unroll
        for (int ks = 0; ks < 4; ks++) {
            uint32_t kb = (uint32_t)(ks * 32 + kq);
            uint32_t ah0[4], ah1[4], al0[4], al1[4];
            uint32_t bh0[4], bh1[4], bl0[4], bl1[4];
            {
                uint32_t r0 = rowA0, r1 = rowA0 + 16u;
                uint32_t o0 = r0*128u + (kb ^ ((r0 & 7u)*16u));
                uint32_t o1 = r1*128u + (kb ^ ((r1 & 7u)*16u));
                LDSM_X4(ah0[0], ah0[1], ah0[2], ah0[3], SM_S + o0);
                LDSM_X4(ah1[0], ah1[1], ah1[2], ah1[3], SM_S + o1);
                LDSM_X4(al0[0], al0[1], al0[2], al0[3], SM_S + 16384u + o0);
                LDSM_X4(al1[0], al1[1], al1[2], al1[3], SM_S + 16384u + o1);
            }
            {
                uint32_t r0 = rowB0, r1 = rowB0 + 16u;
                uint32_t o0 = r0*128u + (kb ^ ((r0 & 7u)*16u));
                uint32_t o1 = r1*128u + (kb ^ ((r1 & 7u)*16u));
                LDSM_X4(bh0[0], bh0[1], bh0[2], bh0[3], Bt + o0);
                LDSM_X4(bh1[0], bh1[1], bh1[2], bh1[3], Bt + o1);
                LDSM_X4(bl0[0], bl0[1], bl0[2], bl0[3], Bt + 8192u + o0);
                LDSM_X4(bl1[0], bl1[1], bl1[2], bl1[3], Bt + 8192u + o1);
            }
            MMA_BF16(acc[0][0], ah0, bh0[0], bh0[2]);
            MMA_BF16(acc[0][1], ah0, bh0[1], bh0[3]);
            MMA_BF16(acc[0][2], ah0, bh1[0], bh1[2]);
            MMA_BF16(acc[0][3], ah0, bh1[1], bh1[3]);
            MMA_BF16(acc[1][0], ah1, bh0[0], bh0[2]);
            MMA_BF16(acc[1][1], ah1, bh0[1], bh0[3]);
            MMA_BF16(acc[1][2], ah1, bh1[0], bh1[2]);
            MMA_BF16(acc[1][3], ah1, bh1[1], bh1[3]);
            MMA_BF16(acc[0][0], ah0, bl0[0], bl0[2]);
            MMA_BF16(acc[0][1], ah0, bl0[1], bl0[3]);
            MMA_BF16(acc[0][2], ah0, bl1[0], bl1[2]);
            MMA_BF16(acc[0][3], ah0, bl1[1], bl1[3]);
            MMA_BF16(acc[1][0], ah1, bl0[0], bl0[2]);
            MMA_BF16(acc[1][1], ah1, bl0[1], bl0[3]);
            MMA_BF16(acc[1][2], ah1, bl1[0], bl1[2]);
            MMA_BF16(acc[1][3], ah1, bl1[1], bl1[3]);
            MMA_BF16(acc[0][0], al0, bh0[0], bh0[2]);
            MMA_BF16(acc[0][1], al0, bh0[1], bh0[3]);
            MMA_BF16(acc[0][2], al0, bh1[0], bh1[2]);
            MMA_BF16(acc[0][3], al0, bh1[1], bh1[3]);
            MMA_BF16(acc[1][0], al1, bh0[0], bh0[2]);
            MMA_BF16(acc[1][1], al1, bh0[1], bh0[3]);
            MMA_BF16(acc[1][2], al1, bh1[0], bh1[2]);
            MMA_BF16(acc[1][3], al1, bh1[1], bh1[3]);
        }
        __syncthreads();
    }

    // ---- epilogue: bias + NCHW fp32 store ----
    float bs2[4][2];
    #pragma unroll
    for (int nb = 0; nb < 4; nb++) {
        int co = nbase + nb * 8 + (lane & 3) * 2;
        bs2[nb][0] = bias[co];
        bs2[nb][1] = bias[co + 1];
    }
    #pragma unroll
    for (int mt = 0; mt < 2; mt++) {
        #pragma unroll
        for (int rh = 0; rh < 2; rh++) {
            int px = x0 + mbase + mt * 16 + (lane >> 2) + rh * 8;
            size_t pix = ((size_t)y << 8) + px;
            #pragma unroll
            for (int nb = 0; nb < 4; nb++) {
                int co = nbase + nb * 8 + (lane & 3) * 2;
                out[(((size_t)b * 64 + co    ) << 16) + pix] = acc[mt][nb][rh*2+0] + bs2[nb][0];
                out[(((size_t)b * 64 + co + 1) << 16) + pix] = acc[mt][nb][rh*2+1] + bs2[nb][1];
            }
        }
    }
}

// ---------------------------------------------------------------------------
// Launch
// ---------------------------------------------------------------------------
extern "C" void kernel_launch(void* const* d_in, const int* in_sizes, int n_in,
                              void* d_out, int out_size)
{
    const float* ref   = (const float*)d_in[0];
    const float* supp  = (const float*)d_in[1];
    const float* flow  = (const float*)d_in[2];
    const float* fc_w  = (const float*)d_in[3];
    const float* fc_b  = (const float*)d_in[4];
    const float* cw[6], *cb[6];
    for (int i = 0; i < 6; i++) {
        cw[i] = (const float*)d_in[5 + 2*i];
        cb[i] = (const float*)d_in[6 + 2*i];
    }
    const float* off_w = (const float*)d_in[17];
    const float* off_b = (const float*)d_in[18];
    const float* dcn_w = (const float*)d_in[19];
    const float* dcn_b = (const float*)d_in[20];
    float* out = (float*)d_out;

    __nv_bfloat16 *wH, *wL, *rH, *rL, *t0H, *t0L, *tmpH, *tmpL, *ftH, *ftL, *Bg;
    float *f0F, *ffF, *offbuf;
    cudaGetSymbolAddress((void**)&wH,  g_wH);   cudaGetSymbolAddress((void**)&wL,  g_wL);
    cudaGetSymbolAddress((void**)&rH,  g_rH);   cudaGetSymbolAddress((void**)&rL,  g_rL);
    cudaGetSymbolAddress((void**)&t0H, g_t0H);  cudaGetSymbolAddress((void**)&t0L, g_t0L);
    cudaGetSymbolAddress((void**)&tmpH,g_tmpH); cudaGetSymbolAddress((void**)&tmpL,g_tmpL);
    cudaGetSymbolAddress((void**)&ftH, g_ftH);  cudaGetSymbolAddress((void**)&ftL, g_ftL);
    cudaGetSymbolAddress((void**)&Bg,  g_B);
    cudaGetSymbolAddress((void**)&f0F,   g_f0F);
    cudaGetSymbolAddress((void**)&ffF,   g_ffF);
    cudaGetSymbolAddress((void**)&offbuf,g_off);

    const int SMB = 1024 + 2 * (int)ABUF + 2 * 16384;   // 103424
    const int SMD = 1024 + 32768 + 32768;               // 66560
    cudaFuncSetAttribute((const void*)conv_mma_kernel<1,1,1,18>, cudaFuncAttributeMaxDynamicSharedMemorySize, SMB);
    cudaFuncSetAttribute((const void*)conv_mma_kernel<1,2,1,9>,  cudaFuncAttributeMaxDynamicSharedMemorySize, SMB);
    cudaFuncSetAttribute((const void*)conv_mma_kernel<1,3,1,9>,  cudaFuncAttributeMaxDynamicSharedMemorySize, SMB);
    cudaFuncSetAttribute((const void*)conv_mma_kernel<2,2,1,9>,  cudaFuncAttributeMaxDynamicSharedMemorySize, SMB);
    cudaFuncSetAttribute((const void*)conv_mma_kernel<2,4,1,9>,  cudaFuncAttributeMaxDynamicSharedMemorySize, SMB);
    cudaFuncSetAttribute((const void*)conv_mma_kernel<4,5,1,9>,  cudaFuncAttributeMaxDynamicSharedMemorySize, SMB);
    cudaFuncSetAttribute((const void*)conv_mma_kernel<1,6,1,9>,  cudaFuncAttributeMaxDynamicSharedMemorySize, SMB);
    cudaFuncSetAttribute((const void*)dcn_mma_kernel, cudaFuncAttributeMaxDynamicSharedMemorySize, SMD);

    // Fused weight prep (13 sets, one launch)
    PrepTable tab;
    tab.d[0]  = {fc_w, 128, 0,  64, 0};
    tab.d[1]  = {fc_w, 128, 64, 64, 0};
    for (int i = 0; i < 6; i++) tab.d[2+i] = {cw[i], 64, 0, 64, 0};
    for (int ch = 0; ch < 4; ch++) tab.d[8+ch] = {off_w, 64, 0, 216, ch*64};
    tab.d[12] = {dcn_w, 64, 0, 64, 0};
    prep_all_kernel<<<dim3(144, 13), 256>>>(tab, Bg);

    // Input format conversion
    warp_nhwc_kernel<<<dim3(HWSZ/256, BB), 256>>>(supp, flow, wH, wL);
    to_nhwc_kernel<<<dim3(HWSZ/256, BB), 256>>>(ref, rH, rL);

    dim3 cg(2, 256, 4);
    // fc (fused 18-tap): lrelu -> feat0 (f32 + hi/lo)
    conv_mma_kernel<1,1,1,18><<<cg, 256, SMB>>>(wH, wL, rH, rL, Bg + 0*BSET, fc_b, 1, 64,
                                                f0F, t0H, t0L, nullptr, nullptr);
    // c1: relu -> tmp
    conv_mma_kernel<1,2,1,9><<<cg, 256, SMB>>>(t0H, t0L, nullptr, nullptr, Bg + 2*BSET, cb[0], 1, 64,
                                               nullptr, tmpH, tmpL, nullptr, nullptr);
    // c2: ff = feat0 + relu(v)
    conv_mma_kernel<1,3,1,9><<<cg, 256, SMB>>>(tmpH, tmpL, nullptr, nullptr, Bg + 3*BSET, cb[1], 1, 64,
                                               ffF, nullptr, nullptr, f0F, nullptr);
    // c3 (dil2): relu -> tmp
    conv_mma_kernel<2,2,1,9><<<cg, 256, SMB>>>(t0H, t0L, nullptr, nullptr, Bg + 4*BSET, cb[2], 1, 64,
                                               nullptr, tmpH, tmpL, nullptr, nullptr);
    // c4 (dil2): ff += 0.1*relu(v)
    conv_mma_kernel<2,4,1,9><<<cg, 256, SMB>>>(tmpH, tmpL, nullptr, nullptr, Bg + 5*BSET, cb[3], 1, 64,
                                               ffF, nullptr, nullptr, nullptr, nullptr);
    // c5 (dil2): relu -> tmp
    conv_mma_kernel<2,2,1,9><<<cg, 256, SMB>>>(t0H, t0L, nullptr, nullptr, Bg + 6*BSET, cb[4], 1, 64,
                                               nullptr, tmpH, tmpL, nullptr, nullptr);
    // c6 (dil4): feat = ff + 0.1*relu(v) -> hi/lo
    conv_mma_kernel<4,5,1,9><<<cg, 256, SMB>>>(tmpH, tmpL, nullptr, nullptr, Bg + 7*BSET, cb[5], 1, 64,
                                               nullptr, ftH, ftL, ffF, nullptr);
    // offset conv: 216 couts, 4 chunks, NCHW out
    dim3 og(2, 256, 16);
    conv_mma_kernel<1,6,1,9><<<og, 256, SMB>>>(ftH, ftL, nullptr, nullptr, Bg + 8*BSET, off_b, 4, 216,
                                               nullptr, nullptr, nullptr, nullptr, offbuf);
    // tensorized deformable conv
    dcn_mma_kernel<<<cg, 256, SMD>>>(supp, offbuf, flow, Bg + 12*BSET, dcn_b, out);
}

// round 10
// speedup vs baseline: 2.9669x; 1.0032x over previous
#include <cuda_runtime.h>
#include <cuda_bf16.h>
#include <math.h>
#include <stdint.h>

#define BB 4
#define HH 256
#define WW 256
#define HWSZ 65536
#define NPX (BB*HWSZ)

// ---------------------------------------------------------------------------
// PTX helpers (plain sm_103-safe: ldmatrix + mma.sync + cp.async)
// ---------------------------------------------------------------------------
__device__ __forceinline__ uint32_t smem_u32(const void* p) {
    uint32_t a;
    asm("{ .reg .u64 t; cvta.to.shared.u64 t, %1; cvt.u32.u64 %0, t; }" : "=r"(a) : "l"(p));
    return a;
}

#define LDSM_X4(r0, r1, r2, r3, addr) \
    asm volatile("ldmatrix.sync.aligned.m8n8.x4.shared.b16 {%0,%1,%2,%3}, [%4];" \
        : "=r"(r0), "=r"(r1), "=r"(r2), "=r"(r3) : "r"(addr))

#define MMA_BF16(d, a, b0v, b1v) \
    asm volatile("mma.sync.aligned.m16n8k16.row.col.f32.bf16.bf16.f32 " \
        "{%0,%1,%2,%3},{%4,%5,%6,%7},{%8,%9},{%0,%1,%2,%3};" \
        : "+f"((d)[0]), "+f"((d)[1]), "+f"((d)[2]), "+f"((d)[3]) \
        : "r"((a)[0]), "r"((a)[1]), "r"((a)[2]), "r"((a)[3]), "r"(b0v), "r"(b1v))

#define CP_ASYNC16(dst, src, sz) \
    asm volatile("cp.async.cg.shared.global [%0], [%1], 16, %2;" \
        :: "r"(dst), "l"(src), "r"(sz) : "memory")
#define CP_COMMIT() asm volatile("cp.async.commit_group;" ::: "memory")
#define CP_WAIT1() asm volatile("cp.async.wait_group 1;" ::: "memory")
#define CP_WAIT0() asm volatile("cp.async.wait_group 0;" ::: "memory")

// ---------------------------------------------------------------------------
// Device global scratch
// ---------------------------------------------------------------------------
#define FEAT_ELEMS ((size_t)NPX*64)
__device__ __nv_bfloat16 g_wH[FEAT_ELEMS], g_wL[FEAT_ELEMS];     // warped supp
__device__ __nv_bfloat16 g_rH[FEAT_ELEMS], g_rL[FEAT_ELEMS];     // ref
__device__ __nv_bfloat16 g_t0H[FEAT_ELEMS], g_t0L[FEAT_ELEMS];   // feat0
__device__ __nv_bfloat16 g_tmpH[FEAT_ELEMS], g_tmpL[FEAT_ELEMS];
__device__ __nv_bfloat16 g_ftH[FEAT_ELEMS], g_ftL[FEAT_ELEMS];   // final feat
__device__ float g_f0F[FEAT_ELEMS];                               // feat0 fp32
__device__ float g_ffF[FEAT_ELEMS];                               // feat fp32 accum
__device__ float g_off[(size_t)BB*216*HWSZ];                      // NCHW
// 13 B-sets (fc0, fc1, c1..c6, off chunks 0..3, dcn); each 9 taps x 16KB
#define BSET 73728
__device__ __nv_bfloat16 g_B[13*BSET];

// ---------------------------------------------------------------------------
// Fused B prep: all 13 sets in one launch (blockIdx.y = set)
// ---------------------------------------------------------------------------
struct PrepDesc { const float* w; int cinTot, cin0, coutTot, cout0; };
struct PrepTable { PrepDesc d[13]; };

__global__ void prep_all_kernel(PrepTable tab, __nv_bfloat16* __restrict__ outB)
{
    int set = blockIdx.y;
    PrepDesc pd = tab.d[set];
    int idx = blockIdx.x * 256 + threadIdx.x;   // < 36864
    int c = idx & 63;
    int r = (idx >> 6) & 63;
    int t = idx >> 12;
    float v = 0.f;
    int co = pd.cout0 + r;
    if (co < pd.coutTot) v = pd.w[((size_t)co * pd.cinTot + pd.cin0 + c) * 9 + t];
    __nv_bfloat16 h = __float2bfloat16(v);
    __nv_bfloat16 l = __float2bfloat16(v - __bfloat162float(h));
    uint32_t off = (uint32_t)r * 128u + (uint32_t)c * 2u;
    uint32_t so = off ^ ((off >> 3) & 0x70u);
    char* ob = (char*)(outB + (size_t)set * BSET) + (size_t)t * 16384;
    *(__nv_bfloat16*)(ob + so) = h;
    *(__nv_bfloat16*)(ob + 8192 + so) = l;
}

// ---------------------------------------------------------------------------
// flow_warp -> NHWC bf16 hi/lo
// ---------------------------------------------------------------------------
__global__ void warp_nhwc_kernel(const float* __restrict__ supp, const float* __restrict__ flow,
                                 __nv_bfloat16* __restrict__ oH, __nv_bfloat16* __restrict__ oL)
{
    int p = blockIdx.x * 256 + threadIdx.x;
    int b = blockIdx.y;
    int y = p >> 8, x = p & 255;
    float fx = flow[((size_t)b*2    )*HWSZ + p];
    float fy = flow[((size_t)b*2 + 1)*HWSZ + p];
    float sy = (float)y + fy, sx = (float)x + fx;
    float y0f = floorf(sy), x0f = floorf(sx);
    int iy0 = (int)y0f, ix0 = (int)x0f, iy1 = iy0+1, ix1 = ix0+1;
    float wy = sy - y0f, wx = sx - x0f;
    bool vy0 = ((unsigned)iy0 < HH), vy1 = ((unsigned)iy1 < HH);
    bool vx0 = ((unsigned)ix0 < WW), vx1 = ((unsigned)ix1 < WW);
    float w00 = (1.f-wy)*(1.f-wx) * ((vy0&&vx0)?1.f:0.f);
    float w01 = (1.f-wy)*wx       * ((vy0&&vx1)?1.f:0.f);
    float w10 = wy*(1.f-wx)       * ((vy1&&vx0)?1.f:0.f);
    float w11 = wy*wx             * ((vy1&&vx1)?1.f:0.f);
    int cy0 = min(max(iy0,0),HH-1), cy1 = min(max(iy1,0),HH-1);
    int cx0 = min(max(ix0,0),WW-1), cx1 = min(max(ix1,0),WW-1);
    int i00 = cy0*WW+cx0, i01 = cy0*WW+cx1, i10 = cy1*WW+cx0, i11 = cy1*WW+cx1;
    const float* sb = supp + (size_t)b*64*HWSZ;
    __nv_bfloat16* ohp = oH + ((size_t)b*HWSZ + p)*64;
    __nv_bfloat16* olp = oL + ((size_t)b*HWSZ + p)*64;
    for (int g = 0; g < 8; g++) {
        uint4 uh, ul;
        uint32_t* ph = (uint32_t*)&uh;
        uint32_t* pl = (uint32_t*)&ul;
        #pragma unroll
        for (int q = 0; q < 4; q++) {
            const float* c0 = sb + (size_t)(g*8 + q*2)*HWSZ;
            const float* c1 = c0 + HWSZ;
            float v0 = w00*c0[i00] + w01*c0[i01] + w10*c0[i10] + w11*c0[i11];
            float v1 = w00*c1[i00] + w01*c1[i01] + w10*c1[i10] + w11*c1[i11];
            __nv_bfloat162 h2 = __floats2bfloat162_rn(v0, v1);
            float2 hf = __bfloat1622float2(h2);
            __nv_bfloat162 l2 = __floats2bfloat162_rn(v0 - hf.x, v1 - hf.y);
            ph[q] = *(uint32_t*)&h2;
            pl[q] = *(uint32_t*)&l2;
        }
        ((uint4*)ohp)[g] = uh;
        ((uint4*)olp)[g] = ul;
    }
}

// NCHW fp32 -> NHWC bf16 hi/lo
__global__ void to_nhwc_kernel(const float* __restrict__ src,
                               __nv_bfloat16* __restrict__ oH, __nv_bfloat16* __restrict__ oL)
{
    int p = blockIdx.x * 256 + threadIdx.x;
    int b = blockIdx.y;
    const float* sp = src + (size_t)b*64*HWSZ + p;
    __nv_bfloat16* ohp = oH + ((size_t)b*HWSZ + p)*64;
    __nv_bfloat16* olp = oL + ((size_t)b*HWSZ + p)*64;
    for (int g = 0; g < 8; g++) {
        uint4 uh, ul;
        uint32_t* ph = (uint32_t*)&uh;
        uint32_t* pl = (uint32_t*)&ul;
        #pragma unroll
        for (int q = 0; q < 4; q++) {
            float v0 = sp[(size_t)(g*8 + q*2    )*HWSZ];
            float v1 = sp[(size_t)(g*8 + q*2 + 1)*HWSZ];
            __nv_bfloat162 h2 = __floats2bfloat162_rn(v0, v1);
            float2 hf = __bfloat1622float2(h2);
            __nv_bfloat162 l2 = __floats2bfloat162_rn(v0 - hf.x, v1 - hf.y);
            ph[q] = *(uint32_t*)&h2;
            pl[q] = *(uint32_t*)&l2;
        }
        ((uint4*)ohp)[g] = uh;
        ((uint4*)olp)[g] = ul;
    }
}

// ---------------------------------------------------------------------------
// mma.sync conv: SINGLE A buffer (staged per ki-boundary after post-compute
// sync), double-buffered B streamed per tap. 3 CTAs/SM (smem ~67KB, regs<=84).
// cp.async group invariant: if this iteration committed a group, wait_group 1
// drains tap tt's group; otherwise (ki boundary / last tap) wait_group 0.
// EPI: 1 +bias lrelu -> f32+hi/lo; 2 relu hi/lo; 3 relu out=res+v f32;
//      4 relu outF+=0.1v; 5 relu res+0.1v hi/lo; 6 NCHW f32 (coutTot guard)
// ---------------------------------------------------------------------------
template<int DIL, int EPI, int HASBIAS, int NT>
__global__ void __launch_bounds__(256, 3)
conv_mma_kernel(const __nv_bfloat16* __restrict__ inH,
                const __nv_bfloat16* __restrict__ inL,
                const __nv_bfloat16* __restrict__ inH2,
                const __nv_bfloat16* __restrict__ inL2,
                const __nv_bfloat16* __restrict__ Bimg,
                const float* __restrict__ bias,
                int nchunk, int coutTot,
                float* __restrict__ outF,
                __nv_bfloat16* __restrict__ outH,
                __nv_bfloat16* __restrict__ outL,
                const float* __restrict__ resF,
                float* __restrict__ outNCHW)
{
    constexpr uint32_t R = 128 + 2 * DIL;
    constexpr uint32_t AHALF = R * 128u;
    constexpr uint32_t ABUF = 2u * AHALF;

    extern __shared__ char smem[];
    uint32_t base = (smem_u32(smem) + 1023u) & ~1023u;

    int tid = threadIdx.x;
    int lane = tid & 31, w = tid >> 5;
    int z = blockIdx.z;
    int b = z / nchunk, chunk = z - b * nchunk;
    int y = blockIdx.y, x0 = blockIdx.x * 128;

    const char* Bbase = (const char*)Bimg + (size_t)chunk * 147456;

    // Stage A row group for stage index s into the single A buffer
    auto stageA = [&](int s) {
        int ki = (NT == 18 && s >= 3) ? s - 3 : s;
        const __nv_bfloat16* iH = (NT == 18 && s >= 3) ? inH2 : inH;
        const __nv_bfloat16* iL = (NT == 18 && s >= 3) ? inL2 : inL;
        int gy = y + (ki - 1) * DIL;
        bool rowok = ((unsigned)gy < HH);
        for (int i = tid; i < (int)(R * 8); i += 256) {
            int r = i >> 3, j = i & 7;
            int gx = x0 - DIL + r;
            bool ok = rowok && ((unsigned)gx < WW);
            size_t gidx = ok ? ((((size_t)b * HH + gy) * WW + gx) * 64) : 0;
            int sz = ok ? 16 : 0;
            uint32_t dst = base + (uint32_t)r * 128u +
                           (((uint32_t)j * 16u) ^ (((uint32_t)r & 7u) * 16u));
            CP_ASYNC16(dst, (const char*)(iH + gidx) + j * 16, sz);
            CP_ASYNC16(dst + AHALF, (const char*)(iL + gidx) + j * 16, sz);
        }
    };
    auto stageB = [&](int t2) {
        const char* bsrc = Bbase + (size_t)t2 * 16384;
        uint32_t bB = base + ABUF + (uint32_t)(t2 & 1) * 16384u;
        #pragma unroll
        for (int kk = 0; kk < 4; kk++)
            CP_ASYNC16(bB + (uint32_t)tid * 16u + (uint32_t)kk * 4096u,
                       bsrc + tid * 16 + kk * 4096, 16);
    };

    stageA(0);
    stageB(0);
    CP_COMMIT();

    int mbase = (w & 3) * 32;
    int nbase = (w >> 2) * 32;

    float acc[2][4][4];
    #pragma unroll
    for (int i = 0; i < 2; i++)
        #pragma unroll
        for (int j = 0; j < 4; j++)
            #pragma unroll
            for (int q = 0; q < 4; q++) acc[i][j][q] = 0.f;

    int lr = (lane & 7) + ((lane >> 3) & 1) * 8;
    int kq = (lane >> 4) * 16;

    #pragma unroll 1
    for (int tt = 0; tt < NT; tt++) {
        // Non-boundary: prefetch next tap's B, then wait1 drains tap tt's group.
        // Boundary / last: nothing new committed -> the sole pending group holds
        // tap tt's data, so wait0 (it was committed a full iteration ago).
        if (tt + 1 < NT && (tt + 1) % 3 != 0) {
            stageB(tt + 1);
            CP_COMMIT();
            CP_WAIT1();
        } else {
            CP_WAIT0();
        }
        __syncthreads();

        int s = tt / 3, kj = tt - s * 3;
        uint32_t Bt = base + ABUF + (uint32_t)(tt & 1) * 16384u;
        uint32_t rowA0 = (uint32_t)(kj * DIL + mbase + lr);
        uint32_t rowB0 = (uint32_t)(nbase + lr);

        #pragma unroll
        for (int ks = 0; ks < 4; ks++) {
            uint32_t kb = (uint32_t)(ks * 32 + kq);
            uint32_t ah0[4], ah1[4], al0[4], al1[4];
            uint32_t bh0[4], bh1[4], bl0[4], bl1[4];
            {
                uint32_t r0 = rowA0, r1 = rowA0 + 16u;
                uint32_t o0 = r0*128u + (kb ^ ((r0 & 7u)*16u));
                uint32_t o1 = r1*128u + (kb ^ ((r1 & 7u)*16u));
                LDSM_X4(ah0[0], ah0[1], ah0[2], ah0[3], base + o0);
                LDSM_X4(ah1[0], ah1[1], ah1[2], ah1[3], base + o1);
                LDSM_X4(al0[0], al0[1], al0[2], al0[3], base + AHALF + o0);
                LDSM_X4(al1[0], al1[1], al1[2], al1[3], base + AHALF + o1);
            }
            {
                uint32_t r0 = rowB0, r1 = rowB0 + 16u;
                uint32_t o0 = r0*128u + (kb ^ ((r0 & 7u)*16u));
                uint32_t o1 = r1*128u + (kb ^ ((r1 & 7u)*16u));
                LDSM_X4(bh0[0], bh0[1], bh0[2], bh0[3], Bt + o0);
                LDSM_X4(bh1[0], bh1[1], bh1[2], bh1[3], Bt + o1);
                LDSM_X4(bl0[0], bl0[1], bl0[2], bl0[3], Bt + 8192u + o0);
                LDSM_X4(bl1[0], bl1[1], bl1[2], bl1[3], Bt + 8192u + o1);
            }
            // Ah*Bh
            MMA_BF16(acc[0][0], ah0, bh0[0], bh0[2]);
            MMA_BF16(acc[0][1], ah0, bh0[1], bh0[3]);
            MMA_BF16(acc[0][2], ah0, bh1[0], bh1[2]);
            MMA_BF16(acc[0][3], ah0, bh1[1], bh1[3]);
            MMA_BF16(acc[1][0], ah1, bh0[0], bh0[2]);
            MMA_BF16(acc[1][1], ah1, bh0[1], bh0[3]);
            MMA_BF16(acc[1][2], ah1, bh1[0], bh1[2]);
            MMA_BF16(acc[1][3], ah1, bh1[1], bh1[3]);
            // Ah*Bl
            MMA_BF16(acc[0][0], ah0, bl0[0], bl0[2]);
            MMA_BF16(acc[0][1], ah0, bl0[1], bl0[3]);
            MMA_BF16(acc[0][2], ah0, bl1[0], bl1[2]);
            MMA_BF16(acc[0][3], ah0, bl1[1], bl1[3]);
            MMA_BF16(acc[1][0], ah1, bl0[0], bl0[2]);
            MMA_BF16(acc[1][1], ah1, bl0[1], bl0[3]);
            MMA_BF16(acc[1][2], ah1, bl1[0], bl1[2]);
            MMA_BF16(acc[1][3], ah1, bl1[1], bl1[3]);
            // Al*Bh
            MMA_BF16(acc[0][0], al0, bh0[0], bh0[2]);
            MMA_BF16(acc[0][1], al0, bh0[1], bh0[3]);
            MMA_BF16(acc[0][2], al0, bh1[0], bh1[2]);
            MMA_BF16(acc[0][3], al0, bh1[1], bh1[3]);
            MMA_BF16(acc[1][0], al1, bh0[0], bh0[2]);
            MMA_BF16(acc[1][1], al1, bh0[1], bh0[3]);
            MMA_BF16(acc[1][2], al1, bh1[0], bh1[2]);
            MMA_BF16(acc[1][3], al1, bh1[1], bh1[3]);
        }
        __syncthreads();

        // ki-boundary: A buffer now free of readers; stage next A + next B
        if (tt + 1 < NT && (tt + 1) % 3 == 0) {
            stageA((tt + 1) / 3);
            stageB(tt + 1);
            CP_COMMIT();
        }
    }

    // ---- epilogue ----
    float bs2[4][2];
    #pragma unroll
    for (int nb = 0; nb < 4; nb++) {
        int co = chunk * 64 + nbase + nb * 8 + (lane & 3) * 2;
        bs2[nb][0] = (HASBIAS && co     < coutTot) ? bias[co]     : 0.f;
        bs2[nb][1] = (HASBIAS && co + 1 < coutTot) ? bias[co + 1] : 0.f;
    }
    #pragma unroll
    for (int mt = 0; mt < 2; mt++) {
        #pragma unroll
        for (int rh = 0; rh < 2; rh++) {
            int px = x0 + mbase + mt * 16 + (lane >> 2) + rh * 8;
            size_t P = ((size_t)b * HH + y) * WW + px;
            #pragma unroll
            for (int nb = 0; nb < 4; nb++) {
                int cl = nbase + nb * 8 + (lane & 3) * 2;
                float v0 = acc[mt][nb][rh * 2 + 0] + bs2[nb][0];
                float v1 = acc[mt][nb][rh * 2 + 1] + bs2[nb][1];
                size_t ob = P * 64 + cl;

                if (EPI == 1) {
                    v0 = (v0 > 0.f) ? v0 : 0.1f * v0;
                    v1 = (v1 > 0.f) ? v1 : 0.1f * v1;
                    *(float2*)(outF + ob) = make_float2(v0, v1);
                    __nv_bfloat162 h2 = __floats2bfloat162_rn(v0, v1);
                    float2 hf = __bfloat1622float2(h2);
                    __nv_bfloat162 l2 = __floats2bfloat162_rn(v0 - hf.x, v1 - hf.y);
                    *(uint32_t*)(outH + ob) = *(uint32_t*)&h2;
                    *(uint32_t*)(outL + ob) = *(uint32_t*)&l2;
                } else if (EPI == 2) {
                    v0 = fmaxf(v0, 0.f); v1 = fmaxf(v1, 0.f);
                    __nv_bfloat162 h2 = __floats2bfloat162_rn(v0, v1);
                    float2 hf = __bfloat1622float2(h2);
                    __nv_bfloat162 l2 = __floats2bfloat162_rn(v0 - hf.x, v1 - hf.y);
                    *(uint32_t*)(outH + ob) = *(uint32_t*)&h2;
                    *(uint32_t*)(outL + ob) = *(uint32_t*)&l2;
                } else if (EPI == 3) {
                    float2 rv = *(const float2*)(resF + ob);
                    v0 = rv.x + fmaxf(v0, 0.f);
                    v1 = rv.y + fmaxf(v1, 0.f);
                    *(float2*)(outF + ob) = make_float2(v0, v1);
                } else if (EPI == 4) {
                    float2 rv = *(const float2*)(outF + ob);
                    v0 = rv.x + 0.1f * fmaxf(v0, 0.f);
                    v1 = rv.y + 0.1f * fmaxf(v1, 0.f);
                    *(float2*)(outF + ob) = make_float2(v0, v1);
                } else if (EPI == 5) {
                    float2 rv = *(const float2*)(resF + ob);
                    v0 = rv.x + 0.1f * fmaxf(v0, 0.f);
                    v1 = rv.y + 0.1f * fmaxf(v1, 0.f);
                    __nv_bfloat162 h2 = __floats2bfloat162_rn(v0, v1);
                    float2 hf = __bfloat1622float2(h2);
                    __nv_bfloat162 l2 = __floats2bfloat162_rn(v0 - hf.x, v1 - hf.y);
                    *(uint32_t*)(outH + ob) = *(uint32_t*)&h2;
                    *(uint32_t*)(outL + ob) = *(uint32_t*)&l2;
                } else if (EPI == 6) {
                    int co = chunk * 64 + cl;
                    size_t pix = ((size_t)y << 8) + px;
                    if (co < coutTot)
                        outNCHW[(((size_t)b * coutTot + co) << 16) + pix] = v0;
                    if (co + 1 < coutTot)
                        outNCHW[(((size_t)b * coutTot + co + 1) << 16) + pix] = v1;
                }
            }
        }
    }
}

// ---------------------------------------------------------------------------
// Modulated deformable conv, tensorized (sample -> bf16 hi/lo smem -> mma)
// ---------------------------------------------------------------------------
__global__ void __launch_bounds__(256, 2)
dcn_mma_kernel(const float* __restrict__ supp, const float* __restrict__ off,
               const float* __restrict__ flow, const __nv_bfloat16* __restrict__ Bimg,
               const float* __restrict__ bias, float* __restrict__ out)
{
    extern __shared__ char smem[];
    uint32_t base = (smem_u32(smem) + 1023u) & ~1023u;
    const uint32_t SM_S = base;            // 32KB: hi 16K | lo 16K
    const uint32_t SM_Bd = base + 32768u;  // 2 x 16KB B double buffer

    int tid = threadIdx.x;
    int lane = tid & 31, w = tid >> 5;
    int b = blockIdx.z, y = blockIdx.y, x0 = blockIdx.x * 128;

    #pragma unroll
    for (int kk = 0; kk < 4; kk++)
        CP_ASYNC16(SM_Bd + (uint32_t)tid * 16u + (uint32_t)kk * 4096u,
                   (const char*)Bimg + tid * 16 + kk * 4096, 16);
    CP_COMMIT();

    int mbase = (w & 3) * 32;
    int nbase = (w >> 2) * 32;
    float acc[2][4][4];
    #pragma unroll
    for (int i = 0; i < 2; i++)
        #pragma unroll
        for (int j = 0; j < 4; j++)
            #pragma unroll
            for (int q = 0; q < 4; q++) acc[i][j][q] = 0.f;

    int lr = (lane & 7) + ((lane >> 3) & 1) * 8;
    int kq = (lane >> 4) * 16;

    const float* fxp  = flow + ((size_t)b*2 + 0)*HWSZ + y*WW + x0;
    const float* fyp  = flow + ((size_t)b*2 + 1)*HWSZ + y*WW + x0;
    const float* offb = off  + (size_t)b*216*HWSZ + y*WW + x0;

    #pragma unroll 1
    for (int k = 0; k < 9; k++) {
        if (k < 8) {
            const char* bsrc = (const char*)Bimg + (size_t)(k + 1) * 16384;
            uint32_t bB = SM_Bd + (uint32_t)((k + 1) & 1) * 16384u;
            #pragma unroll
            for (int kk = 0; kk < 4; kk++)
                CP_ASYNC16(bB + (uint32_t)tid * 16u + (uint32_t)kk * 4096u,
                           bsrc + tid * 16 + kk * 4096, 16);
            CP_COMMIT();
        }

        int ki = k / 3, kj = k - ki * 3;
        #pragma unroll 1
        for (int it = 0; it < 4; it++) {
            int task = tid + it * 256;
            int px = task & 127;
            int g  = task >> 7;
            int cdy = g*18 + k*2;
            float rawdy = offb[(size_t)cdy          *HWSZ + px];
            float rawdx = offb[(size_t)(cdy + 1)    *HWSZ + px];
            float rawm  = offb[(size_t)(144 + g*9+k)*HWSZ + px];
            float fx = fxp[px], fy = fyp[px];
            float ady = 25.f * tanhf(rawdy) + ((cdy     < 72) ? fx : fy);
            float adx = 25.f * tanhf(rawdx) + ((cdy + 1 < 72) ? fx : fy);
            float m   = 1.f / (1.f + expf(-rawm));
            float sy = (float)y         + (float)(ki - 1) + ady;
            float sx = (float)(x0 + px) + (float)(kj - 1) + adx;
            float y0f = floorf(sy), x0f = floorf(sx);
            int iy0 = (int)y0f, ix0 = (int)x0f;
            int iy1 = iy0 + 1,  ix1 = ix0 + 1;
            float wy = sy - y0f, wx = sx - x0f;
            bool vy0 = ((unsigned)iy0 < HH), vy1 = ((unsigned)iy1 < HH);
            bool vx0 = ((unsigned)ix0 < WW), vx1 = ((unsigned)ix1 < WW);
            float w00 = (1.f - wy)*(1.f - wx) * ((vy0 && vx0) ? 1.f : 0.f) * m;
            float w01 = (1.f - wy)*wx         * ((vy0 && vx1) ? 1.f : 0.f) * m;
            float w10 = wy*(1.f - wx)         * ((vy1 && vx0) ? 1.f : 0.f) * m;
            float w11 = wy*wx                 * ((vy1 && vx1) ? 1.f : 0.f) * m;
            int cy0 = min(max(iy0, 0), HH-1), cy1 = min(max(iy1, 0), HH-1);
            int cx0 = min(max(ix0, 0), WW-1), cx1 = min(max(ix1, 0), WW-1);
            int i00 = cy0*WW + cx0, i01 = cy0*WW + cx1;
            int i10 = cy1*WW + cx0, i11 = cy1*WW + cx1;
            const float* sb = supp + ((size_t)b*64 + g*8)*HWSZ;
            uint32_t hpk[4], lpk[4];
            #pragma unroll
            for (int q = 0; q < 4; q++) {
                const float* c0 = sb + (size_t)(q*2    )*HWSZ;
                const float* c1 = sb + (size_t)(q*2 + 1)*HWSZ;
                float v0 = w00*c0[i00] + w01*c0[i01] + w10*c0[i10] + w11*c0[i11];
                float v1 = w00*c1[i00] + w01*c1[i01] + w10*c1[i10] + w11*c1[i11];
                __nv_bfloat162 h2 = __floats2bfloat162_rn(v0, v1);
                float2 hf = __bfloat1622float2(h2);
                __nv_bfloat162 l2 = __floats2bfloat162_rn(v0 - hf.x, v1 - hf.y);
                hpk[q] = *(uint32_t*)&h2;
                lpk[q] = *(uint32_t*)&l2;
            }
            uint32_t so = (uint32_t)px * 128u +
                          (((uint32_t)g * 16u) ^ (((uint32_t)px & 7u) * 16u));
            asm volatile("st.shared.v4.b32 [%0], {%1,%2,%3,%4};"
                :: "r"(SM_S + so), "r"(hpk[0]), "r"(hpk[1]), "r"(hpk[2]), "r"(hpk[3]) : "memory");
            asm volatile("st.shared.v4.b32 [%0], {%1,%2,%3,%4};"
                :: "r"(SM_S + 16384u + so), "r"(lpk[0]), "r"(lpk[1]), "r"(lpk[2]), "r"(lpk[3]) : "memory");
        }

        if (k < 8) CP_WAIT1(); else CP_WAIT0();
        __syncthreads();

        uint32_t Bt = SM_Bd + (uint32_t)(k & 1) * 16384u;
        uint32_t rowA0 = (uint32_t)(mbase + lr);
        uint32_t rowB0 = (uint32_t)(nbase + lr);
        #pragma unroll
        for (int ks = 0; ks < 4; ks++) {
            uint32_t kb = (uint32_t)(ks * 32 + kq);
            uint32_t ah0[4], ah1[4], al0[4], al1[4];
            uint32_t bh0[4], bh1[4], bl0[4], bl1[4];
            {
                uint32_t r0 = rowA0, r1 = rowA0 + 16u;
                uint32_t o0 = r0*128u + (kb ^ ((r0 & 7u)*16u));
                uint32_t o1 = r1*128u + (kb ^ ((r1 & 7u)*16u));
                LDSM_X4(ah0[0], ah0[1], ah0[2], ah0[3], SM_S + o0);
                LDSM_X4(ah1[0], ah1[1], ah1[2], ah1[3], SM_S + o1);
                LDSM_X4(al0[0], al0[1], al0[2], al0[3], SM_S + 16384u + o0);
                LDSM_X4(al1[0], al1[1], al1[2], al1[3], SM_S + 16384u + o1);
            }
            {
                uint32_t r0 = rowB0, r1 = rowB0 + 16u;
                uint32_t o0 = r0*128u + (kb ^ ((r0 & 7u)*16u));
                uint32_t o1 = r1*128u + (kb ^ ((r1 & 7u)*16u));
                LDSM_X4(bh0[0], bh0[1], bh0[2], bh0[3], Bt + o0);
                LDSM_X4(bh1[0], bh1[1], bh1[2], bh1[3], Bt + o1);
                LDSM_X4(bl0[0], bl0[1], bl0[2], bl0[3], Bt + 8192u + o0);
                LDSM_X4(bl1[0], bl1[1], bl1[2], bl1[3], Bt + 8192u + o1);
            }
            MMA_BF16(acc[0][0], ah0, bh0[0], bh0[2]);
            MMA_BF16(acc[0][1], ah0, bh0[1], bh0[3]);
            MMA_BF16(acc[0][2], ah0, bh1[0], bh1[2]);
            MMA_BF16(acc[0][3], ah0, bh1[1], bh1[3]);
            MMA_BF16(acc[1][0], ah1, bh0[0], bh0[2]);
            MMA_BF16(acc[1][1], ah1, bh0[1], bh0[3]);
            MMA_BF16(acc[1][2], ah1, bh1[0], bh1[2]);
            MMA_BF16(acc[1][3], ah1, bh1[1], bh1[3]);
            MMA_BF16(acc[0][0], ah0, bl0[0], bl0[2]);
            MMA_BF16(acc[0][1], ah0, bl0[1], bl0[3]);
            MMA_BF16(acc[0][2], ah0, bl1[0], bl1[2]);
            MMA_BF16(acc[0][3], ah0, bl1[1], bl1[3]);
            MMA_BF16(acc[1][0], ah1, bl0[0], bl0[2]);
            MMA_BF16(acc[1][1], ah1, bl0[1], bl0[3]);
            MMA_BF16(acc[1][2], ah1, bl1[0], bl1[2]);
            MMA_BF16(acc[1][3], ah1, bl1[1], bl1[3]);
            MMA_BF16(acc[0][0], al0, bh0[0], bh0[2]);
            MMA_BF16(acc[0][1], al0, bh0[1], bh0[3]);
            MMA_BF16(acc[0][2], al0, bh1[0], bh1[2]);
            MMA_BF16(acc[0][3], al0, bh1[1], bh1[3]);
            MMA_BF16(acc[1][0], al1, bh0[0], bh0[2]);
            MMA_BF16(acc[1][1], al1, bh0[1], bh0[3]);
            MMA_BF16(acc[1][2], al1, bh1[0], bh1[2]);
            MMA_BF16(acc[1][3], al1, bh1[1], bh1[3]);
        }
        __syncthreads();
    }

    // ---- epilogue: bias + NCHW fp32 store ----
    float bs2[4][2];
    #pragma unroll
    for (int nb = 0; nb < 4; nb++) {
        int co = nbase + nb * 8 + (lane & 3) * 2;
        bs2[nb][0] = bias[co];
        bs2[nb][1] = bias[co + 1];
    }
    #pragma unroll
    for (int mt = 0; mt < 2; mt++) {
        #pragma unroll
        for (int rh = 0; rh < 2; rh++) {
            int px = x0 + mbase + mt * 16 + (lane >> 2) + rh * 8;
            size_t pix = ((size_t)y << 8) + px;
            #pragma unroll
            for (int nb = 0; nb < 4; nb++) {
                int co = nbase + nb * 8 + (lane & 3) * 2;
                out[(((size_t)b * 64 + co    ) << 16) + pix] = acc[mt][nb][rh*2+0] + bs2[nb][0];
                out[(((size_t)b * 64 + co + 1) << 16) + pix] = acc[mt][nb][rh*2+1] + bs2[nb][1];
            }
        }
    }
}

// ---------------------------------------------------------------------------
// Launch
// ---------------------------------------------------------------------------
extern "C" void kernel_launch(void* const* d_in, const int* in_sizes, int n_in,
                              void* d_out, int out_size)
{
    const float* ref   = (const float*)d_in[0];
    const float* supp  = (const float*)d_in[1];
    const float* flow  = (const float*)d_in[2];
    const float* fc_w  = (const float*)d_in[3];
    const float* fc_b  = (const float*)d_in[4];
    const float* cw[6], *cb[6];
    for (int i = 0; i < 6; i++) {
        cw[i] = (const float*)d_in[5 + 2*i];
        cb[i] = (const float*)d_in[6 + 2*i];
    }
    const float* off_w = (const float*)d_in[17];
    const float* off_b = (const float*)d_in[18];
    const float* dcn_w = (const float*)d_in[19];
    const float* dcn_b = (const float*)d_in[20];
    float* out = (float*)d_out;

    __nv_bfloat16 *wH, *wL, *rH, *rL, *t0H, *t0L, *tmpH, *tmpL, *ftH, *ftL, *Bg;
    float *f0F, *ffF, *offbuf;
    cudaGetSymbolAddress((void**)&wH,  g_wH);   cudaGetSymbolAddress((void**)&wL,  g_wL);
    cudaGetSymbolAddress((void**)&rH,  g_rH);   cudaGetSymbolAddress((void**)&rL,  g_rL);
    cudaGetSymbolAddress((void**)&t0H, g_t0H);  cudaGetSymbolAddress((void**)&t0L, g_t0L);
    cudaGetSymbolAddress((void**)&tmpH,g_tmpH); cudaGetSymbolAddress((void**)&tmpL,g_tmpL);
    cudaGetSymbolAddress((void**)&ftH, g_ftH);  cudaGetSymbolAddress((void**)&ftL, g_ftL);
    cudaGetSymbolAddress((void**)&Bg,  g_B);
    cudaGetSymbolAddress((void**)&f0F,   g_f0F);
    cudaGetSymbolAddress((void**)&ffF,   g_ffF);
    cudaGetSymbolAddress((void**)&offbuf,g_off);

    // smem per DIL: pad + single A (2*(128+2d)*128) + 2x16KB B
    const int SMB1 = 1024 + 2*(130*128) + 32768;   // 67072
    const int SMB2 = 1024 + 2*(132*128) + 32768;   // 67584
    const int SMB4 = 1024 + 2*(136*128) + 32768;   // 68608
    const int SMD  = 1024 + 32768 + 32768;         // 66560
    cudaFuncSetAttribute((const void*)conv_mma_kernel<1,1,1,18>, cudaFuncAttributeMaxDynamicSharedMemorySize, SMB1);
    cudaFuncSetAttribute((const void*)conv_mma_kernel<1,2,1,9>,  cudaFuncAttributeMaxDynamicSharedMemorySize, SMB1);
    cudaFuncSetAttribute((const void*)conv_mma_kernel<1,3,1,9>,  cudaFuncAttributeMaxDynamicSharedMemorySize, SMB1);
    cudaFuncSetAttribute((const void*)conv_mma_kernel<2,2,1,9>,  cudaFuncAttributeMaxDynamicSharedMemorySize, SMB2);
    cudaFuncSetAttribute((const void*)conv_mma_kernel<2,4,1,9>,  cudaFuncAttributeMaxDynamicSharedMemorySize, SMB2);
    cudaFuncSetAttribute((const void*)conv_mma_kernel<4,5,1,9>,  cudaFuncAttributeMaxDynamicSharedMemorySize, SMB4);
    cudaFuncSetAttribute((const void*)conv_mma_kernel<1,6,1,9>,  cudaFuncAttributeMaxDynamicSharedMemorySize, SMB1);
    cudaFuncSetAttribute((const void*)dcn_mma_kernel, cudaFuncAttributeMaxDynamicSharedMemorySize, SMD);

    // Fused weight prep (13 sets, one launch)
    PrepTable tab;
    tab.d[0]  = {fc_w, 128, 0,  64, 0};
    tab.d[1]  = {fc_w, 128, 64, 64, 0};
    for (int i = 0; i < 6; i++) tab.d[2+i] = {cw[i], 64, 0, 64, 0};
    for (int ch = 0; ch < 4; ch++) tab.d[8+ch] = {off_w, 64, 0, 216, ch*64};
    tab.d[12] = {dcn_w, 64, 0, 64, 0};
    prep_all_kernel<<<dim3(144, 13), 256>>>(tab, Bg);

    // Input format conversion
    warp_nhwc_kernel<<<dim3(HWSZ/256, BB), 256>>>(supp, flow, wH, wL);
    to_nhwc_kernel<<<dim3(HWSZ/256, BB), 256>>>(ref, rH, rL);

    dim3 cg(2, 256, 4);
    // fc (fused 18-tap): lrelu -> feat0 (f32 + hi/lo)
    conv_mma_kernel<1,1,1,18><<<cg, 256, SMB1>>>(wH, wL, rH, rL, Bg + 0*BSET, fc_b, 1, 64,
                                                 f0F, t0H, t0L, nullptr, nullptr);
    // c1: relu -> tmp
    conv_mma_kernel<1,2,1,9><<<cg, 256, SMB1>>>(t0H, t0L, nullptr, nullptr, Bg + 2*BSET, cb[0], 1, 64,
                                                nullptr, tmpH, tmpL, nullptr, nullptr);
    // c2: ff = feat0 + relu(v)
    conv_mma_kernel<1,3,1,9><<<cg, 256, SMB1>>>(tmpH, tmpL, nullptr, nullptr, Bg + 3*BSET, cb[1], 1, 64,
                                                ffF, nullptr, nullptr, f0F, nullptr);
    // c3 (dil2): relu -> tmp
    conv_mma_kernel<2,2,1,9><<<cg, 256, SMB2>>>(t0H, t0L, nullptr, nullptr, Bg + 4*BSET, cb[2], 1, 64,
                                                nullptr, tmpH, tmpL, nullptr, nullptr);
    // c4 (dil2): ff += 0.1*relu(v)
    conv_mma_kernel<2,4,1,9><<<cg, 256, SMB2>>>(tmpH, tmpL, nullptr, nullptr, Bg + 5*BSET, cb[3], 1, 64,
                                                ffF, nullptr, nullptr, nullptr, nullptr);
    // c5 (dil2): relu -> tmp
    conv_mma_kernel<2,2,1,9><<<cg, 256, SMB2>>>(t0H, t0L, nullptr, nullptr, Bg + 6*BSET, cb[4], 1, 64,
                                                nullptr, tmpH, tmpL, nullptr, nullptr);
    // c6 (dil4): feat = ff + 0.1*relu(v) -> hi/lo
    conv_mma_kernel<4,5,1,9><<<cg, 256, SMB4>>>(tmpH, tmpL, nullptr, nullptr, Bg + 7*BSET, cb[5], 1, 64,
                                                nullptr, ftH, ftL, ffF, nullptr);
    // offset conv: 216 couts, 4 chunks, NCHW out
    dim3 og(2, 256, 16);
    conv_mma_kernel<1,6,1,9><<<og, 256, SMB1>>>(ftH, ftL, nullptr, nullptr, Bg + 8*BSET, off_b, 4, 216,
                                                nullptr, nullptr, nullptr, nullptr, offbuf);
    // tensorized deformable conv
    dcn_mma_kernel<<<cg, 256, SMD>>>(supp, offbuf, flow, Bg + 12*BSET, dcn_b, out);
}

// round 11
// speedup vs baseline: 3.2003x; 1.0787x over previous
#include <cuda_runtime.h>
#include <cuda_bf16.h>
#include <math.h>
#include <stdint.h>

#define BB 4
#define HH 256
#define WW 256
#define HWSZ 65536
#define NPX (BB*HWSZ)

// ---------------------------------------------------------------------------
// PTX helpers (plain sm_103-safe: ldmatrix + mma.sync + cp.async)
// ---------------------------------------------------------------------------
__device__ __forceinline__ uint32_t smem_u32(const void* p) {
    uint32_t a;
    asm("{ .reg .u64 t; cvta.to.shared.u64 t, %1; cvt.u32.u64 %0, t; }" : "=r"(a) : "l"(p));
    return a;
}

#define LDSM_X4(r0, r1, r2, r3, addr) \
    asm volatile("ldmatrix.sync.aligned.m8n8.x4.shared.b16 {%0,%1,%2,%3}, [%4];" \
        : "=r"(r0), "=r"(r1), "=r"(r2), "=r"(r3) : "r"(addr))

#define MMA_BF16(d, a, b0v, b1v) \
    asm volatile("mma.sync.aligned.m16n8k16.row.col.f32.bf16.bf16.f32 " \
        "{%0,%1,%2,%3},{%4,%5,%6,%7},{%8,%9},{%0,%1,%2,%3};" \
        : "+f"((d)[0]), "+f"((d)[1]), "+f"((d)[2]), "+f"((d)[3]) \
        : "r"((a)[0]), "r"((a)[1]), "r"((a)[2]), "r"((a)[3]), "r"(b0v), "r"(b1v))

#define CP_ASYNC16(dst, src, sz) \
    asm volatile("cp.async.cg.shared.global [%0], [%1], 16, %2;" \
        :: "r"(dst), "l"(src), "r"(sz) : "memory")
#define CP_COMMIT() asm volatile("cp.async.commit_group;" ::: "memory")
#define CP_WAIT1() asm volatile("cp.async.wait_group 1;" ::: "memory")
#define CP_WAIT0() asm volatile("cp.async.wait_group 0;" ::: "memory")

// ---------------------------------------------------------------------------
// Device global scratch
// ---------------------------------------------------------------------------
#define FEAT_ELEMS ((size_t)NPX*64)
__device__ __nv_bfloat16 g_wH[FEAT_ELEMS], g_wL[FEAT_ELEMS];     // warped supp
__device__ __nv_bfloat16 g_rH[FEAT_ELEMS], g_rL[FEAT_ELEMS];     // ref
__device__ __nv_bfloat16 g_t0H[FEAT_ELEMS], g_t0L[FEAT_ELEMS];   // feat0
__device__ __nv_bfloat16 g_tmpH[FEAT_ELEMS], g_tmpL[FEAT_ELEMS];
__device__ __nv_bfloat16 g_ftH[FEAT_ELEMS], g_ftL[FEAT_ELEMS];   // final feat
__device__ float g_f0F[FEAT_ELEMS];                               // feat0 fp32
__device__ float g_ffF[FEAT_ELEMS];                               // feat fp32 accum
__device__ float g_off[(size_t)BB*216*HWSZ];                      // NCHW
__device__ float g_sN[FEAT_ELEMS];                                // supp NHWC fp32
// 13 B-sets (fc0, fc1, c1..c6, off chunks 0..3, dcn); each 9 taps x 16KB
#define BSET 73728
__device__ __nv_bfloat16 g_B[13*BSET];

// ---------------------------------------------------------------------------
// Fused B prep: all 13 sets in one launch (blockIdx.y = set)
// ---------------------------------------------------------------------------
struct PrepDesc { const float* w; int cinTot, cin0, coutTot, cout0; };
struct PrepTable { PrepDesc d[13]; };

__global__ void prep_all_kernel(PrepTable tab, __nv_bfloat16* __restrict__ outB)
{
    int set = blockIdx.y;
    PrepDesc pd = tab.d[set];
    int idx = blockIdx.x * 256 + threadIdx.x;   // < 36864
    int c = idx & 63;
    int r = (idx >> 6) & 63;
    int t = idx >> 12;
    float v = 0.f;
    int co = pd.cout0 + r;
    if (co < pd.coutTot) v = pd.w[((size_t)co * pd.cinTot + pd.cin0 + c) * 9 + t];
    __nv_bfloat16 h = __float2bfloat16(v);
    __nv_bfloat16 l = __float2bfloat16(v - __bfloat162float(h));
    uint32_t off = (uint32_t)r * 128u + (uint32_t)c * 2u;
    uint32_t so = off ^ ((off >> 3) & 0x70u);
    char* ob = (char*)(outB + (size_t)set * BSET) + (size_t)t * 16384;
    *(__nv_bfloat16*)(ob + so) = h;
    *(__nv_bfloat16*)(ob + 8192 + so) = l;
}

// ---------------------------------------------------------------------------
// supp NCHW fp32 -> NHWC fp32 (smem-tiled transpose, 64px x 64ch per block)
// ---------------------------------------------------------------------------
__global__ void supp_nhwc_kernel(const float* __restrict__ src, float* __restrict__ dst)
{
    __shared__ float s[64 * 65];
    int b  = blockIdx.y;
    int x0 = blockIdx.x * 64;     // linear pixel base
    int tid = threadIdx.x;
    int lc = tid >> 6;            // 0..3
    int lp = tid & 63;
    #pragma unroll
    for (int i = 0; i < 16; i++) {
        int c = i * 4 + lc;
        s[lp * 65 + c] = src[((size_t)b * 64 + c) * HWSZ + x0 + lp];
    }
    __syncthreads();
    int px = tid >> 2, q4 = (tid & 3) * 16;
    float* dp = dst + ((size_t)b * HWSZ + x0 + px) * 64 + q4;
    const float* sp = s + px * 65 + q4;
    #pragma unroll
    for (int q = 0; q < 4; q++)
        ((float4*)dp)[q] = make_float4(sp[q*4], sp[q*4+1], sp[q*4+2], sp[q*4+3]);
}

// ---------------------------------------------------------------------------
// flow_warp (reads NHWC fp32 supp, vectorized corners) -> NHWC bf16 hi/lo
// ---------------------------------------------------------------------------
__global__ void warp_nhwc_kernel(const float* __restrict__ suppN, const float* __restrict__ flow,
                                 __nv_bfloat16* __restrict__ oH, __nv_bfloat16* __restrict__ oL)
{
    int p = blockIdx.x * 256 + threadIdx.x;
    int b = blockIdx.y;
    int y = p >> 8, x = p & 255;
    float fx = flow[((size_t)b*2    )*HWSZ + p];
    float fy = flow[((size_t)b*2 + 1)*HWSZ + p];
    float sy = (float)y + fy, sx = (float)x + fx;
    float y0f = floorf(sy), x0f = floorf(sx);
    int iy0 = (int)y0f, ix0 = (int)x0f, iy1 = iy0+1, ix1 = ix0+1;
    float wy = sy - y0f, wx = sx - x0f;
    bool vy0 = ((unsigned)iy0 < HH), vy1 = ((unsigned)iy1 < HH);
    bool vx0 = ((unsigned)ix0 < WW), vx1 = ((unsigned)ix1 < WW);
    float w00 = (1.f-wy)*(1.f-wx) * ((vy0&&vx0)?1.f:0.f);
    float w01 = (1.f-wy)*wx       * ((vy0&&vx1)?1.f:0.f);
    float w10 = wy*(1.f-wx)       * ((vy1&&vx0)?1.f:0.f);
    float w11 = wy*wx             * ((vy1&&vx1)?1.f:0.f);
    int cy0 = min(max(iy0,0),HH-1), cy1 = min(max(iy1,0),HH-1);
    int cx0 = min(max(ix0,0),WW-1), cx1 = min(max(ix1,0),WW-1);
    size_t i00 = (size_t)(cy0*WW+cx0)*64, i01 = (size_t)(cy0*WW+cx1)*64;
    size_t i10 = (size_t)(cy1*WW+cx0)*64, i11 = (size_t)(cy1*WW+cx1)*64;
    const float* sb = suppN + (size_t)b*HWSZ*64;
    __nv_bfloat16* ohp = oH + ((size_t)b*HWSZ + p)*64;
    __nv_bfloat16* olp = oL + ((size_t)b*HWSZ + p)*64;
    #pragma unroll 1
    for (int g = 0; g < 8; g++) {
        const float4* p00 = (const float4*)(sb + i00 + g*8);
        const float4* p01 = (const float4*)(sb + i01 + g*8);
        const float4* p10 = (const float4*)(sb + i10 + g*8);
        const float4* p11 = (const float4*)(sb + i11 + g*8);
        float v[8];
        #pragma unroll
        for (int h = 0; h < 2; h++) {
            float4 a = p00[h], bb = p01[h], cc = p10[h], dd = p11[h];
            v[h*4+0] = w00*a.x + w01*bb.x + w10*cc.x + w11*dd.x;
            v[h*4+1] = w00*a.y + w01*bb.y + w10*cc.y + w11*dd.y;
            v[h*4+2] = w00*a.z + w01*bb.z + w10*cc.z + w11*dd.z;
            v[h*4+3] = w00*a.w + w01*bb.w + w10*cc.w + w11*dd.w;
        }
        uint4 uh, ul;
        uint32_t* ph = (uint32_t*)&uh;
        uint32_t* pl = (uint32_t*)&ul;
        #pragma unroll
        for (int q = 0; q < 4; q++) {
            __nv_bfloat162 h2 = __floats2bfloat162_rn(v[q*2], v[q*2+1]);
            float2 hf = __bfloat1622float2(h2);
            __nv_bfloat162 l2 = __floats2bfloat162_rn(v[q*2] - hf.x, v[q*2+1] - hf.y);
            ph[q] = *(uint32_t*)&h2;
            pl[q] = *(uint32_t*)&l2;
        }
        ((uint4*)ohp)[g] = uh;
        ((uint4*)olp)[g] = ul;
    }
}

// NCHW fp32 -> NHWC bf16 hi/lo (ref)
__global__ void to_nhwc_kernel(const float* __restrict__ src,
                               __nv_bfloat16* __restrict__ oH, __nv_bfloat16* __restrict__ oL)
{
    int p = blockIdx.x * 256 + threadIdx.x;
    int b = blockIdx.y;
    const float* sp = src + (size_t)b*64*HWSZ + p;
    __nv_bfloat16* ohp = oH + ((size_t)b*HWSZ + p)*64;
    __nv_bfloat16* olp = oL + ((size_t)b*HWSZ + p)*64;
    for (int g = 0; g < 8; g++) {
        uint4 uh, ul;
        uint32_t* ph = (uint32_t*)&uh;
        uint32_t* pl = (uint32_t*)&ul;
        #pragma unroll
        for (int q = 0; q < 4; q++) {
            float v0 = sp[(size_t)(g*8 + q*2    )*HWSZ];
            float v1 = sp[(size_t)(g*8 + q*2 + 1)*HWSZ];
            __nv_bfloat162 h2 = __floats2bfloat162_rn(v0, v1);
            float2 hf = __bfloat1622float2(h2);
            __nv_bfloat162 l2 = __floats2bfloat162_rn(v0 - hf.x, v1 - hf.y);
            ph[q] = *(uint32_t*)&h2;
            pl[q] = *(uint32_t*)&l2;
        }
        ((uint4*)ohp)[g] = uh;
        ((uint4*)olp)[g] = ul;
    }
}

// ---------------------------------------------------------------------------
// mma.sync conv (unchanged from R10, passing): single A buffer per ki group,
// double-buffered B, 3 CTAs/SM; group-accounting invariant in the wait logic.
// ---------------------------------------------------------------------------
template<int DIL, int EPI, int HASBIAS, int NT>
__global__ void __launch_bounds__(256, 3)
conv_mma_kernel(const __nv_bfloat16* __restrict__ inH,
                const __nv_bfloat16* __restrict__ inL,
                const __nv_bfloat16* __restrict__ inH2,
                const __nv_bfloat16* __restrict__ inL2,
                const __nv_bfloat16* __restrict__ Bimg,
                const float* __restrict__ bias,
                int nchunk, int coutTot,
                float* __restrict__ outF,
                __nv_bfloat16* __restrict__ outH,
                __nv_bfloat16* __restrict__ outL,
                const float* __restrict__ resF,
                float* __restrict__ outNCHW)
{
    constexpr uint32_t R = 128 + 2 * DIL;
    constexpr uint32_t AHALF = R * 128u;
    constexpr uint32_t ABUF = 2u * AHALF;

    extern __shared__ char smem[];
    uint32_t base = (smem_u32(smem) + 1023u) & ~1023u;

    int tid = threadIdx.x;
    int lane = tid & 31, w = tid >> 5;
    int z = blockIdx.z;
    int b = z / nchunk, chunk = z - b * nchunk;
    int y = blockIdx.y, x0 = blockIdx.x * 128;

    const char* Bbase = (const char*)Bimg + (size_t)chunk * 147456;

    auto stageA = [&](int s) {
        int ki = (NT == 18 && s >= 3) ? s - 3 : s;
        const __nv_bfloat16* iH = (NT == 18 && s >= 3) ? inH2 : inH;
        const __nv_bfloat16* iL = (NT == 18 && s >= 3) ? inL2 : inL;
        int gy = y + (ki - 1) * DIL;
        bool rowok = ((unsigned)gy < HH);
        for (int i = tid; i < (int)(R * 8); i += 256) {
            int r = i >> 3, j = i & 7;
            int gx = x0 - DIL + r;
            bool ok = rowok && ((unsigned)gx < WW);
            size_t gidx = ok ? ((((size_t)b * HH + gy) * WW + gx) * 64) : 0;
            int sz = ok ? 16 : 0;
            uint32_t dst = base + (uint32_t)r * 128u +
                           (((uint32_t)j * 16u) ^ (((uint32_t)r & 7u) * 16u));
            CP_ASYNC16(dst, (const char*)(iH + gidx) + j * 16, sz);
            CP_ASYNC16(dst + AHALF, (const char*)(iL + gidx) + j * 16, sz);
        }
    };
    auto stageB = [&](int t2) {
        const char* bsrc = Bbase + (size_t)t2 * 16384;
        uint32_t bB = base + ABUF + (uint32_t)(t2 & 1) * 16384u;
        #pragma unroll
        for (int kk = 0; kk < 4; kk++)
            CP_ASYNC16(bB + (uint32_t)tid * 16u + (uint32_t)kk * 4096u,
                       bsrc + tid * 16 + kk * 4096, 16);
    };

    stageA(0);
    stageB(0);
    CP_COMMIT();

    int mbase = (w & 3) * 32;
    int nbase = (w >> 2) * 32;

    float acc[2][4][4];
    #pragma unroll
    for (int i = 0; i < 2; i++)
        #pragma unroll
        for (int j = 0; j < 4; j++)
            #pragma unroll
            for (int q = 0; q < 4; q++) acc[i][j][q] = 0.f;

    int lr = (lane & 7) + ((lane >> 3) & 1) * 8;
    int kq = (lane >> 4) * 16;

    #pragma unroll 1
    for (int tt = 0; tt < NT; tt++) {
        if (tt + 1 < NT && (tt + 1) % 3 != 0) {
            stageB(tt + 1);
            CP_COMMIT();
            CP_WAIT1();
        } else {
            CP_WAIT0();
        }
        __syncthreads();

        int s = tt / 3, kj = tt - s * 3;
        uint32_t Bt = base + ABUF + (uint32_t)(tt & 1) * 16384u;
        uint32_t rowA0 = (uint32_t)(kj * DIL + mbase + lr);
        uint32_t rowB0 = (uint32_t)(nbase + lr);

        #pragma unroll
        for (int ks = 0; ks < 4; ks++) {
            uint32_t kb = (uint32_t)(ks * 32 + kq);
            uint32_t ah0[4], ah1[4], al0[4], al1[4];
            uint32_t bh0[4], bh1[4], bl0[4], bl1[4];
            {
                uint32_t r0 = rowA0, r1 = rowA0 + 16u;
                uint32_t o0 = r0*128u + (kb ^ ((r0 & 7u)*16u));
                uint32_t o1 = r1*128u + (kb ^ ((r1 & 7u)*16u));
                LDSM_X4(ah0[0], ah0[1], ah0[2], ah0[3], base + o0);
                LDSM_X4(ah1[0], ah1[1], ah1[2], ah1[3], base + o1);
                LDSM_X4(al0[0], al0[1], al0[2], al0[3], base + AHALF + o0);
                LDSM_X4(al1[0], al1[1], al1[2], al1[3], base + AHALF + o1);
            }
            {
                uint32_t r0 = rowB0, r1 = rowB0 + 16u;
                uint32_t o0 = r0*128u + (kb ^ ((r0 & 7u)*16u));
                uint32_t o1 = r1*128u + (kb ^ ((r1 & 7u)*16u));
                LDSM_X4(bh0[0], bh0[1], bh0[2], bh0[3], Bt + o0);
                LDSM_X4(bh1[0], bh1[1], bh1[2], bh1[3], Bt + o1);
                LDSM_X4(bl0[0], bl0[1], bl0[2], bl0[3], Bt + 8192u + o0);
                LDSM_X4(bl1[0], bl1[1], bl1[2], bl1[3], Bt + 8192u + o1);
            }
            MMA_BF16(acc[0][0], ah0, bh0[0], bh0[2]);
            MMA_BF16(acc[0][1], ah0, bh0[1], bh0[3]);
            MMA_BF16(acc[0][2], ah0, bh1[0], bh1[2]);
            MMA_BF16(acc[0][3], ah0, bh1[1], bh1[3]);
            MMA_BF16(acc[1][0], ah1, bh0[0], bh0[2]);
            MMA_BF16(acc[1][1], ah1, bh0[1], bh0[3]);
            MMA_BF16(acc[1][2], ah1, bh1[0], bh1[2]);
            MMA_BF16(acc[1][3], ah1, bh1[1], bh1[3]);
            MMA_BF16(acc[0][0], ah0, bl0[0], bl0[2]);
            MMA_BF16(acc[0][1], ah0, bl0[1], bl0[3]);
            MMA_BF16(acc[0][2], ah0, bl1[0], bl1[2]);
            MMA_BF16(acc[0][3], ah0, bl1[1], bl1[3]);
            MMA_BF16(acc[1][0], ah1, bl0[0], bl0[2]);
            MMA_BF16(acc[1][1], ah1, bl0[1], bl0[3]);
            MMA_BF16(acc[1][2], ah1, bl1[0], bl1[2]);
            MMA_BF16(acc[1][3], ah1, bl1[1], bl1[3]);
            MMA_BF16(acc[0][0], al0, bh0[0], bh0[2]);
            MMA_BF16(acc[0][1], al0, bh0[1], bh0[3]);
            MMA_BF16(acc[0][2], al0, bh1[0], bh1[2]);
            MMA_BF16(acc[0][3], al0, bh1[1], bh1[3]);
            MMA_BF16(acc[1][0], al1, bh0[0], bh0[2]);
            MMA_BF16(acc[1][1], al1, bh0[1], bh0[3]);
            MMA_BF16(acc[1][2], al1, bh1[0], bh1[2]);
            MMA_BF16(acc[1][3], al1, bh1[1], bh1[3]);
        }
        __syncthreads();

        if (tt + 1 < NT && (tt + 1) % 3 == 0) {
            stageA((tt + 1) / 3);
            stageB(tt + 1);
            CP_COMMIT();
        }
    }

    // ---- epilogue ----
    float bs2[4][2];
    #pragma unroll
    for (int nb = 0; nb < 4; nb++) {
        int co = chunk * 64 + nbase + nb * 8 + (lane & 3) * 2;
        bs2[nb][0] = (HASBIAS && co     < coutTot) ? bias[co]     : 0.f;
        bs2[nb][1] = (HASBIAS && co + 1 < coutTot) ? bias[co + 1] : 0.f;
    }
    #pragma unroll
    for (int mt = 0; mt < 2; mt++) {
        #pragma unroll
        for (int rh = 0; rh < 2; rh++) {
            int px = x0 + mbase + mt * 16 + (lane >> 2) + rh * 8;
            size_t P = ((size_t)b * HH + y) * WW + px;
            #pragma unroll
            for (int nb = 0; nb < 4; nb++) {
                int cl = nbase + nb * 8 + (lane & 3) * 2;
                float v0 = acc[mt][nb][rh * 2 + 0] + bs2[nb][0];
                float v1 = acc[mt][nb][rh * 2 + 1] + bs2[nb][1];
                size_t ob = P * 64 + cl;

                if (EPI == 1) {
                    v0 = (v0 > 0.f) ? v0 : 0.1f * v0;
                    v1 = (v1 > 0.f) ? v1 : 0.1f * v1;
                    *(float2*)(outF + ob) = make_float2(v0, v1);
                    __nv_bfloat162 h2 = __floats2bfloat162_rn(v0, v1);
                    float2 hf = __bfloat1622float2(h2);
                    __nv_bfloat162 l2 = __floats2bfloat162_rn(v0 - hf.x, v1 - hf.y);
                    *(uint32_t*)(outH + ob) = *(uint32_t*)&h2;
                    *(uint32_t*)(outL + ob) = *(uint32_t*)&l2;
                } else if (EPI == 2) {
                    v0 = fmaxf(v0, 0.f); v1 = fmaxf(v1, 0.f);
                    __nv_bfloat162 h2 = __floats2bfloat162_rn(v0, v1);
                    float2 hf = __bfloat1622float2(h2);
                    __nv_bfloat162 l2 = __floats2bfloat162_rn(v0 - hf.x, v1 - hf.y);
                    *(uint32_t*)(outH + ob) = *(uint32_t*)&h2;
                    *(uint32_t*)(outL + ob) = *(uint32_t*)&l2;
                } else if (EPI == 3) {
                    float2 rv = *(const float2*)(resF + ob);
                    v0 = rv.x + fmaxf(v0, 0.f);
                    v1 = rv.y + fmaxf(v1, 0.f);
                    *(float2*)(outF + ob) = make_float2(v0, v1);
                } else if (EPI == 4) {
                    float2 rv = *(const float2*)(outF + ob);
                    v0 = rv.x + 0.1f * fmaxf(v0, 0.f);
                    v1 = rv.y + 0.1f * fmaxf(v1, 0.f);
                    *(float2*)(outF + ob) = make_float2(v0, v1);
                } else if (EPI == 5) {
                    float2 rv = *(const float2*)(resF + ob);
                    v0 = rv.x + 0.1f * fmaxf(v0, 0.f);
                    v1 = rv.y + 0.1f * fmaxf(v1, 0.f);
                    __nv_bfloat162 h2 = __floats2bfloat162_rn(v0, v1);
                    float2 hf = __bfloat1622float2(h2);
                    __nv_bfloat162 l2 = __floats2bfloat162_rn(v0 - hf.x, v1 - hf.y);
                    *(uint32_t*)(outH + ob) = *(uint32_t*)&h2;
                    *(uint32_t*)(outL + ob) = *(uint32_t*)&l2;
                } else if (EPI == 6) {
                    int co = chunk * 64 + cl;
                    size_t pix = ((size_t)y << 8) + px;
                    if (co < coutTot)
                        outNCHW[(((size_t)b * coutTot + co) << 16) + pix] = v0;
                    if (co + 1 < coutTot)
                        outNCHW[(((size_t)b * coutTot + co + 1) << 16) + pix] = v1;
                }
            }
        }
    }
}

// ---------------------------------------------------------------------------
// Modulated deformable conv, tensorized; sampling reads NHWC fp32 supp
// (2x float4 per corner per group -> 4x fewer LSU issues than NCHW path).
// ---------------------------------------------------------------------------
__global__ void __launch_bounds__(256, 2)
dcn_mma_kernel(const float* __restrict__ suppN, const float* __restrict__ off,
               const float* __restrict__ flow, const __nv_bfloat16* __restrict__ Bimg,
               const float* __restrict__ bias, float* __restrict__ out)
{
    extern __shared__ char smem[];
    uint32_t base = (smem_u32(smem) + 1023u) & ~1023u;
    const uint32_t SM_S = base;            // 32KB: hi 16K | lo 16K
    const uint32_t SM_Bd = base + 32768u;  // 2 x 16KB B double buffer

    int tid = threadIdx.x;
    int lane = tid & 31, w = tid >> 5;
    int b = blockIdx.z, y = blockIdx.y, x0 = blockIdx.x * 128;

    #pragma unroll
    for (int kk = 0; kk < 4; kk++)
        CP_ASYNC16(SM_Bd + (uint32_t)tid * 16u + (uint32_t)kk * 4096u,
                   (const char*)Bimg + tid * 16 + kk * 4096, 16);
    CP_COMMIT();

    int mbase = (w & 3) * 32;
    int nbase = (w >> 2) * 32;
    float acc[2][4][4];
    #pragma unroll
    for (int i = 0; i < 2; i++)
        #pragma unroll
        for (int j = 0; j < 4; j++)
            #pragma unroll
            for (int q = 0; q < 4; q++) acc[i][j][q] = 0.f;

    int lr = (lane & 7) + ((lane >> 3) & 1) * 8;
    int kq = (lane >> 4) * 16;

    const float* fxp  = flow + ((size_t)b*2 + 0)*HWSZ + y*WW + x0;
    const float* fyp  = flow + ((size_t)b*2 + 1)*HWSZ + y*WW + x0;
    const float* offb = off  + (size_t)b*216*HWSZ + y*WW + x0;
    const float* sb   = suppN + (size_t)b*HWSZ*64;

    #pragma unroll 1
    for (int k = 0; k < 9; k++) {
        if (k < 8) {
            const char* bsrc = (const char*)Bimg + (size_t)(k + 1) * 16384;
            uint32_t bB = SM_Bd + (uint32_t)((k + 1) & 1) * 16384u;
            #pragma unroll
            for (int kk = 0; kk < 4; kk++)
                CP_ASYNC16(bB + (uint32_t)tid * 16u + (uint32_t)kk * 4096u,
                           bsrc + tid * 16 + kk * 4096, 16);
            CP_COMMIT();
        }

        int ki = k / 3, kj = k - ki * 3;
        #pragma unroll 1
        for (int it = 0; it < 4; it++) {
            int task = tid + it * 256;
            int px = task & 127;
            int g  = task >> 7;
            int cdy = g*18 + k*2;
            float rawdy = offb[(size_t)cdy          *HWSZ + px];
            float rawdx = offb[(size_t)(cdy + 1)    *HWSZ + px];
            float rawm  = offb[(size_t)(144 + g*9+k)*HWSZ + px];
            float fx = fxp[px], fy = fyp[px];
            float ady = 25.f * tanhf(rawdy) + ((cdy     < 72) ? fx : fy);
            float adx = 25.f * tanhf(rawdx) + ((cdy + 1 < 72) ? fx : fy);
            float m   = 1.f / (1.f + expf(-rawm));
            float sy = (float)y         + (float)(ki - 1) + ady;
            float sx = (float)(x0 + px) + (float)(kj - 1) + adx;
            float y0f = floorf(sy), x0f = floorf(sx);
            int iy0 = (int)y0f, ix0 = (int)x0f;
            int iy1 = iy0 + 1,  ix1 = ix0 + 1;
            float wy = sy - y0f, wx = sx - x0f;
            bool vy0 = ((unsigned)iy0 < HH), vy1 = ((unsigned)iy1 < HH);
            bool vx0 = ((unsigned)ix0 < WW), vx1 = ((unsigned)ix1 < WW);
            float w00 = (1.f - wy)*(1.f - wx) * ((vy0 && vx0) ? 1.f : 0.f) * m;
            float w01 = (1.f - wy)*wx         * ((vy0 && vx1) ? 1.f : 0.f) * m;
            float w10 = wy*(1.f - wx)         * ((vy1 && vx0) ? 1.f : 0.f) * m;
            float w11 = wy*wx                 * ((vy1 && vx1) ? 1.f : 0.f) * m;
            int cy0 = min(max(iy0, 0), HH-1), cy1 = min(max(iy1, 0), HH-1);
            int cx0 = min(max(ix0, 0), WW-1), cx1 = min(max(ix1, 0), WW-1);
            const float4* p00 = (const float4*)(sb + (size_t)(cy0*WW + cx0)*64 + g*8);
            const float4* p01 = (const float4*)(sb + (size_t)(cy0*WW + cx1)*64 + g*8);
            const float4* p10 = (const float4*)(sb + (size_t)(cy1*WW + cx0)*64 + g*8);
            const float4* p11 = (const float4*)(sb + (size_t)(cy1*WW + cx1)*64 + g*8);
            float v[8];
            #pragma unroll
            for (int h = 0; h < 2; h++) {
                float4 a = p00[h], bb = p01[h], cc = p10[h], dd = p11[h];
                v[h*4+0] = w00*a.x + w01*bb.x + w10*cc.x + w11*dd.x;
                v[h*4+1] = w00*a.y + w01*bb.y + w10*cc.y + w11*dd.y;
                v[h*4+2] = w00*a.z + w01*bb.z + w10*cc.z + w11*dd.z;
                v[h*4+3] = w00*a.w + w01*bb.w + w10*cc.w + w11*dd.w;
            }
            uint32_t hpk[4], lpk[4];
            #pragma unroll
            for (int q = 0; q < 4; q++) {
                __nv_bfloat162 h2 = __floats2bfloat162_rn(v[q*2], v[q*2+1]);
                float2 hf = __bfloat1622float2(h2);
                __nv_bfloat162 l2 = __floats2bfloat162_rn(v[q*2] - hf.x, v[q*2+1] - hf.y);
                hpk[q] = *(uint32_t*)&h2;
                lpk[q] = *(uint32_t*)&l2;
            }
            uint32_t so = (uint32_t)px * 128u +
                          (((uint32_t)g * 16u) ^ (((uint32_t)px & 7u) * 16u));
            asm volatile("st.shared.v4.b32 [%0], {%1,%2,%3,%4};"
                :: "r"(SM_S + so), "r"(hpk[0]), "r"(hpk[1]), "r"(hpk[2]), "r"(hpk[3]) : "memory");
            asm volatile("st.shared.v4.b32 [%0], {%1,%2,%3,%4};"
                :: "r"(SM_S + 16384u + so), "r"(lpk[0]), "r"(lpk[1]), "r"(lpk[2]), "r"(lpk[3]) : "memory");
        }

        if (k < 8) CP_WAIT1(); else CP_WAIT0();
        __syncthreads();

        uint32_t Bt = SM_Bd + (uint32_t)(k & 1) * 16384u;
        uint32_t rowA0 = (uint32_t)(mbase + lr);
        uint32_t rowB0 = (uint32_t)(nbase + lr);
        #pragma unroll
        for (int ks = 0; ks < 4; ks++) {
            uint32_t kb = (uint32_t)(ks * 32 + kq);
            uint32_t ah0[4], ah1[4], al0[4], al1[4];
            uint32_t bh0[4], bh1[4], bl0[4], bl1[4];
            {
                uint32_t r0 = rowA0, r1 = rowA0 + 16u;
                uint32_t o0 = r0*128u + (kb ^ ((r0 & 7u)*16u));
                uint32_t o1 = r1*128u + (kb ^ ((r1 & 7u)*16u));
                LDSM_X4(ah0[0], ah0[1], ah0[2], ah0[3], SM_S + o0);
                LDSM_X4(ah1[0], ah1[1], ah1[2], ah1[3], SM_S + o1);
                LDSM_X4(al0[0], al0[1], al0[2], al0[3], SM_S + 16384u + o0);
                LDSM_X4(al1[0], al1[1], al1[2], al1[3], SM_S + 16384u + o1);
            }
            {
                uint32_t r0 = rowB0, r1 = rowB0 + 16u;
                uint32_t o0 = r0*128u + (kb ^ ((r0 & 7u)*16u));
                uint32_t o1 = r1*128u + (kb ^ ((r1 & 7u)*16u));
                LDSM_X4(bh0[0], bh0[1], bh0[2], bh0[3], Bt + o0);
                LDSM_X4(bh1[0], bh1[1], bh1[2], bh1[3], Bt + o1);
                LDSM_X4(bl0[0], bl0[1], bl0[2], bl0[3], Bt + 8192u + o0);
                LDSM_X4(bl1[0], bl1[1], bl1[2], bl1[3], Bt + 8192u + o1);
            }
            MMA_BF16(acc[0][0], ah0, bh0[0], bh0[2]);
            MMA_BF16(acc[0][1], ah0, bh0[1], bh0[3]);
            MMA_BF16(acc[0][2], ah0, bh1[0], bh1[2]);
            MMA_BF16(acc[0][3], ah0, bh1[1], bh1[3]);
            MMA_BF16(acc[1][0], ah1, bh0[0], bh0[2]);
            MMA_BF16(acc[1][1], ah1, bh0[1], bh0[3]);
            MMA_BF16(acc[1][2], ah1, bh1[0], bh1[2]);
            MMA_BF16(acc[1][3], ah1, bh1[1], bh1[3]);
            MMA_BF16(acc[0][0], ah0, bl0[0], bl0[2]);
            MMA_BF16(acc[0][1], ah0, bl0[1], bl0[3]);
            MMA_BF16(acc[0][2], ah0, bl1[0], bl1[2]);
            MMA_BF16(acc[0][3], ah0, bl1[1], bl1[3]);
            MMA_BF16(acc[1][0], ah1, bl0[0], bl0[2]);
            MMA_BF16(acc[1][1], ah1, bl0[1], bl0[3]);
            MMA_BF16(acc[1][2], ah1, bl1[0], bl1[2]);
            MMA_BF16(acc[1][3], ah1, bl1[1], bl1[3]);
            MMA_BF16(acc[0][0], al0, bh0[0], bh0[2]);
            MMA_BF16(acc[0][1], al0, bh0[1], bh0[3]);
            MMA_BF16(acc[0][2], al0, bh1[0], bh1[2]);
            MMA_BF16(acc[0][3], al0, bh1[1], bh1[3]);
            MMA_BF16(acc[1][0], al1, bh0[0], bh0[2]);
            MMA_BF16(acc[1][1], al1, bh0[1], bh0[3]);
            MMA_BF16(acc[1][2], al1, bh1[0], bh1[2]);
            MMA_BF16(acc[1][3], al1, bh1[1], bh1[3]);
        }
        __syncthreads();
    }

    // ---- epilogue: bias + NCHW fp32 store ----
    float bs2[4][2];
    #pragma unroll
    for (int nb = 0; nb < 4; nb++) {
        int co = nbase + nb * 8 + (lane & 3) * 2;
        bs2[nb][0] = bias[co];
        bs2[nb][1] = bias[co + 1];
    }
    #pragma unroll
    for (int mt = 0; mt < 2; mt++) {
        #pragma unroll
        for (int rh = 0; rh < 2; rh++) {
            int px = x0 + mbase + mt * 16 + (lane >> 2) + rh * 8;
            size_t pix = ((size_t)y << 8) + px;
            #pragma unroll
            for (int nb = 0; nb < 4; nb++) {
                int co = nbase + nb * 8 + (lane & 3) * 2;
                out[(((size_t)b * 64 + co    ) << 16) + pix] = acc[mt][nb][rh*2+0] + bs2[nb][0];
                out[(((size_t)b * 64 + co + 1) << 16) + pix] = acc[mt][nb][rh*2+1] + bs2[nb][1];
            }
        }
    }
}

// ---------------------------------------------------------------------------
// Launch
// ---------------------------------------------------------------------------
extern "C" void kernel_launch(void* const* d_in, const int* in_sizes, int n_in,
                              void* d_out, int out_size)
{
    const float* ref   = (const float*)d_in[0];
    const float* supp  = (const float*)d_in[1];
    const float* flow  = (const float*)d_in[2];
    const float* fc_w  = (const float*)d_in[3];
    const float* fc_b  = (const float*)d_in[4];
    const float* cw[6], *cb[6];
    for (int i = 0; i < 6; i++) {
        cw[i] = (const float*)d_in[5 + 2*i];
        cb[i] = (const float*)d_in[6 + 2*i];
    }
    const float* off_w = (const float*)d_in[17];
    const float* off_b = (const float*)d_in[18];
    const float* dcn_w = (const float*)d_in[19];
    const float* dcn_b = (const float*)d_in[20];
    float* out = (float*)d_out;

    __nv_bfloat16 *wH, *wL, *rH, *rL, *t0H, *t0L, *tmpH, *tmpL, *ftH, *ftL, *Bg;
    float *f0F, *ffF, *offbuf, *suppN;
    cudaGetSymbolAddress((void**)&wH,  g_wH);   cudaGetSymbolAddress((void**)&wL,  g_wL);
    cudaGetSymbolAddress((void**)&rH,  g_rH);   cudaGetSymbolAddress((void**)&rL,  g_rL);
    cudaGetSymbolAddress((void**)&t0H, g_t0H);  cudaGetSymbolAddress((void**)&t0L, g_t0L);
    cudaGetSymbolAddress((void**)&tmpH,g_tmpH); cudaGetSymbolAddress((void**)&tmpL,g_tmpL);
    cudaGetSymbolAddress((void**)&ftH, g_ftH);  cudaGetSymbolAddress((void**)&ftL, g_ftL);
    cudaGetSymbolAddress((void**)&Bg,  g_B);
    cudaGetSymbolAddress((void**)&f0F,   g_f0F);
    cudaGetSymbolAddress((void**)&ffF,   g_ffF);
    cudaGetSymbolAddress((void**)&offbuf,g_off);
    cudaGetSymbolAddress((void**)&suppN, g_sN);

    // smem per DIL: pad + single A (2*(128+2d)*128) + 2x16KB B
    const int SMB1 = 1024 + 2*(130*128) + 32768;   // 67072
    const int SMB2 = 1024 + 2*(132*128) + 32768;   // 67584
    const int SMB4 = 1024 + 2*(136*128) + 32768;   // 68608
    const int SMD  = 1024 + 32768 + 32768;         // 66560
    cudaFuncSetAttribute((const void*)conv_mma_kernel<1,1,1,18>, cudaFuncAttributeMaxDynamicSharedMemorySize, SMB1);
    cudaFuncSetAttribute((const void*)conv_mma_kernel<1,2,1,9>,  cudaFuncAttributeMaxDynamicSharedMemorySize, SMB1);
    cudaFuncSetAttribute((const void*)conv_mma_kernel<1,3,1,9>,  cudaFuncAttributeMaxDynamicSharedMemorySize, SMB1);
    cudaFuncSetAttribute((const void*)conv_mma_kernel<2,2,1,9>,  cudaFuncAttributeMaxDynamicSharedMemorySize, SMB2);
    cudaFuncSetAttribute((const void*)conv_mma_kernel<2,4,1,9>,  cudaFuncAttributeMaxDynamicSharedMemorySize, SMB2);
    cudaFuncSetAttribute((const void*)conv_mma_kernel<4,5,1,9>,  cudaFuncAttributeMaxDynamicSharedMemorySize, SMB4);
    cudaFuncSetAttribute((const void*)conv_mma_kernel<1,6,1,9>,  cudaFuncAttributeMaxDynamicSharedMemorySize, SMB1);
    cudaFuncSetAttribute((const void*)dcn_mma_kernel, cudaFuncAttributeMaxDynamicSharedMemorySize, SMD);

    // Fused weight prep (13 sets, one launch)
    PrepTable tab;
    tab.d[0]  = {fc_w, 128, 0,  64, 0};
    tab.d[1]  = {fc_w, 128, 64, 64, 0};
    for (int i = 0; i < 6; i++) tab.d[2+i] = {cw[i], 64, 0, 64, 0};
    for (int ch = 0; ch < 4; ch++) tab.d[8+ch] = {off_w, 64, 0, 216, ch*64};
    tab.d[12] = {dcn_w, 64, 0, 64, 0};
    prep_all_kernel<<<dim3(144, 13), 256>>>(tab, Bg);

    // supp NCHW -> NHWC fp32 (feeds warp + dcn gathers)
    supp_nhwc_kernel<<<dim3(HWSZ/64, BB), 256>>>(supp, suppN);
    // flow warp (reads NHWC supp)
    warp_nhwc_kernel<<<dim3(HWSZ/256, BB), 256>>>(suppN, flow, wH, wL);
    to_nhwc_kernel<<<dim3(HWSZ/256, BB), 256>>>(ref, rH, rL);

    dim3 cg(2, 256, 4);
    // fc (fused 18-tap): lrelu -> feat0 (f32 + hi/lo)
    conv_mma_kernel<1,1,1,18><<<cg, 256, SMB1>>>(wH, wL, rH, rL, Bg + 0*BSET, fc_b, 1, 64,
                                                 f0F, t0H, t0L, nullptr, nullptr);
    // c1: relu -> tmp
    conv_mma_kernel<1,2,1,9><<<cg, 256, SMB1>>>(t0H, t0L, nullptr, nullptr, Bg + 2*BSET, cb[0], 1, 64,
                                                nullptr, tmpH, tmpL, nullptr, nullptr);
    // c2: ff = feat0 + relu(v)
    conv_mma_kernel<1,3,1,9><<<cg, 256, SMB1>>>(tmpH, tmpL, nullptr, nullptr, Bg + 3*BSET, cb[1], 1, 64,
                                                ffF, nullptr, nullptr, f0F, nullptr);
    // c3 (dil2): relu -> tmp
    conv_mma_kernel<2,2,1,9><<<cg, 256, SMB2>>>(t0H, t0L, nullptr, nullptr, Bg + 4*BSET, cb[2], 1, 64,
                                                nullptr, tmpH, tmpL, nullptr, nullptr);
    // c4 (dil2): ff += 0.1*relu(v)
    conv_mma_kernel<2,4,1,9><<<cg, 256, SMB2>>>(tmpH, tmpL, nullptr, nullptr, Bg + 5*BSET, cb[3], 1, 64,
                                                ffF, nullptr, nullptr, nullptr, nullptr);
    // c5 (dil2): relu -> tmp
    conv_mma_kernel<2,2,1,9><<<cg, 256, SMB2>>>(t0H, t0L, nullptr, nullptr, Bg + 6*BSET, cb[4], 1, 64,
                                                nullptr, tmpH, tmpL, nullptr, nullptr);
    // c6 (dil4): feat = ff + 0.1*relu(v) -> hi/lo
    conv_mma_kernel<4,5,1,9><<<cg, 256, SMB4>>>(tmpH, tmpL, nullptr, nullptr, Bg + 7*BSET, cb[5], 1, 64,
                                                nullptr, ftH, ftL, ffF, nullptr);
    // offset conv: 216 couts, 4 chunks, NCHW out
    dim3 og(2, 256, 16);
    conv_mma_kernel<1,6,1,9><<<og, 256, SMB1>>>(ftH, ftL, nullptr, nullptr, Bg + 8*BSET, off_b, 4, 216,
                                                nullptr, nullptr, nullptr, nullptr, offbuf);
    // tensorized deformable conv (NHWC fp32 gathers)
    dcn_mma_kernel<<<cg, 256, SMD>>>(suppN, offbuf, flow, Bg + 12*BSET, dcn_b, out);
}